// round 2
// baseline (speedup 1.0000x reference)
#include <cuda_runtime.h>
#include <math.h>

#define Bv 2
#define Cch 64
#define Hdim 192
#define Wdim 192
#define HW 36864
#define SEG 65536
#define CHUNK 8192

// ---------------- scratch (static device globals; no runtime allocation) ----------------
__device__ float g_xwork[Bv*Cch*HW];
__device__ int   g_invh[Bv*32*HW];
__device__ int   g_invw[Bv*32*HW];
__device__ float g_q[Bv*320*HW];            // 94 MB
__device__ float g_cat[Bv*960*HW];          // 283 MB
__device__ float g_qkv[Bv*320*HW];          // 94 MB
__device__ float g_keys[Bv*64*SEG];
__device__ int   g_idx[Bv*64*SEG];
__device__ float g_gq1[Bv*Cch*HW];
__device__ float g_gk1[Bv*Cch*HW];
__device__ float g_gq2[Bv*Cch*HW];
__device__ float g_gk2[Bv*Cch*HW];
__device__ float g_vsc[Bv*Cch*HW];
__device__ float g_tq2[Bv*Cch*HW];
__device__ float g_tk2[Bv*Cch*HW];
__device__ float g_tv [Bv*Cch*HW];
__device__ float g_o1 [Bv*Cch*HW];
__device__ float g_ont[Bv*Cch*HW];
__device__ float g_o2 [Bv*Cch*HW];
__device__ float g_pre[Bv*Cch*HW];
__device__ float g_outp[Bv*Cch*HW];
__device__ float g_part[2*8*16*4096];
__device__ float g_attn[2*8*4096];
__device__ float g_nq[2*512];
__device__ float g_nk[2*512];

// ---------------- small 192-element sorts (stable bitonic, padded to 256) ----------------
__global__ void sort_h_kernel(const float* __restrict__ x) {
    int blk = blockIdx.x;
    int w = blk % Wdim; int c = (blk / Wdim) % 32; int b = blk / (Wdim * 32);
    __shared__ float key[256];
    __shared__ int   ind[256];
    int t = threadIdx.x;
    key[t] = (t < Hdim) ? x[((b*Cch + c)*Hdim + t)*Wdim + w] : INFINITY;
    ind[t] = t;
    __syncthreads();
    for (int k = 2; k <= 256; k <<= 1) {
        for (int s = k >> 1; s > 0; s >>= 1) {
            int j = t ^ s;
            if (j > t) {
                bool up = ((t & k) == 0);
                float ka = key[t], kb = key[j];
                int ia = ind[t], ib = ind[j];
                bool agtb = (ka > kb) || (ka == kb && ia > ib);
                if (agtb == up) { key[t] = kb; key[j] = ka; ind[t] = ib; ind[j] = ia; }
            }
            __syncthreads();
        }
    }
    if (t < Hdim) {
        g_xwork[((b*Cch + c)*Hdim + t)*Wdim + w] = key[t];
        g_invh[((b*32 + c)*Hdim + ind[t])*Wdim + w] = t;   // rank of original row
    }
}

__global__ void sort_w_kernel() {
    int blk = blockIdx.x;
    int h = blk % Hdim; int c = (blk / Hdim) % 32; int b = blk / (Hdim * 32);
    int base = ((b*Cch + c)*Hdim + h)*Wdim;
    __shared__ float key[256];
    __shared__ int   ind[256];
    int t = threadIdx.x;
    key[t] = (t < Wdim) ? g_xwork[base + t] : INFINITY;
    ind[t] = t;
    __syncthreads();
    for (int k = 2; k <= 256; k <<= 1) {
        for (int s = k >> 1; s > 0; s >>= 1) {
            int j = t ^ s;
            if (j > t) {
                bool up = ((t & k) == 0);
                float ka = key[t], kb = key[j];
                int ia = ind[t], ib = ind[j];
                bool agtb = (ka > kb) || (ka == kb && ia > ib);
                if (agtb == up) { key[t] = kb; key[j] = ka; ind[t] = ib; ind[j] = ia; }
            }
            __syncthreads();
        }
    }
    if (t < Wdim) {
        g_xwork[base + t] = key[t];
        g_invw[((b*32 + c)*Hdim + h)*Wdim + ind[t]] = t;   // rank of original col
    }
}

__global__ void copy_rest_kernel(const float* __restrict__ x) {
    int gid = blockIdx.x * 256 + threadIdx.x;
    if (gid >= Bv*32*HW) return;
    int p = gid % HW; int c = (gid / HW) % 32; int b = gid / (32 * HW);
    int o = (b*Cch + 32 + c)*HW + p;
    g_xwork[o] = x[o];
}

// ---------------- generic fp32 GEMM: C[b] = A(MxK) @ X[b](KxN) + bias ----------------
// BM=128, BN=64, BK=16, 256 threads, 8x4 per thread
__global__ void gemm_kernel(const float* __restrict__ A, const float* __restrict__ Bm,
                            const float* __restrict__ bias, float* __restrict__ Cm,
                            int M, int K, int N) {
    const int BM = 128, BN = 64, BK = 16;
    int bn = blockIdx.x * BN, bm = blockIdx.y * BM, bb = blockIdx.z;
    const float* Bp = Bm + (size_t)bb * K * N;
    float* Cp = Cm + (size_t)bb * M * N;
    __shared__ float As[BK][BM];
    __shared__ float Bs[BK][BN];
    int tid = threadIdx.x;
    int tx = tid & 15, ty = tid >> 4;
    int rm = ty * 8, rn = tx * 4;
    float acc[8][4];
    #pragma unroll
    for (int i = 0; i < 8; i++)
        #pragma unroll
        for (int j = 0; j < 4; j++) acc[i][j] = 0.f;

    for (int k0 = 0; k0 < K; k0 += BK) {
        {
            int lm = tid >> 1;
            int lk = (tid & 1) * 8;
            int gm = bm + lm;
            if (gm < M) {
                float4 v0 = *reinterpret_cast<const float4*>(&A[(size_t)gm*K + k0 + lk]);
                float4 v1 = *reinterpret_cast<const float4*>(&A[(size_t)gm*K + k0 + lk + 4]);
                As[lk+0][lm] = v0.x; As[lk+1][lm] = v0.y; As[lk+2][lm] = v0.z; As[lk+3][lm] = v0.w;
                As[lk+4][lm] = v1.x; As[lk+5][lm] = v1.y; As[lk+6][lm] = v1.z; As[lk+7][lm] = v1.w;
            } else {
                #pragma unroll
                for (int i = 0; i < 8; i++) As[lk+i][lm] = 0.f;
            }
        }
        {
            int lk = tid >> 4; int ln = (tid & 15) * 4;
            float4 v = *reinterpret_cast<const float4*>(&Bp[(size_t)(k0 + lk)*N + bn + ln]);
            *reinterpret_cast<float4*>(&Bs[lk][ln]) = v;
        }
        __syncthreads();
        #pragma unroll
        for (int k = 0; k < BK; k++) {
            float4 a0 = *reinterpret_cast<const float4*>(&As[k][rm]);
            float4 a1 = *reinterpret_cast<const float4*>(&As[k][rm + 4]);
            float4 bv4 = *reinterpret_cast<const float4*>(&Bs[k][rn]);
            float av[8] = {a0.x, a0.y, a0.z, a0.w, a1.x, a1.y, a1.z, a1.w};
            float bv[4] = {bv4.x, bv4.y, bv4.z, bv4.w};
            #pragma unroll
            for (int i = 0; i < 8; i++)
                #pragma unroll
                for (int j = 0; j < 4; j++) acc[i][j] += av[i] * bv[j];
        }
        __syncthreads();
    }
    #pragma unroll
    for (int i = 0; i < 8; i++) {
        int gm = bm + rm + i;
        if (gm < M) {
            float bvv = bias ? bias[gm] : 0.f;
            float4 o = make_float4(acc[i][0] + bvv, acc[i][1] + bvv, acc[i][2] + bvv, acc[i][3] + bvv);
            *reinterpret_cast<float4*>(&Cp[(size_t)gm*N + bn + rn]) = o;
        }
    }
}

// ---------------- fused depthwise 3x3 / 5x5 / 7x7 ----------------
__global__ void dwconv_kernel(const float* __restrict__ w3, const float* __restrict__ w5,
                              const float* __restrict__ w7) {
    int tile = blockIdx.x; int ch = blockIdx.y; int b = blockIdx.z;
    int ty0 = (tile / 12) * 16, tx0 = (tile % 12) * 16;
    __shared__ float s[22][24];
    __shared__ float wts[83];
    int tid = threadIdx.y * 16 + threadIdx.x;
    if (tid < 9)       wts[tid] = w3[ch*9 + tid];
    else if (tid < 34) wts[tid] = w5[ch*25 + tid - 9];
    else if (tid < 83) wts[tid] = w7[ch*49 + tid - 34];
    const float* base = g_q + (size_t)(b*320 + ch) * HW;
    for (int i = tid; i < 22*22; i += 256) {
        int sy = i / 22, sx = i % 22;
        int gy = ty0 + sy - 3, gx = tx0 + sx - 3;
        s[sy][sx] = (gy >= 0 && gy < Hdim && gx >= 0 && gx < Wdim) ? base[gy*Wdim + gx] : 0.f;
    }
    __syncthreads();
    int y = threadIdx.y, x = threadIdx.x;
    float a3 = 0.f, a5 = 0.f, a7 = 0.f;
    #pragma unroll
    for (int dy = 0; dy < 7; dy++)
        #pragma unroll
        for (int dx = 0; dx < 7; dx++) {
            float v = s[y + dy][x + dx];
            a7 += wts[34 + dy*7 + dx] * v;
            if (dy >= 1 && dy <= 5 && dx >= 1 && dx <= 5) a5 += wts[9 + (dy-1)*5 + (dx-1)] * v;
            if (dy >= 2 && dy <= 4 && dx >= 2 && dx <= 4) a3 += wts[(dy-2)*3 + (dx-2)] * v;
        }
    int gp = (ty0 + y)*Wdim + tx0 + x;
    size_t bo = (size_t)b * 960 * HW;
    g_cat[bo + (size_t)ch*HW + gp]        = a3;
    g_cat[bo + (size_t)(320 + ch)*HW + gp] = a5;
    g_cat[bo + (size_t)(640 + ch)*HW + gp] = a7;
}

// ---------------- big argsort of V: 128 segments of 36864 padded to 65536 ----------------
__device__ __forceinline__ void ce_smem(float* sk, int* si, int i, int j, bool up) {
    float ka = sk[i], kb = sk[j];
    int ia = si[i], ib = si[j];
    bool agtb = (ka > kb) || (ka == kb && ia > ib);
    if (agtb == up) { sk[i] = kb; sk[j] = ka; si[i] = ib; si[j] = ia; }
}

__global__ void bigsort_kernel() {
    int seg = blockIdx.x;                 // b*64 + c
    float* K = g_keys + (size_t)seg * SEG;
    int*   I = g_idx  + (size_t)seg * SEG;
    const float* src = g_qkv + ((size_t)(seg >> 6) * 320 + 256 + (seg & 63)) * HW;
    extern __shared__ float sm[];
    float* sk = sm;
    int*   si = (int*)(sm + CHUNK);
    int t = threadIdx.x;                  // 1024 threads

    for (int i = t; i < SEG; i += 1024) { K[i] = (i < HW) ? src[i] : INFINITY; I[i] = i; }
    __syncthreads();

    // phase 1: all stages k=2..CHUNK, done fully in smem per 8192-chunk
    for (int cb = 0; cb < SEG; cb += CHUNK) {
        for (int i = t; i < CHUNK; i += 1024) { sk[i] = K[cb + i]; si[i] = I[cb + i]; }
        __syncthreads();
        for (int k = 2; k <= CHUNK; k <<= 1) {
            for (int s = k >> 1; s > 0; s >>= 1) {
                for (int p = t; p < CHUNK/2; p += 1024) {
                    int i = ((p & ~(s - 1)) << 1) | (p & (s - 1));
                    int j = i + s;
                    bool up = (((cb + i) & k) == 0);
                    ce_smem(sk, si, i, j, up);
                }
                __syncthreads();
            }
        }
        for (int i = t; i < CHUNK; i += 1024) { K[cb + i] = sk[i]; I[cb + i] = si[i]; }
        __syncthreads();
    }

    // phase 2: stages k = 16384, 32768, 65536
    for (int k = CHUNK*2; k <= SEG; k <<= 1) {
        for (int s = k >> 1; s >= CHUNK; s >>= 1) {
            for (int p = t; p < SEG/2; p += 1024) {
                int i = ((p & ~(s - 1)) << 1) | (p & (s - 1));
                int j = i + s;
                bool up = ((i & k) == 0);
                float ka = K[i], kb = K[j];
                int ia = I[i], ib = I[j];
                bool agtb = (ka > kb) || (ka == kb && ia > ib);
                if (agtb == up) { K[i] = kb; K[j] = ka; I[i] = ib; I[j] = ia; }
            }
            __syncthreads();
        }
        for (int cb = 0; cb < SEG; cb += CHUNK) {
            for (int i = t; i < CHUNK; i += 1024) { sk[i] = K[cb + i]; si[i] = I[cb + i]; }
            __syncthreads();
            for (int s = CHUNK >> 1; s > 0; s >>= 1) {
                for (int p = t; p < CHUNK/2; p += 1024) {
                    int i = ((p & ~(s - 1)) << 1) | (p & (s - 1));
                    int j = i + s;
                    bool up = (((cb + i) & k) == 0);
                    ce_smem(sk, si, i, j, up);
                }
                __syncthreads();
            }
            for (int i = t; i < CHUNK; i += 1024) { K[cb + i] = sk[i]; I[cb + i] = si[i]; }
            __syncthreads();
        }
    }
}

// ---------------- gather q1/k1/q2/k2 + sorted v ----------------
__global__ void gather_kernel() {
    int gid = blockIdx.x * 256 + threadIdx.x;
    if (gid >= Bv*Cch*HW) return;
    int r = gid % HW; int c = (gid / HW) % Cch; int b = gid / (HW * Cch);
    int src = g_idx[(size_t)(b*64 + c)*SEG + r];
    size_t qb = (size_t)b * 320 * HW;
    g_gq1[gid] = g_qkv[qb + (size_t)c*HW + src];
    g_gk1[gid] = g_qkv[qb + (size_t)(64 + c)*HW + src];
    g_gq2[gid] = g_qkv[qb + (size_t)(128 + c)*HW + src];
    g_gk2[gid] = g_qkv[qb + (size_t)(192 + c)*HW + src];
    g_vsc[gid] = g_keys[(size_t)(b*64 + c)*SEG + r];
}

// non-box view transpose: out[(bh*64+d)*9216+n] = in[(b*64+h*16+d/4)*HW + n*4 + d%4]
__global__ void nbt_kernel(const float* __restrict__ in, float* __restrict__ out) {
    int gid = blockIdx.x * 256 + threadIdx.x;
    if (gid >= Bv*Cch*HW) return;
    int n = gid % 9216; int d = (gid / 9216) % 64; int bh = gid / (9216 * 64);
    int b = bh >> 2, h = bh & 3;
    out[gid] = in[((size_t)(b*64 + h*16 + (d >> 2)))*HW + n*4 + (d & 3)];
}

__global__ void nbt_inv_kernel() {  // g_ont (view) -> g_o2 (b,c,p)
    int gid = blockIdx.x * 256 + threadIdx.x;
    if (gid >= Bv*Cch*HW) return;
    int p = gid % HW; int c = (gid / HW) % 64; int b = gid / (HW * 64);
    int h = c >> 4, chi = c & 15;
    int f = p & 3, n = p >> 2;
    int d = chi*4 + f;
    g_o2[gid] = g_ont[((size_t)(b*4 + h)*64 + d)*9216 + n];
}

// ---------------- row L2 norms over 9216 ----------------
__global__ void norm_kernel(const float* __restrict__ t, float* __restrict__ out) {
    int row = blockIdx.x;   // 512 rows
    const float* p = t + (size_t)row * 9216;
    float ss = 0.f;
    for (int i = threadIdx.x; i < 9216; i += 256) { float v = p[i]; ss += v * v; }
    __shared__ float red[256];
    red[threadIdx.x] = ss;
    __syncthreads();
    for (int o = 128; o > 0; o >>= 1) {
        if (threadIdx.x < o) red[threadIdx.x] += red[threadIdx.x + o];
        __syncthreads();
    }
    if (threadIdx.x == 0) out[row] = fmaxf(sqrtf(red[0]), 1e-12f);
}

// ---------------- Q.K^T partials (K split x16) ----------------
__global__ void qk_partial_kernel(const float* __restrict__ q, const float* __restrict__ k,
                                  float* __restrict__ part) {
    int kc = blockIdx.x, bh = blockIdx.y;
    const float* qb = q + (size_t)bh * 64 * 9216;
    const float* kb = k + (size_t)bh * 64 * 9216;
    __shared__ float qs[64][65];
    __shared__ float ks[64][65];
    int tid = threadIdx.x;
    int rm = (tid >> 4) * 4, rn = (tid & 15) * 4;
    float acc[4][4];
    #pragma unroll
    for (int i = 0; i < 4; i++)
        #pragma unroll
        for (int j = 0; j < 4; j++) acc[i][j] = 0.f;
    int nbase0 = kc * 576;
    for (int nt = 0; nt < 576; nt += 64) {
        #pragma unroll
        for (int l = 0; l < 16; l++) {
            int lin = l * 256 + tid;
            int d = lin >> 6, nn = lin & 63;
            qs[d][nn] = qb[(size_t)d*9216 + nbase0 + nt + nn];
            ks[d][nn] = kb[(size_t)d*9216 + nbase0 + nt + nn];
        }
        __syncthreads();
        #pragma unroll 8
        for (int nn = 0; nn < 64; nn++) {
            float a[4], bv[4];
            #pragma unroll
            for (int i = 0; i < 4; i++) a[i] = qs[rm + i][nn];
            #pragma unroll
            for (int j = 0; j < 4; j++) bv[j] = ks[rn + j][nn];
            #pragma unroll
            for (int i = 0; i < 4; i++)
                #pragma unroll
                for (int j = 0; j < 4; j++) acc[i][j] += a[i] * bv[j];
        }
        __syncthreads();
    }
    float* pp = part + ((size_t)bh * 16 + kc) * 4096;
    #pragma unroll
    for (int i = 0; i < 4; i++)
        #pragma unroll
        for (int j = 0; j < 4; j++) pp[(rm + i)*64 + rn + j] = acc[i][j];
}

// ---------------- softmax-with-+1 denominator ----------------
__global__ void softmax_kernel(const float* __restrict__ temp) {
    int bh = blockIdx.x, var = blockIdx.y;
    int d = threadIdx.x;            // 64 threads
    int h = bh & 3;
    const float* pp = g_part + ((size_t)(var*8 + bh) * 16) * 4096;
    float qn = g_nq[var*512 + bh*64 + d];
    float tmp = temp[h];
    float ev[64];
    float rs = 0.f;
    #pragma unroll
    for (int e = 0; e < 64; e++) {
        float s = 0.f;
        #pragma unroll
        for (int c2 = 0; c2 < 16; c2++) s += pp[(size_t)c2*4096 + d*64 + e];
        float a = s * tmp / (qn * g_nk[var*512 + bh*64 + e]);
        float x = expf(a);
        ev[e] = x;
        rs += x;
    }
    float inv = 1.f / (rs + 1.f);
    float* ap = g_attn + (size_t)(var*8 + bh) * 4096;
    #pragma unroll
    for (int e = 0; e < 64; e++) ap[d*64 + e] = ev[e] * inv;
}

// ---------------- o = attn @ vv  (per bh, 64x9216, K=64) ----------------
__global__ void o_gemm_kernel(const float* __restrict__ attn, const float* __restrict__ v,
                              float* __restrict__ o) {
    int nt = blockIdx.x * 64, bh = blockIdx.y;
    const float* ap = attn + (size_t)bh * 4096;
    const float* vp = v + (size_t)bh * 64 * 9216;
    float* op = o + (size_t)bh * 64 * 9216;
    __shared__ float as_[64][65];
    __shared__ float vs_[64][65];
    int tid = threadIdx.x;
    #pragma unroll
    for (int l = 0; l < 16; l++) {
        int lin = l * 256 + tid;
        int r = lin >> 6, cc = lin & 63;
        as_[r][cc] = ap[lin];
        vs_[r][cc] = vp[(size_t)r*9216 + nt + cc];
    }
    __syncthreads();
    int rm = (tid >> 4) * 4, rn = (tid & 15) * 4;
    float acc[4][4];
    #pragma unroll
    for (int i = 0; i < 4; i++)
        #pragma unroll
        for (int j = 0; j < 4; j++) acc[i][j] = 0.f;
    #pragma unroll 8
    for (int e = 0; e < 64; e++) {
        float a[4], bv[4];
        #pragma unroll
        for (int i = 0; i < 4; i++) a[i] = as_[rm + i][e];
        #pragma unroll
        for (int j = 0; j < 4; j++) bv[j] = vs_[e][rn + j];
        #pragma unroll
        for (int i = 0; i < 4; i++)
            #pragma unroll
            for (int j = 0; j < 4; j++) acc[i][j] += a[i] * bv[j];
    }
    #pragma unroll
    for (int i = 0; i < 4; i++) {
        float4 ov = make_float4(acc[i][0], acc[i][1], acc[i][2], acc[i][3]);
        *reinterpret_cast<float4*>(&op[(size_t)(rm + i)*9216 + nt + rn]) = ov;
    }
}

// ---------------- combine out1*out2 and scatter back to original positions ----------------
__global__ void combine_scatter_kernel() {
    int gid = blockIdx.x * 256 + threadIdx.x;
    if (gid >= Bv*Cch*HW) return;
    int r = gid % HW; int c = (gid / HW) % 64; int b = gid / (HW * 64);
    int dst = g_idx[(size_t)(b*64 + c)*SEG + r];
    g_pre[(size_t)(b*64 + c)*HW + dst] = g_o1[gid] * g_o2[gid];
}

// ---------------- final unsort of first 32 channels ----------------
__global__ void final_kernel(float* __restrict__ out) {
    int gid = blockIdx.x * 256 + threadIdx.x;
    if (gid >= Bv*Cch*HW) return;
    int w = gid % Wdim; int h = (gid / Wdim) % Hdim;
    int c = (gid / HW) % 64; int b = gid / (HW * 64);
    if (c < 32) {
        int hh = g_invh[((b*32 + c)*Hdim + h)*Wdim + w];
        int ww = g_invw[((b*32 + c)*Hdim + hh)*Wdim + w];
        out[gid] = g_outp[(size_t)(b*64 + c)*HW + hh*Wdim + ww];
    } else {
        out[gid] = g_outp[gid];
    }
}

// ---------------- launcher ----------------
extern "C" void kernel_launch(void* const* d_in, const int* in_sizes, int n_in,
                              void* d_out, int out_size) {
    (void)in_sizes; (void)n_in; (void)out_size;
    const float* x      = (const float*)d_in[0];
    const float* temp   = (const float*)d_in[1];
    const float* w_qkv  = (const float*)d_in[2];
    const float* w_dw3  = (const float*)d_in[3];
    const float* w_dw5  = (const float*)d_in[4];
    const float* w_dw7  = (const float*)d_in[5];
    const float* w_fuse = (const float*)d_in[6];
    const float* b_fuse = (const float*)d_in[7];
    const float* w_proj = (const float*)d_in[8];
    float* out = (float*)d_out;

    cudaFuncSetAttribute(bigsort_kernel, cudaFuncAttributeMaxDynamicSharedMemorySize, 65536);

    void *p_xwork, *p_q, *p_cat, *p_qkv, *p_pre, *p_outp;
    void *p_gq1, *p_gk1, *p_gq2, *p_gk2, *p_vsc, *p_tq2, *p_tk2, *p_tv;
    void *p_o1, *p_ont, *p_part, *p_attn, *p_nq, *p_nk;
    cudaGetSymbolAddress(&p_xwork, g_xwork);
    cudaGetSymbolAddress(&p_q, g_q);
    cudaGetSymbolAddress(&p_cat, g_cat);
    cudaGetSymbolAddress(&p_qkv, g_qkv);
    cudaGetSymbolAddress(&p_pre, g_pre);
    cudaGetSymbolAddress(&p_outp, g_outp);
    cudaGetSymbolAddress(&p_gq1, g_gq1);
    cudaGetSymbolAddress(&p_gk1, g_gk1);
    cudaGetSymbolAddress(&p_gq2, g_gq2);
    cudaGetSymbolAddress(&p_gk2, g_gk2);
    cudaGetSymbolAddress(&p_vsc, g_vsc);
    cudaGetSymbolAddress(&p_tq2, g_tq2);
    cudaGetSymbolAddress(&p_tk2, g_tk2);
    cudaGetSymbolAddress(&p_tv, g_tv);
    cudaGetSymbolAddress(&p_o1, g_o1);
    cudaGetSymbolAddress(&p_ont, g_ont);
    cudaGetSymbolAddress(&p_part, g_part);
    cudaGetSymbolAddress(&p_attn, g_attn);
    cudaGetSymbolAddress(&p_nq, g_nq);
    cudaGetSymbolAddress(&p_nk, g_nk);

    const int NELT = Bv*Cch*HW;
    const int EB = (NELT + 255) / 256;

    // 1) channel sorts + copy of untouched channels
    copy_rest_kernel<<<(Bv*32*HW + 255)/256, 256>>>(x);
    sort_h_kernel<<<Bv*32*Wdim, 256>>>(x);
    sort_w_kernel<<<Bv*32*Hdim, 256>>>();

    // 2) q = w_qkv @ x   (M=320, K=64, N=36864)
    gemm_kernel<<<dim3(HW/64, (320 + 127)/128, Bv), 256>>>(
        w_qkv, (const float*)p_xwork, nullptr, (float*)p_q, 320, 64, HW);

    // 3) depthwise 3/5/7 -> cat
    dwconv_kernel<<<dim3(144, 320, Bv), dim3(16, 16)>>>(w_dw3, w_dw5, w_dw7);

    // 4) qkv = w_fuse @ cat + b  (M=320, K=960)
    gemm_kernel<<<dim3(HW/64, (320 + 127)/128, Bv), 256>>>(
        w_fuse, (const float*)p_cat, b_fuse, (float*)p_qkv, 320, 960, HW);

    // 5) per-(b,c) argsort of v
    bigsort_kernel<<<128, 1024, 65536>>>();

    // 6) gather + non-box transposes
    gather_kernel<<<EB, 256>>>();
    nbt_kernel<<<EB, 256>>>((const float*)p_gq2, (float*)p_tq2);
    nbt_kernel<<<EB, 256>>>((const float*)p_gk2, (float*)p_tk2);
    nbt_kernel<<<EB, 256>>>((const float*)p_vsc, (float*)p_tv);

    // 7) L2 norms
    norm_kernel<<<512, 256>>>((const float*)p_gq1, (float*)p_nq);
    norm_kernel<<<512, 256>>>((const float*)p_gk1, (float*)p_nk);
    norm_kernel<<<512, 256>>>((const float*)p_tq2, (float*)p_nq + 512);
    norm_kernel<<<512, 256>>>((const float*)p_tk2, (float*)p_nk + 512);

    // 8) Q.K^T partials + softmax
    qk_partial_kernel<<<dim3(16, 8), 256>>>((const float*)p_gq1, (const float*)p_gk1,
                                            (float*)p_part);
    qk_partial_kernel<<<dim3(16, 8), 256>>>((const float*)p_tq2, (const float*)p_tk2,
                                            (float*)p_part + 8*16*4096);
    softmax_kernel<<<dim3(8, 2), 64>>>(temp);

    // 9) o = attn @ vv (both variants), un-transpose non-box
    o_gemm_kernel<<<dim3(144, 8), 256>>>((const float*)p_attn, (const float*)p_vsc,
                                         (float*)p_o1);
    o_gemm_kernel<<<dim3(144, 8), 256>>>((const float*)p_attn + 8*4096, (const float*)p_tv,
                                         (float*)p_ont);
    nbt_inv_kernel<<<EB, 256>>>();

    // 10) combine + scatter back, proj, final unsort
    combine_scatter_kernel<<<EB, 256>>>();
    gemm_kernel<<<dim3(HW/64, 1, Bv), 256>>>(
        w_proj, (const float*)p_pre, nullptr, (float*)p_outp, 64, 64, HW);
    final_kernel<<<EB, 256>>>(out);
}

// round 9
// speedup vs baseline: 1.0510x; 1.0510x over previous
#include <cuda_runtime.h>
#include <math.h>
#include <cstdint>

#define Bv 2
#define Cch 64
#define Hdim 192
#define Wdim 192
#define HW 36864
#define SEG 65536
#define CHUNK 8192

// ---------------- scratch (static device globals; no runtime allocation) ----------------
__device__ float g_xwork[Bv*Cch*HW];
__device__ int   g_invh[Bv*32*HW];
__device__ int   g_invw[Bv*32*HW];
__device__ float g_q[Bv*320*HW];
__device__ float g_cat[Bv*960*HW];
__device__ float g_qkv[Bv*320*HW];
__device__ float g_keys[Bv*64*SEG];
__device__ int   g_idx[Bv*64*SEG];
__device__ float g_gq1[Bv*Cch*HW];
__device__ float g_gk1[Bv*Cch*HW];
__device__ float g_gq2[Bv*Cch*HW];
__device__ float g_gk2[Bv*Cch*HW];
__device__ float g_vsc[Bv*Cch*HW];
__device__ float g_tq2[Bv*Cch*HW];
__device__ float g_tk2[Bv*Cch*HW];
__device__ float g_tv [Bv*Cch*HW];
__device__ float g_o1 [Bv*Cch*HW];
__device__ float g_ont[Bv*Cch*HW];
__device__ float g_o2 [Bv*Cch*HW];
__device__ float g_pre[Bv*Cch*HW];
__device__ float g_outp[Bv*Cch*HW];
__device__ float g_part[2*8*16*4096];
__device__ float g_attn[2*8*4096];
__device__ float g_nq[2*512];
__device__ float g_nk[2*512];

// ================= exact fp32 SIMT GEMM, BM=128 (q GEMM) =================
__global__ void gemm_kernel(const float* __restrict__ A, const float* __restrict__ Bm,
                            const float* __restrict__ bias, float* __restrict__ Cm,
                            int M, int K, int N) {
    const int BM = 128, BN = 64, BK = 16;
    int bn = blockIdx.x * BN, bm = blockIdx.y * BM, bb = blockIdx.z;
    const float* Bp = Bm + (size_t)bb * K * N;
    float* Cp = Cm + (size_t)bb * M * N;
    __shared__ float As[BK][BM];
    __shared__ float Bs[BK][BN];
    int tid = threadIdx.x;
    int tx = tid & 15, ty = tid >> 4;
    int rm = ty * 8, rn = tx * 4;
    float acc[8][4];
    #pragma unroll
    for (int i = 0; i < 8; i++)
        #pragma unroll
        for (int j = 0; j < 4; j++) acc[i][j] = 0.f;

    for (int k0 = 0; k0 < K; k0 += BK) {
        {
            int lm = tid >> 1;
            int lk = (tid & 1) * 8;
            int gm = bm + lm;
            if (gm < M) {
                float4 v0 = *reinterpret_cast<const float4*>(&A[(size_t)gm*K + k0 + lk]);
                float4 v1 = *reinterpret_cast<const float4*>(&A[(size_t)gm*K + k0 + lk + 4]);
                As[lk+0][lm] = v0.x; As[lk+1][lm] = v0.y; As[lk+2][lm] = v0.z; As[lk+3][lm] = v0.w;
                As[lk+4][lm] = v1.x; As[lk+5][lm] = v1.y; As[lk+6][lm] = v1.z; As[lk+7][lm] = v1.w;
            } else {
                #pragma unroll
                for (int i = 0; i < 8; i++) As[lk+i][lm] = 0.f;
            }
        }
        {
            int lk = tid >> 4; int ln = (tid & 15) * 4;
            float4 v = *reinterpret_cast<const float4*>(&Bp[(size_t)(k0 + lk)*N + bn + ln]);
            *reinterpret_cast<float4*>(&Bs[lk][ln]) = v;
        }
        __syncthreads();
        #pragma unroll
        for (int k = 0; k < BK; k++) {
            float4 a0 = *reinterpret_cast<const float4*>(&As[k][rm]);
            float4 a1 = *reinterpret_cast<const float4*>(&As[k][rm + 4]);
            float4 bv4 = *reinterpret_cast<const float4*>(&Bs[k][rn]);
            float av[8] = {a0.x, a0.y, a0.z, a0.w, a1.x, a1.y, a1.z, a1.w};
            float bv[4] = {bv4.x, bv4.y, bv4.z, bv4.w};
            #pragma unroll
            for (int i = 0; i < 8; i++)
                #pragma unroll
                for (int j = 0; j < 4; j++) acc[i][j] += av[i] * bv[j];
        }
        __syncthreads();
    }
    #pragma unroll
    for (int i = 0; i < 8; i++) {
        int gm = bm + rm + i;
        if (gm < M) {
            float bvv = bias ? bias[gm] : 0.f;
            float4 o = make_float4(acc[i][0] + bvv, acc[i][1] + bvv, acc[i][2] + bvv, acc[i][3] + bvv);
            *reinterpret_cast<float4*>(&Cp[(size_t)gm*N + bn + rn]) = o;
        }
    }
}

// ================= exact fp32 SIMT GEMM, BM=64 (v rows + proj) =================
// M fixed 64, N=HW, BN=128, BK=16, 256 threads, 4x8 per thread.
__global__ void __launch_bounds__(256) gemm64(const float* __restrict__ A,
                                              const float* __restrict__ Bg,
                                              const float* __restrict__ bias,
                                              float* __restrict__ Cg, int K,
                                              long long bstr, long long cstr) {
    __shared__ float As[16][68];
    __shared__ float Bs[16][132];
    int tid = threadIdx.x;
    int bn = blockIdx.x * 128;
    const float* Bz = Bg + (size_t)blockIdx.z * bstr;
    float* Cz = Cg + (size_t)blockIdx.z * cstr;
    int arow = tid >> 2, akq = (tid & 3) * 4;
    int rm = (tid >> 4) * 4, rn = (tid & 15) * 8;
    float acc[4][8];
    #pragma unroll
    for (int i = 0; i < 4; i++)
        #pragma unroll
        for (int j = 0; j < 8; j++) acc[i][j] = 0.f;

    for (int k0 = 0; k0 < K; k0 += 16) {
        float4 av = *reinterpret_cast<const float4*>(&A[(size_t)arow * K + k0 + akq]);
        As[akq+0][arow] = av.x; As[akq+1][arow] = av.y;
        As[akq+2][arow] = av.z; As[akq+3][arow] = av.w;
        #pragma unroll
        for (int j = 0; j < 2; j++) {
            int v = tid + j * 256;
            int kk = v >> 5, nq = (v & 31) * 4;
            *reinterpret_cast<float4*>(&Bs[kk][nq]) =
                *reinterpret_cast<const float4*>(&Bz[(size_t)(k0 + kk)*HW + bn + nq]);
        }
        __syncthreads();
        #pragma unroll
        for (int kk = 0; kk < 16; kk++) {
            float a0 = As[kk][rm], a1 = As[kk][rm+1], a2 = As[kk][rm+2], a3 = As[kk][rm+3];
            float b[8];
            *reinterpret_cast<float4*>(&b[0]) = *reinterpret_cast<const float4*>(&Bs[kk][rn]);
            *reinterpret_cast<float4*>(&b[4]) = *reinterpret_cast<const float4*>(&Bs[kk][rn+4]);
            #pragma unroll
            for (int j = 0; j < 8; j++) {
                acc[0][j] += a0 * b[j];
                acc[1][j] += a1 * b[j];
                acc[2][j] += a2 * b[j];
                acc[3][j] += a3 * b[j];
            }
        }
        __syncthreads();
    }
    #pragma unroll
    for (int i = 0; i < 4; i++) {
        float bv = bias ? bias[rm + i] : 0.f;
        float4 o0 = make_float4(acc[i][0]+bv, acc[i][1]+bv, acc[i][2]+bv, acc[i][3]+bv);
        float4 o1 = make_float4(acc[i][4]+bv, acc[i][5]+bv, acc[i][6]+bv, acc[i][7]+bv);
        *reinterpret_cast<float4*>(&Cz[(size_t)(rm+i)*HW + bn + rn])     = o0;
        *reinterpret_cast<float4*>(&Cz[(size_t)(rm+i)*HW + bn + rn + 4]) = o1;
    }
}

// ================= mma.sync 3xTF32 GEMM (attention-operand rows only) =================
#define CP16CG(dst, src) asm volatile("cp.async.cg.shared.global [%0], [%1], 16;" :: "r"(dst), "l"(src) : "memory")
#define CP16CA(dst, src) asm volatile("cp.async.ca.shared.global [%0], [%1], 16;" :: "r"(dst), "l"(src) : "memory")
#define CP_COMMIT() asm volatile("cp.async.commit_group;" ::: "memory")
#define CP_WAIT(n)  asm volatile("cp.async.wait_group %0;" :: "n"(n) : "memory")
#define MMA_TF32(d, a0, a1, a2, a3, b0, b1) \
    asm volatile("mma.sync.aligned.m16n8k8.row.col.f32.tf32.tf32.f32 " \
        "{%0,%1,%2,%3}, {%4,%5,%6,%7}, {%8,%9}, {%0,%1,%2,%3};" \
        : "+f"((d)[0]), "+f"((d)[1]), "+f"((d)[2]), "+f"((d)[3]) \
        : "r"(a0), "r"(a1), "r"(a2), "r"(a3), "r"(b0), "r"(b1))

__device__ __forceinline__ uint32_t smem_u32(const void* p) {
    uint32_t a;
    asm("{ .reg .u64 t; cvta.to.shared.u64 t, %1; cvt.u32.u64 %0, t; }" : "=r"(a) : "l"(p));
    return a;
}
__device__ __forceinline__ void tf32_split(float x, uint32_t& hi, uint32_t& lo) {
    uint32_t h;
    asm("cvt.rna.tf32.f32 %0, %1;" : "=r"(h) : "f"(x));
    float r = x - __uint_as_float(h);
    asm("cvt.rna.tf32.f32 %0, %1;" : "=r"(lo) : "f"(r));
    hi = h;
}

// BM=64, BN=256, BK=32, 3-stage cp.async, 8 warps (2Mx4N), warp tile 32x64.
// grid: x = M-tiles (share B strip in L2), y = N-tiles, z = batch.
// M param = full C row count (batch stride); grid.x limits which rows are computed.
template<int NC, bool HASBIAS>
__global__ void __launch_bounds__(256, 1) mma_gemm(const float* __restrict__ A,
                                                   const float* __restrict__ Bg,
                                                   const float* __restrict__ bias,
                                                   float* __restrict__ Cg, int M) {
    constexpr int K = NC * 32;
    constexpr int N = HW;
    constexpr int STAGES = 3;
    constexpr int APITCH = 36;
    constexpr int BPITCH = 260;
    constexpr int AWORDS = 64 * APITCH;
    constexpr int STAGE_WORDS = AWORDS + 32 * BPITCH;

    extern __shared__ float sm[];
    int tid = threadIdx.x;
    int bm = blockIdx.x * 64;
    int bn = blockIdx.y * 256;
    const float* Az = A + (size_t)bm * K;
    const float* Bz = Bg + (size_t)blockIdx.z * K * N;
    float* Cz = Cg + (size_t)blockIdx.z * M * N;
    uint32_t sbase = smem_u32(sm);

    auto load_stage = [&](int chunk, int buf) {
        int k0 = chunk * 32;
        uint32_t abase = sbase + (uint32_t)buf * STAGE_WORDS * 4;
        #pragma unroll
        for (int j = 0; j < 2; j++) {
            int v = tid + j * 256;
            int m = v >> 3, kq = v & 7;
            uint32_t dst = abase + (uint32_t)(m * APITCH + kq * 4) * 4;
            const float* src = Az + (size_t)m * K + k0 + kq * 4;
            CP16CA(dst, src);
        }
        uint32_t bbase = abase + AWORDS * 4;
        #pragma unroll
        for (int j = 0; j < 8; j++) {
            int v = tid + j * 256;
            int k = v >> 6, nq = v & 63;
            uint32_t dst = bbase + (uint32_t)(k * BPITCH + nq * 4) * 4;
            const float* src = Bz + (size_t)(k0 + k) * N + bn + nq * 4;
            CP16CG(dst, src);
        }
    };

    int lane = tid & 31, g = lane >> 2, tg = lane & 3;
    int wid = tid >> 5;
    int wm = (wid & 1) * 32;
    int wn = (wid >> 1) * 64;

    float acc[2][8][4];
    #pragma unroll
    for (int mf = 0; mf < 2; mf++)
        #pragma unroll
        for (int nf = 0; nf < 8; nf++)
            #pragma unroll
            for (int q = 0; q < 4; q++) acc[mf][nf][q] = 0.f;

    #pragma unroll
    for (int s = 0; s < STAGES - 1; s++) {
        if (s < NC) load_stage(s, s);
        CP_COMMIT();
    }

    for (int c = 0; c < NC; c++) {
        CP_WAIT(STAGES - 2);
        __syncthreads();
        {
            int nxt = c + STAGES - 1;
            if (nxt < NC) load_stage(nxt, nxt % STAGES);
            CP_COMMIT();
        }
        const float* As = sm + (size_t)(c % STAGES) * STAGE_WORDS;
        const float* Bs = As + AWORDS;
        #pragma unroll
        for (int ks = 0; ks < 4; ks++) {
            int ka = ks * 8 + tg;
            uint32_t ah[2][4], al[2][4];
            #pragma unroll
            for (int mf = 0; mf < 2; mf++) {
                int m = wm + mf * 16 + g;
                tf32_split(As[m * APITCH + ka],           ah[mf][0], al[mf][0]);
                tf32_split(As[(m + 8) * APITCH + ka],     ah[mf][1], al[mf][1]);
                tf32_split(As[m * APITCH + ka + 4],       ah[mf][2], al[mf][2]);
                tf32_split(As[(m + 8) * APITCH + ka + 4], ah[mf][3], al[mf][3]);
            }
            #pragma unroll
            for (int nf = 0; nf < 8; nf++) {
                int n = wn + nf * 8 + g;
                uint32_t b0h, b0l, b1h, b1l;
                tf32_split(Bs[ka * BPITCH + n],       b0h, b0l);
                tf32_split(Bs[(ka + 4) * BPITCH + n], b1h, b1l);
                #pragma unroll
                for (int mf = 0; mf < 2; mf++) {
                    MMA_TF32(acc[mf][nf], ah[mf][0], ah[mf][1], ah[mf][2], ah[mf][3], b0h, b1h);
                    MMA_TF32(acc[mf][nf], ah[mf][0], ah[mf][1], ah[mf][2], ah[mf][3], b0l, b1l);
                    MMA_TF32(acc[mf][nf], al[mf][0], al[mf][1], al[mf][2], al[mf][3], b0h, b1h);
                }
            }
        }
        __syncthreads();
    }

    #pragma unroll
    for (int mf = 0; mf < 2; mf++) {
        int row = bm + wm + mf * 16 + g;
        float bv0 = 0.f, bv1 = 0.f;
        if (HASBIAS) { bv0 = bias[row]; bv1 = bias[row + 8]; }
        #pragma unroll
        for (int nf = 0; nf < 8; nf++) {
            int col = bn + wn + nf * 8 + 2 * tg;
            float2 v0 = make_float2(acc[mf][nf][0] + bv0, acc[mf][nf][1] + bv0);
            float2 v1 = make_float2(acc[mf][nf][2] + bv1, acc[mf][nf][3] + bv1);
            *reinterpret_cast<float2*>(&Cz[(size_t)row * N + col]) = v0;
            *reinterpret_cast<float2*>(&Cz[(size_t)(row + 8) * N + col]) = v1;
        }
    }
}

// ---------------- small 192-element sorts (stable bitonic, padded to 256) ----------------
__global__ void sort_h_kernel(const float* __restrict__ x) {
    int blk = blockIdx.x;
    int w = blk % Wdim; int c = (blk / Wdim) % 32; int b = blk / (Wdim * 32);
    __shared__ float key[256];
    __shared__ int   ind[256];
    int t = threadIdx.x;
    key[t] = (t < Hdim) ? x[((b*Cch + c)*Hdim + t)*Wdim + w] : INFINITY;
    ind[t] = t;
    __syncthreads();
    for (int k = 2; k <= 256; k <<= 1) {
        for (int s = k >> 1; s > 0; s >>= 1) {
            int j = t ^ s;
            if (j > t) {
                bool up = ((t & k) == 0);
                float ka = key[t], kb = key[j];
                int ia = ind[t], ib = ind[j];
                bool agtb = (ka > kb) || (ka == kb && ia > ib);
                if (agtb == up) { key[t] = kb; key[j] = ka; ind[t] = ib; ind[j] = ia; }
            }
            __syncthreads();
        }
    }
    if (t < Hdim) {
        g_xwork[((b*Cch + c)*Hdim + t)*Wdim + w] = key[t];
        g_invh[((b*32 + c)*Hdim + ind[t])*Wdim + w] = t;
    }
}

__global__ void sort_w_kernel() {
    int blk = blockIdx.x;
    int h = blk % Hdim; int c = (blk / Hdim) % 32; int b = blk / (Hdim * 32);
    int base = ((b*Cch + c)*Hdim + h)*Wdim;
    __shared__ float key[256];
    __shared__ int   ind[256];
    int t = threadIdx.x;
    key[t] = (t < Wdim) ? g_xwork[base + t] : INFINITY;
    ind[t] = t;
    __syncthreads();
    for (int k = 2; k <= 256; k <<= 1) {
        for (int s = k >> 1; s > 0; s >>= 1) {
            int j = t ^ s;
            if (j > t) {
                bool up = ((t & k) == 0);
                float ka = key[t], kb = key[j];
                int ia = ind[t], ib = ind[j];
                bool agtb = (ka > kb) || (ka == kb && ia > ib);
                if (agtb == up) { key[t] = kb; key[j] = ka; ind[t] = ib; ind[j] = ia; }
            }
            __syncthreads();
        }
    }
    if (t < Wdim) {
        g_xwork[base + t] = key[t];
        g_invw[((b*32 + c)*Hdim + h)*Wdim + ind[t]] = t;
    }
}

__global__ void copy_rest_kernel(const float* __restrict__ x) {
    int gid = blockIdx.x * 256 + threadIdx.x;
    if (gid >= Bv*32*HW) return;
    int p = gid % HW; int c = (gid / HW) % 32; int b = gid / (32 * HW);
    int o = (b*Cch + 32 + c)*HW + p;
    g_xwork[o] = x[o];
}

// ---------------- fused depthwise 3x3 / 5x5 / 7x7 ----------------
__global__ void dwconv_kernel(const float* __restrict__ w3, const float* __restrict__ w5,
                              const float* __restrict__ w7) {
    int tile = blockIdx.x; int ch = blockIdx.y; int b = blockIdx.z;
    int ty0 = (tile / 12) * 16, tx0 = (tile % 12) * 16;
    __shared__ float s[22][24];
    __shared__ float wts[83];
    int tid = threadIdx.y * 16 + threadIdx.x;
    if (tid < 9)       wts[tid] = w3[ch*9 + tid];
    else if (tid < 34) wts[tid] = w5[ch*25 + tid - 9];
    else if (tid < 83) wts[tid] = w7[ch*49 + tid - 34];
    const float* base = g_q + (size_t)(b*320 + ch) * HW;
    for (int i = tid; i < 22*22; i += 256) {
        int sy = i / 22, sx = i % 22;
        int gy = ty0 + sy - 3, gx = tx0 + sx - 3;
        s[sy][sx] = (gy >= 0 && gy < Hdim && gx >= 0 && gx < Wdim) ? base[gy*Wdim + gx] : 0.f;
    }
    __syncthreads();
    int y = threadIdx.y, x = threadIdx.x;
    float a3 = 0.f, a5 = 0.f, a7 = 0.f;
    #pragma unroll
    for (int dy = 0; dy < 7; dy++)
        #pragma unroll
        for (int dx = 0; dx < 7; dx++) {
            float v = s[y + dy][x + dx];
            a7 += wts[34 + dy*7 + dx] * v;
            if (dy >= 1 && dy <= 5 && dx >= 1 && dx <= 5) a5 += wts[9 + (dy-1)*5 + (dx-1)] * v;
            if (dy >= 2 && dy <= 4 && dx >= 2 && dx <= 4) a3 += wts[(dy-2)*3 + (dx-2)] * v;
        }
    int gp = (ty0 + y)*Wdim + tx0 + x;
    size_t bo = (size_t)b * 960 * HW;
    g_cat[bo + (size_t)ch*HW + gp]        = a3;
    g_cat[bo + (size_t)(320 + ch)*HW + gp] = a5;
    g_cat[bo + (size_t)(640 + ch)*HW + gp] = a7;
}

// ---------------- big argsort of V ----------------
__device__ __forceinline__ void ce_smem(float* sk, int* si, int i, int j, bool up) {
    float ka = sk[i], kb = sk[j];
    int ia = si[i], ib = si[j];
    bool agtb = (ka > kb) || (ka == kb && ia > ib);
    if (agtb == up) { sk[i] = kb; sk[j] = ka; si[i] = ib; si[j] = ia; }
}

__global__ void bigsort_kernel() {
    int seg = blockIdx.x;
    float* K = g_keys + (size_t)seg * SEG;
    int*   I = g_idx  + (size_t)seg * SEG;
    const float* src = g_qkv + ((size_t)(seg >> 6) * 320 + 256 + (seg & 63)) * HW;
    extern __shared__ float sm[];
    float* sk = sm;
    int*   si = (int*)(sm + CHUNK);
    int t = threadIdx.x;

    for (int i = t; i < SEG; i += 1024) { K[i] = (i < HW) ? src[i] : INFINITY; I[i] = i; }
    __syncthreads();

    for (int cb = 0; cb < SEG; cb += CHUNK) {
        for (int i = t; i < CHUNK; i += 1024) { sk[i] = K[cb + i]; si[i] = I[cb + i]; }
        __syncthreads();
        for (int k = 2; k <= CHUNK; k <<= 1) {
            for (int s = k >> 1; s > 0; s >>= 1) {
                for (int p = t; p < CHUNK/2; p += 1024) {
                    int i = ((p & ~(s - 1)) << 1) | (p & (s - 1));
                    int j = i + s;
                    bool up = (((cb + i) & k) == 0);
                    ce_smem(sk, si, i, j, up);
                }
                __syncthreads();
            }
        }
        for (int i = t; i < CHUNK; i += 1024) { K[cb + i] = sk[i]; I[cb + i] = si[i]; }
        __syncthreads();
    }

    for (int k = CHUNK*2; k <= SEG; k <<= 1) {
        for (int s = k >> 1; s >= CHUNK; s >>= 1) {
            for (int p = t; p < SEG/2; p += 1024) {
                int i = ((p & ~(s - 1)) << 1) | (p & (s - 1));
                int j = i + s;
                bool up = ((i & k) == 0);
                float ka = K[i], kb = K[j];
                int ia = I[i], ib = I[j];
                bool agtb = (ka > kb) || (ka == kb && ia > ib);
                if (agtb == up) { K[i] = kb; K[j] = ka; I[i] = ib; I[j] = ia; }
            }
            __syncthreads();
        }
        for (int cb = 0; cb < SEG; cb += CHUNK) {
            for (int i = t; i < CHUNK; i += 1024) { sk[i] = K[cb + i]; si[i] = I[cb + i]; }
            __syncthreads();
            for (int s = CHUNK >> 1; s > 0; s >>= 1) {
                for (int p = t; p < CHUNK/2; p += 1024) {
                    int i = ((p & ~(s - 1)) << 1) | (p & (s - 1));
                    int j = i + s;
                    bool up = (((cb + i) & k) == 0);
                    ce_smem(sk, si, i, j, up);
                }
                __syncthreads();
            }
            for (int i = t; i < CHUNK; i += 1024) { K[cb + i] = sk[i]; I[cb + i] = si[i]; }
            __syncthreads();
        }
    }
}

// ---------------- gather q1/k1/q2/k2 + sorted v ----------------
__global__ void gather_kernel() {
    int gid = blockIdx.x * 256 + threadIdx.x;
    if (gid >= Bv*Cch*HW) return;
    int r = gid % HW; int c = (gid / HW) % Cch; int b = gid / (HW * Cch);
    int src = g_idx[(size_t)(b*64 + c)*SEG + r];
    size_t qb = (size_t)b * 320 * HW;
    g_gq1[gid] = g_qkv[qb + (size_t)c*HW + src];
    g_gk1[gid] = g_qkv[qb + (size_t)(64 + c)*HW + src];
    g_gq2[gid] = g_qkv[qb + (size_t)(128 + c)*HW + src];
    g_gk2[gid] = g_qkv[qb + (size_t)(192 + c)*HW + src];
    g_vsc[gid] = g_keys[(size_t)(b*64 + c)*SEG + r];
}

__global__ void nbt_kernel(const float* __restrict__ in, float* __restrict__ out) {
    int gid = blockIdx.x * 256 + threadIdx.x;
    if (gid >= Bv*Cch*HW) return;
    int n = gid % 9216; int d = (gid / 9216) % 64; int bh = gid / (9216 * 64);
    int b = bh >> 2, h = bh & 3;
    out[gid] = in[((size_t)(b*64 + h*16 + (d >> 2)))*HW + n*4 + (d & 3)];
}

__global__ void nbt_inv_kernel() {
    int gid = blockIdx.x * 256 + threadIdx.x;
    if (gid >= Bv*Cch*HW) return;
    int p = gid % HW; int c = (gid / HW) % 64; int b = gid / (HW * 64);
    int h = c >> 4, chi = c & 15;
    int f = p & 3, n = p >> 2;
    int d = chi*4 + f;
    g_o2[gid] = g_ont[((size_t)(b*4 + h)*64 + d)*9216 + n];
}

__global__ void norm_kernel(const float* __restrict__ t, float* __restrict__ out) {
    int row = blockIdx.x;
    const float* p = t + (size_t)row * 9216;
    float ss = 0.f;
    for (int i = threadIdx.x; i < 9216; i += 256) { float v = p[i]; ss += v * v; }
    __shared__ float red[256];
    red[threadIdx.x] = ss;
    __syncthreads();
    for (int o = 128; o > 0; o >>= 1) {
        if (threadIdx.x < o) red[threadIdx.x] += red[threadIdx.x + o];
        __syncthreads();
    }
    if (threadIdx.x == 0) out[row] = fmaxf(sqrtf(red[0]), 1e-12f);
}

__global__ void qk_partial_kernel(const float* __restrict__ q, const float* __restrict__ k,
                                  float* __restrict__ part) {
    int kc = blockIdx.x, bh = blockIdx.y;
    const float* qb = q + (size_t)bh * 64 * 9216;
    const float* kb = k + (size_t)bh * 64 * 9216;
    __shared__ float qs[64][65];
    __shared__ float ks[64][65];
    int tid = threadIdx.x;
    int rm = (tid >> 4) * 4, rn = (tid & 15) * 4;
    float acc[4][4];
    #pragma unroll
    for (int i = 0; i < 4; i++)
        #pragma unroll
        for (int j = 0; j < 4; j++) acc[i][j] = 0.f;
    int nbase0 = kc * 576;
    for (int nt = 0; nt < 576; nt += 64) {
        #pragma unroll
        for (int l = 0; l < 16; l++) {
            int lin = l * 256 + tid;
            int d = lin >> 6, nn = lin & 63;
            qs[d][nn] = qb[(size_t)d*9216 + nbase0 + nt + nn];
            ks[d][nn] = kb[(size_t)d*9216 + nbase0 + nt + nn];
        }
        __syncthreads();
        #pragma unroll 8
        for (int nn = 0; nn < 64; nn++) {
            float a[4], bv[4];
            #pragma unroll
            for (int i = 0; i < 4; i++) a[i] = qs[rm + i][nn];
            #pragma unroll
            for (int j = 0; j < 4; j++) bv[j] = ks[rn + j][nn];
            #pragma unroll
            for (int i = 0; i < 4; i++)
                #pragma unroll
                for (int j = 0; j < 4; j++) acc[i][j] += a[i] * bv[j];
        }
        __syncthreads();
    }
    float* pp = part + ((size_t)bh * 16 + kc) * 4096;
    #pragma unroll
    for (int i = 0; i < 4; i++)
        #pragma unroll
        for (int j = 0; j < 4; j++) pp[(rm + i)*64 + rn + j] = acc[i][j];
}

__global__ void softmax_kernel(const float* __restrict__ temp) {
    int bh = blockIdx.x, var = blockIdx.y;
    int d = threadIdx.x;
    int h = bh & 3;
    const float* pp = g_part + ((size_t)(var*8 + bh) * 16) * 4096;
    float qn = g_nq[var*512 + bh*64 + d];
    float tmp = temp[h];
    float ev[64];
    float rs = 0.f;
    #pragma unroll
    for (int e = 0; e < 64; e++) {
        float s = 0.f;
        #pragma unroll
        for (int c2 = 0; c2 < 16; c2++) s += pp[(size_t)c2*4096 + d*64 + e];
        float a = s * tmp / (qn * g_nk[var*512 + bh*64 + e]);
        float x = expf(a);
        ev[e] = x;
        rs += x;
    }
    float inv = 1.f / (rs + 1.f);
    float* ap = g_attn + (size_t)(var*8 + bh) * 4096;
    #pragma unroll
    for (int e = 0; e < 64; e++) ap[d*64 + e] = ev[e] * inv;
}

__global__ void o_gemm_kernel(const float* __restrict__ attn, const float* __restrict__ v,
                              float* __restrict__ o) {
    int nt = blockIdx.x * 64, bh = blockIdx.y;
    const float* ap = attn + (size_t)bh * 4096;
    const float* vp = v + (size_t)bh * 64 * 9216;
    float* op = o + (size_t)bh * 64 * 9216;
    __shared__ float as_[64][65];
    __shared__ float vs_[64][65];
    int tid = threadIdx.x;
    #pragma unroll
    for (int l = 0; l < 16; l++) {
        int lin = l * 256 + tid;
        int r = lin >> 6, cc = lin & 63;
        as_[r][cc] = ap[lin];
        vs_[r][cc] = vp[(size_t)r*9216 + nt + cc];
    }
    __syncthreads();
    int rm = (tid >> 4) * 4, rn = (tid & 15) * 4;
    float acc[4][4];
    #pragma unroll
    for (int i = 0; i < 4; i++)
        #pragma unroll
        for (int j = 0; j < 4; j++) acc[i][j] = 0.f;
    #pragma unroll 8
    for (int e = 0; e < 64; e++) {
        float a[4], bv[4];
        #pragma unroll
        for (int i = 0; i < 4; i++) a[i] = as_[rm + i][e];
        #pragma unroll
        for (int j = 0; j < 4; j++) bv[j] = vs_[e][rn + j];
        #pragma unroll
        for (int i = 0; i < 4; i++)
            #pragma unroll
            for (int j = 0; j < 4; j++) acc[i][j] += a[i] * bv[j];
    }
    #pragma unroll
    for (int i = 0; i < 4; i++) {
        float4 ov = make_float4(acc[i][0], acc[i][1], acc[i][2], acc[i][3]);
        *reinterpret_cast<float4*>(&op[(size_t)(rm + i)*9216 + nt + rn]) = ov;
    }
}

__global__ void combine_scatter_kernel() {
    int gid = blockIdx.x * 256 + threadIdx.x;
    if (gid >= Bv*Cch*HW) return;
    int r = gid % HW; int c = (gid / HW) % 64; int b = gid / (HW * 64);
    int dst = g_idx[(size_t)(b*64 + c)*SEG + r];
    g_pre[(size_t)(b*64 + c)*HW + dst] = g_o1[gid] * g_o2[gid];
}

__global__ void final_kernel(float* __restrict__ out) {
    int gid = blockIdx.x * 256 + threadIdx.x;
    if (gid >= Bv*Cch*HW) return;
    int w = gid % Wdim; int h = (gid / Wdim) % Hdim;
    int c = (gid / HW) % 64; int b = gid / (HW * 64);
    if (c < 32) {
        int hh = g_invh[((b*32 + c)*Hdim + h)*Wdim + w];
        int ww = g_invw[((b*32 + c)*Hdim + hh)*Wdim + w];
        out[gid] = g_outp[(size_t)(b*64 + c)*HW + hh*Wdim + ww];
    } else {
        out[gid] = g_outp[gid];
    }
}

// ---------------- launcher ----------------
extern "C" void kernel_launch(void* const* d_in, const int* in_sizes, int n_in,
                              void* d_out, int out_size) {
    (void)in_sizes; (void)n_in; (void)out_size;
    const float* x      = (const float*)d_in[0];
    const float* temp   = (const float*)d_in[1];
    const float* w_qkv  = (const float*)d_in[2];
    const float* w_dw3  = (const float*)d_in[3];
    const float* w_dw5  = (const float*)d_in[4];
    const float* w_dw7  = (const float*)d_in[5];
    const float* w_fuse = (const float*)d_in[6];
    const float* b_fuse = (const float*)d_in[7];
    const float* w_proj = (const float*)d_in[8];
    float* out = (float*)d_out;

    const int GEMM_SMEM = 3 * 42496;  // 127488 B
    cudaFuncSetAttribute(bigsort_kernel, cudaFuncAttributeMaxDynamicSharedMemorySize, 65536);
    cudaFuncSetAttribute(mma_gemm<30,true>, cudaFuncAttributeMaxDynamicSharedMemorySize, GEMM_SMEM);

    void *p_xwork, *p_q, *p_cat, *p_qkv, *p_pre, *p_outp;
    void *p_gq1, *p_gk1, *p_gq2, *p_gk2, *p_vsc, *p_tq2, *p_tk2, *p_tv;
    void *p_o1, *p_ont, *p_part, *p_attn, *p_nq, *p_nk;
    cudaGetSymbolAddress(&p_xwork, g_xwork);
    cudaGetSymbolAddress(&p_q, g_q);
    cudaGetSymbolAddress(&p_cat, g_cat);
    cudaGetSymbolAddress(&p_qkv, g_qkv);
    cudaGetSymbolAddress(&p_pre, g_pre);
    cudaGetSymbolAddress(&p_outp, g_outp);
    cudaGetSymbolAddress(&p_gq1, g_gq1);
    cudaGetSymbolAddress(&p_gk1, g_gk1);
    cudaGetSymbolAddress(&p_gq2, g_gq2);
    cudaGetSymbolAddress(&p_gk2, g_gk2);
    cudaGetSymbolAddress(&p_vsc, g_vsc);
    cudaGetSymbolAddress(&p_tq2, g_tq2);
    cudaGetSymbolAddress(&p_tk2, g_tk2);
    cudaGetSymbolAddress(&p_tv, g_tv);
    cudaGetSymbolAddress(&p_o1, g_o1);
    cudaGetSymbolAddress(&p_ont, g_ont);
    cudaGetSymbolAddress(&p_part, g_part);
    cudaGetSymbolAddress(&p_attn, g_attn);
    cudaGetSymbolAddress(&p_nq, g_nq);
    cudaGetSymbolAddress(&p_nk, g_nk);

    const int NELT = Bv*Cch*HW;
    const int EB = (NELT + 255) / 256;

    // 1) channel sorts + copy of untouched channels
    copy_rest_kernel<<<(Bv*32*HW + 255)/256, 256>>>(x);
    sort_h_kernel<<<Bv*32*Wdim, 256>>>(x);
    sort_w_kernel<<<Bv*32*Hdim, 256>>>();

    // 2) q = w_qkv @ x   (M=320, K=64) — exact fp32 (feeds the v chain)
    gemm_kernel<<<dim3(HW/64, 3, Bv), 256>>>(
        w_qkv, (const float*)p_xwork, nullptr, (float*)p_q, 320, 64, HW);

    // 3) depthwise 3/5/7 -> cat (fp32)
    dwconv_kernel<<<dim3(144, 320, Bv), dim3(16, 16)>>>(w_dw3, w_dw5, w_dw7);

    // 4a) qkv rows 0..255 (q1,k1,q2,k2 — attention operands, sort-insensitive) — 3xTF32
    mma_gemm<30,true><<<dim3(4, HW/256, Bv), 256, GEMM_SMEM>>>(
        w_fuse, (const float*)p_cat, b_fuse, (float*)p_qkv, 320);

    // 4b) qkv rows 256..319 (v — feeds argsort, needs exact fp32)
    gemm64<<<dim3(HW/128, 1, Bv), 256>>>(
        w_fuse + (size_t)256*960, (const float*)p_cat, b_fuse + 256,
        (float*)p_qkv + (size_t)256*HW, 960,
        (long long)960*HW, (long long)320*HW);

    // 5) per-(b,c) argsort of v
    bigsort_kernel<<<128, 1024, 65536>>>();

    // 6) gather + non-box transposes
    gather_kernel<<<EB, 256>>>();
    nbt_kernel<<<EB, 256>>>((const float*)p_gq2, (float*)p_tq2);
    nbt_kernel<<<EB, 256>>>((const float*)p_gk2, (float*)p_tk2);
    nbt_kernel<<<EB, 256>>>((const float*)p_vsc, (float*)p_tv);

    // 7) L2 norms
    norm_kernel<<<512, 256>>>((const float*)p_gq1, (float*)p_nq);
    norm_kernel<<<512, 256>>>((const float*)p_gk1, (float*)p_nk);
    norm_kernel<<<512, 256>>>((const float*)p_tq2, (float*)p_nq + 512);
    norm_kernel<<<512, 256>>>((const float*)p_tk2, (float*)p_nk + 512);

    // 8) Q.K^T partials + softmax
    qk_partial_kernel<<<dim3(16, 8), 256>>>((const float*)p_gq1, (const float*)p_gk1,
                                            (float*)p_part);
    qk_partial_kernel<<<dim3(16, 8), 256>>>((const float*)p_tq2, (const float*)p_tk2,
                                            (float*)p_part + 8*16*4096);
    softmax_kernel<<<dim3(8, 2), 64>>>(temp);

    // 9) o = attn @ vv (both variants), un-transpose non-box
    o_gemm_kernel<<<dim3(144, 8), 256>>>((const float*)p_attn, (const float*)p_vsc,
                                         (float*)p_o1);
    o_gemm_kernel<<<dim3(144, 8), 256>>>((const float*)p_attn + 8*4096, (const float*)p_tv,
                                         (float*)p_ont);
    nbt_inv_kernel<<<EB, 256>>>();

    // 10) combine + scatter back, proj (fp32, M=64), final unsort
    combine_scatter_kernel<<<EB, 256>>>();
    gemm64<<<dim3(HW/128, 1, Bv), 256>>>(
        w_proj, (const float*)p_pre, nullptr, (float*)p_outp, 64,
        (long long)64*HW, (long long)64*HW);
    final_kernel<<<EB, 256>>>(out);
}

// round 11
// speedup vs baseline: 1.1479x; 1.0922x over previous
#include <cuda_runtime.h>
#include <math.h>
#include <cstdint>

#define Bv 2
#define Cch 64
#define Hdim 192
#define Wdim 192
#define HW 36864
#define SEG 65536
#define CHUNK 8192

typedef unsigned long long u64;

// ---------------- scratch (static device globals; no runtime allocation) ----------------
__device__ float g_xwork[Bv*Cch*HW];
__device__ int   g_invh[Bv*32*HW];
__device__ int   g_invw[Bv*32*HW];
__device__ float g_q[Bv*320*HW];
__device__ float g_cat[Bv*960*HW];
__device__ float g_qkv[Bv*320*HW];
__device__ u64   g_sort[(size_t)Bv*64*SEG];   // packed (sortable-key<<32 | idx)
__device__ float g_gq1[Bv*Cch*HW];
__device__ float g_gk1[Bv*Cch*HW];
__device__ float g_vsc[Bv*Cch*HW];
__device__ float g_tq2[Bv*Cch*HW];
__device__ float g_tk2[Bv*Cch*HW];
__device__ float g_tv [Bv*Cch*HW];
__device__ float g_o1 [Bv*Cch*HW];
__device__ float g_ont[Bv*Cch*HW];
__device__ float g_pre[Bv*Cch*HW];
__device__ float g_outp[Bv*Cch*HW];
__device__ float g_part[2*8*16*4096];
__device__ float g_attn[2*8*4096];
__device__ float g_nq[2*512];
__device__ float g_nk[2*512];

// ---------------- sortable-key helpers ----------------
__device__ __forceinline__ u64 pack_kv(float f, uint32_t idx) {
    uint32_t u = __float_as_uint(f);
    u = (u & 0x80000000u) ? ~u : (u | 0x80000000u);
    return ((u64)u << 32) | idx;
}
__device__ __forceinline__ float unpack_key(u64 kv) {
    uint32_t u = (uint32_t)(kv >> 32);
    return __uint_as_float((u & 0x80000000u) ? (u ^ 0x80000000u) : ~u);
}

// ================= exact fp32 SIMT GEMM, BM=128 (q GEMM) =================
__global__ void gemm_kernel(const float* __restrict__ A, const float* __restrict__ Bm,
                            const float* __restrict__ bias, float* __restrict__ Cm,
                            int M, int K, int N) {
    const int BM = 128, BN = 64, BK = 16;
    int bn = blockIdx.x * BN, bm = blockIdx.y * BM, bb = blockIdx.z;
    const float* Bp = Bm + (size_t)bb * K * N;
    float* Cp = Cm + (size_t)bb * M * N;
    __shared__ float As[BK][BM];
    __shared__ float Bs[BK][BN];
    int tid = threadIdx.x;
    int tx = tid & 15, ty = tid >> 4;
    int rm = ty * 8, rn = tx * 4;
    float acc[8][4];
    #pragma unroll
    for (int i = 0; i < 8; i++)
        #pragma unroll
        for (int j = 0; j < 4; j++) acc[i][j] = 0.f;

    for (int k0 = 0; k0 < K; k0 += BK) {
        {
            int lm = tid >> 1;
            int lk = (tid & 1) * 8;
            int gm = bm + lm;
            if (gm < M) {
                float4 v0 = *reinterpret_cast<const float4*>(&A[(size_t)gm*K + k0 + lk]);
                float4 v1 = *reinterpret_cast<const float4*>(&A[(size_t)gm*K + k0 + lk + 4]);
                As[lk+0][lm] = v0.x; As[lk+1][lm] = v0.y; As[lk+2][lm] = v0.z; As[lk+3][lm] = v0.w;
                As[lk+4][lm] = v1.x; As[lk+5][lm] = v1.y; As[lk+6][lm] = v1.z; As[lk+7][lm] = v1.w;
            } else {
                #pragma unroll
                for (int i = 0; i < 8; i++) As[lk+i][lm] = 0.f;
            }
        }
        {
            int lk = tid >> 4; int ln = (tid & 15) * 4;
            float4 v = *reinterpret_cast<const float4*>(&Bp[(size_t)(k0 + lk)*N + bn + ln]);
            *reinterpret_cast<float4*>(&Bs[lk][ln]) = v;
        }
        __syncthreads();
        #pragma unroll
        for (int k = 0; k < BK; k++) {
            float4 a0 = *reinterpret_cast<const float4*>(&As[k][rm]);
            float4 a1 = *reinterpret_cast<const float4*>(&As[k][rm + 4]);
            float4 bv4 = *reinterpret_cast<const float4*>(&Bs[k][rn]);
            float av[8] = {a0.x, a0.y, a0.z, a0.w, a1.x, a1.y, a1.z, a1.w};
            float bv[4] = {bv4.x, bv4.y, bv4.z, bv4.w};
            #pragma unroll
            for (int i = 0; i < 8; i++)
                #pragma unroll
                for (int j = 0; j < 4; j++) acc[i][j] += av[i] * bv[j];
        }
        __syncthreads();
    }
    #pragma unroll
    for (int i = 0; i < 8; i++) {
        int gm = bm + rm + i;
        if (gm < M) {
            float bvv = bias ? bias[gm] : 0.f;
            float4 o = make_float4(acc[i][0] + bvv, acc[i][1] + bvv, acc[i][2] + bvv, acc[i][3] + bvv);
            *reinterpret_cast<float4*>(&Cp[(size_t)gm*N + bn + rn]) = o;
        }
    }
}

// ================= exact fp32 SIMT GEMM, BM=64 (v rows + proj) =================
__global__ void __launch_bounds__(256) gemm64(const float* __restrict__ A,
                                              const float* __restrict__ Bg,
                                              const float* __restrict__ bias,
                                              float* __restrict__ Cg, int K,
                                              long long bstr, long long cstr) {
    __shared__ float As[16][68];
    __shared__ float Bs[16][132];
    int tid = threadIdx.x;
    int bn = blockIdx.x * 128;
    const float* Bz = Bg + (size_t)blockIdx.z * bstr;
    float* Cz = Cg + (size_t)blockIdx.z * cstr;
    int arow = tid >> 2, akq = (tid & 3) * 4;
    int rm = (tid >> 4) * 4, rn = (tid & 15) * 8;
    float acc[4][8];
    #pragma unroll
    for (int i = 0; i < 4; i++)
        #pragma unroll
        for (int j = 0; j < 8; j++) acc[i][j] = 0.f;

    for (int k0 = 0; k0 < K; k0 += 16) {
        float4 av = *reinterpret_cast<const float4*>(&A[(size_t)arow * K + k0 + akq]);
        As[akq+0][arow] = av.x; As[akq+1][arow] = av.y;
        As[akq+2][arow] = av.z; As[akq+3][arow] = av.w;
        #pragma unroll
        for (int j = 0; j < 2; j++) {
            int v = tid + j * 256;
            int kk = v >> 5, nq = (v & 31) * 4;
            *reinterpret_cast<float4*>(&Bs[kk][nq]) =
                *reinterpret_cast<const float4*>(&Bz[(size_t)(k0 + kk)*HW + bn + nq]);
        }
        __syncthreads();
        #pragma unroll
        for (int kk = 0; kk < 16; kk++) {
            float a0 = As[kk][rm], a1 = As[kk][rm+1], a2 = As[kk][rm+2], a3 = As[kk][rm+3];
            float b[8];
            *reinterpret_cast<float4*>(&b[0]) = *reinterpret_cast<const float4*>(&Bs[kk][rn]);
            *reinterpret_cast<float4*>(&b[4]) = *reinterpret_cast<const float4*>(&Bs[kk][rn+4]);
            #pragma unroll
            for (int j = 0; j < 8; j++) {
                acc[0][j] += a0 * b[j];
                acc[1][j] += a1 * b[j];
                acc[2][j] += a2 * b[j];
                acc[3][j] += a3 * b[j];
            }
        }
        __syncthreads();
    }
    #pragma unroll
    for (int i = 0; i < 4; i++) {
        float bv = bias ? bias[rm + i] : 0.f;
        float4 o0 = make_float4(acc[i][0]+bv, acc[i][1]+bv, acc[i][2]+bv, acc[i][3]+bv);
        float4 o1 = make_float4(acc[i][4]+bv, acc[i][5]+bv, acc[i][6]+bv, acc[i][7]+bv);
        *reinterpret_cast<float4*>(&Cz[(size_t)(rm+i)*HW + bn + rn])     = o0;
        *reinterpret_cast<float4*>(&Cz[(size_t)(rm+i)*HW + bn + rn + 4]) = o1;
    }
}

// ================= mma.sync 3xBF16 GEMM (attention-operand rows only) =================
#define CP16CG(dst, src) asm volatile("cp.async.cg.shared.global [%0], [%1], 16;" :: "r"(dst), "l"(src) : "memory")
#define CP16CA(dst, src) asm volatile("cp.async.ca.shared.global [%0], [%1], 16;" :: "r"(dst), "l"(src) : "memory")
#define CP_COMMIT() asm volatile("cp.async.commit_group;" ::: "memory")
#define CP_WAIT(n)  asm volatile("cp.async.wait_group %0;" :: "n"(n) : "memory")
#define MMA_BF16(d, a0, a1, a2, a3, b0, b1) \
    asm volatile("mma.sync.aligned.m16n8k16.row.col.f32.bf16.bf16.f32 " \
        "{%0,%1,%2,%3}, {%4,%5,%6,%7}, {%8,%9}, {%0,%1,%2,%3};" \
        : "+f"((d)[0]), "+f"((d)[1]), "+f"((d)[2]), "+f"((d)[3]) \
        : "r"(a0), "r"(a1), "r"(a2), "r"(a3), "r"(b0), "r"(b1))

__device__ __forceinline__ uint32_t smem_u32(const void* p) {
    uint32_t a;
    asm("{ .reg .u64 t; cvta.to.shared.u64 t, %1; cvt.u32.u64 %0, t; }" : "=r"(a) : "l"(p));
    return a;
}
// split two fp32 into packed bf16x2 hi + bf16x2 lo (residual). lower half = first elem.
__device__ __forceinline__ void bf16_split2(float f0, float f1, uint32_t& hi, uint32_t& lo) {
    uint32_t h;
    asm("cvt.rn.bf16x2.f32 %0, %1, %2;" : "=r"(h) : "f"(f1), "f"(f0));
    float h0 = __uint_as_float(h << 16);
    float h1 = __uint_as_float(h & 0xFFFF0000u);
    float l0 = f0 - h0;
    float l1 = f1 - h1;
    asm("cvt.rn.bf16x2.f32 %0, %1, %2;" : "=r"(lo) : "f"(l1), "f"(l0));
    hi = h;
}

// BM=64, BN=256, BK=32, 3-stage cp.async, 8 warps (2Mx4N), warp tile 32x64 via m16n8k16.
template<int NC, bool HASBIAS>
__global__ void __launch_bounds__(256, 1) mma_gemm(const float* __restrict__ A,
                                                   const float* __restrict__ Bg,
                                                   const float* __restrict__ bias,
                                                   float* __restrict__ Cg, int M) {
    constexpr int K = NC * 32;
    constexpr int N = HW;
    constexpr int STAGES = 3;
    constexpr int APITCH = 36;
    constexpr int BPITCH = 260;
    constexpr int AWORDS = 64 * APITCH;
    constexpr int STAGE_WORDS = AWORDS + 32 * BPITCH;

    extern __shared__ float sm[];
    int tid = threadIdx.x;
    int bm = blockIdx.x * 64;
    int bn = blockIdx.y * 256;
    const float* Az = A + (size_t)bm * K;
    const float* Bz = Bg + (size_t)blockIdx.z * K * N;
    float* Cz = Cg + (size_t)blockIdx.z * M * N;
    uint32_t sbase = smem_u32(sm);

    auto load_stage = [&](int chunk, int buf) {
        int k0 = chunk * 32;
        uint32_t abase = sbase + (uint32_t)buf * STAGE_WORDS * 4;
        #pragma unroll
        for (int j = 0; j < 2; j++) {
            int v = tid + j * 256;
            int m = v >> 3, kq = v & 7;
            uint32_t dst = abase + (uint32_t)(m * APITCH + kq * 4) * 4;
            const float* src = Az + (size_t)m * K + k0 + kq * 4;
            CP16CA(dst, src);
        }
        uint32_t bbase = abase + AWORDS * 4;
        #pragma unroll
        for (int j = 0; j < 8; j++) {
            int v = tid + j * 256;
            int k = v >> 6, nq = v & 63;
            uint32_t dst = bbase + (uint32_t)(k * BPITCH + nq * 4) * 4;
            const float* src = Bz + (size_t)(k0 + k) * N + bn + nq * 4;
            CP16CG(dst, src);
        }
    };

    int lane = tid & 31, g = lane >> 2, tg = lane & 3;
    int wid = tid >> 5;
    int wm = (wid & 1) * 32;
    int wn = (wid >> 1) * 64;

    float acc[2][8][4];
    #pragma unroll
    for (int mf = 0; mf < 2; mf++)
        #pragma unroll
        for (int nf = 0; nf < 8; nf++)
            #pragma unroll
            for (int q = 0; q < 4; q++) acc[mf][nf][q] = 0.f;

    #pragma unroll
    for (int s = 0; s < STAGES - 1; s++) {
        if (s < NC) load_stage(s, s);
        CP_COMMIT();
    }

    for (int c = 0; c < NC; c++) {
        CP_WAIT(STAGES - 2);
        __syncthreads();
        {
            int nxt = c + STAGES - 1;
            if (nxt < NC) load_stage(nxt, nxt % STAGES);
            CP_COMMIT();
        }
        const float* As = sm + (size_t)(c % STAGES) * STAGE_WORDS;
        const float* Bs = As + AWORDS;
        #pragma unroll
        for (int ks = 0; ks < 2; ks++) {
            int ka = ks * 16 + 2 * tg;
            uint32_t ah[2][4], al[2][4];
            #pragma unroll
            for (int mf = 0; mf < 2; mf++) {
                int m = wm + mf * 16 + g;
                float2 v0 = *reinterpret_cast<const float2*>(&As[m * APITCH + ka]);
                float2 v1 = *reinterpret_cast<const float2*>(&As[(m + 8) * APITCH + ka]);
                float2 v2 = *reinterpret_cast<const float2*>(&As[m * APITCH + ka + 8]);
                float2 v3 = *reinterpret_cast<const float2*>(&As[(m + 8) * APITCH + ka + 8]);
                bf16_split2(v0.x, v0.y, ah[mf][0], al[mf][0]);
                bf16_split2(v1.x, v1.y, ah[mf][1], al[mf][1]);
                bf16_split2(v2.x, v2.y, ah[mf][2], al[mf][2]);
                bf16_split2(v3.x, v3.y, ah[mf][3], al[mf][3]);
            }
            #pragma unroll
            for (int nf = 0; nf < 8; nf++) {
                int n = wn + nf * 8 + g;
                uint32_t b0h, b0l, b1h, b1l;
                bf16_split2(Bs[(ka)     * BPITCH + n], Bs[(ka + 1) * BPITCH + n], b0h, b0l);
                bf16_split2(Bs[(ka + 8) * BPITCH + n], Bs[(ka + 9) * BPITCH + n], b1h, b1l);
                #pragma unroll
                for (int mf = 0; mf < 2; mf++) {
                    MMA_BF16(acc[mf][nf], ah[mf][0], ah[mf][1], ah[mf][2], ah[mf][3], b0h, b1h);
                    MMA_BF16(acc[mf][nf], ah[mf][0], ah[mf][1], ah[mf][2], ah[mf][3], b0l, b1l);
                    MMA_BF16(acc[mf][nf], al[mf][0], al[mf][1], al[mf][2], al[mf][3], b0h, b1h);
                }
            }
        }
        __syncthreads();
    }

    #pragma unroll
    for (int mf = 0; mf < 2; mf++) {
        int row = bm + wm + mf * 16 + g;
        float bv0 = 0.f, bv1 = 0.f;
        if (HASBIAS) { bv0 = bias[row]; bv1 = bias[row + 8]; }
        #pragma unroll
        for (int nf = 0; nf < 8; nf++) {
            int col = bn + wn + nf * 8 + 2 * tg;
            float2 v0 = make_float2(acc[mf][nf][0] + bv0, acc[mf][nf][1] + bv0);
            float2 v1 = make_float2(acc[mf][nf][2] + bv1, acc[mf][nf][3] + bv1);
            *reinterpret_cast<float2*>(&Cz[(size_t)row * N + col]) = v0;
            *reinterpret_cast<float2*>(&Cz[(size_t)(row + 8) * N + col]) = v1;
        }
    }
}

// ---------------- small 192-element sorts (stable, packed u64, padded to 256) ----------------
__global__ void sort_h_kernel(const float* __restrict__ x) {
    int blk = blockIdx.x;
    int w = blk % Wdim; int c = (blk / Wdim) % 32; int b = blk / (Wdim * 32);
    __shared__ u64 key[256];
    int t = threadIdx.x;
    key[t] = (t < Hdim) ? pack_kv(x[((b*Cch + c)*Hdim + t)*Wdim + w], (uint32_t)t)
                        : ((0xFFFFFFFFull << 32) | (uint32_t)t);
    __syncthreads();
    for (int k = 2; k <= 256; k <<= 1) {
        for (int s = k >> 1; s > 0; s >>= 1) {
            int j = t ^ s;
            if (j > t) {
                u64 a = key[t], bb = key[j];
                if ((a > bb) == ((t & k) == 0)) { key[t] = bb; key[j] = a; }
            }
            __syncthreads();
        }
    }
    if (t < Hdim) {
        u64 v = key[t];
        g_xwork[((b*Cch + c)*Hdim + t)*Wdim + w] = unpack_key(v);
        g_invh[((b*32 + c)*Hdim + (int)(uint32_t)v)*Wdim + w] = t;
    }
}

__global__ void sort_w_kernel() {
    int blk = blockIdx.x;
    int h = blk % Hdim; int c = (blk / Hdim) % 32; int b = blk / (Hdim * 32);
    int base = ((b*Cch + c)*Hdim + h)*Wdim;
    __shared__ u64 key[256];
    int t = threadIdx.x;
    key[t] = (t < Wdim) ? pack_kv(g_xwork[base + t], (uint32_t)t)
                        : ((0xFFFFFFFFull << 32) | (uint32_t)t);
    __syncthreads();
    for (int k = 2; k <= 256; k <<= 1) {
        for (int s = k >> 1; s > 0; s >>= 1) {
            int j = t ^ s;
            if (j > t) {
                u64 a = key[t], bb = key[j];
                if ((a > bb) == ((t & k) == 0)) { key[t] = bb; key[j] = a; }
            }
            __syncthreads();
        }
    }
    if (t < Wdim) {
        u64 v = key[t];
        g_xwork[base + t] = unpack_key(v);
        g_invw[((b*32 + c)*Hdim + h)*Wdim + (int)(uint32_t)v] = t;
    }
}

__global__ void copy_rest_kernel(const float* __restrict__ x) {
    int gid = blockIdx.x * 256 + threadIdx.x;
    if (gid >= Bv*32*HW) return;
    int p = gid % HW; int c = (gid / HW) % 32; int b = gid / (32 * HW);
    int o = (b*Cch + 32 + c)*HW + p;
    g_xwork[o] = x[o];
}

// ---------------- fused depthwise 3x3 / 5x5 / 7x7 ----------------
__global__ void dwconv_kernel(const float* __restrict__ w3, const float* __restrict__ w5,
                              const float* __restrict__ w7) {
    int tile = blockIdx.x; int ch = blockIdx.y; int b = blockIdx.z;
    int ty0 = (tile / 12) * 16, tx0 = (tile % 12) * 16;
    __shared__ float s[22][24];
    __shared__ float wts[83];
    int tid = threadIdx.y * 16 + threadIdx.x;
    if (tid < 9)       wts[tid] = w3[ch*9 + tid];
    else if (tid < 34) wts[tid] = w5[ch*25 + tid - 9];
    else if (tid < 83) wts[tid] = w7[ch*49 + tid - 34];
    const float* base = g_q + (size_t)(b*320 + ch) * HW;
    for (int i = tid; i < 22*22; i += 256) {
        int sy = i / 22, sx = i % 22;
        int gy = ty0 + sy - 3, gx = tx0 + sx - 3;
        s[sy][sx] = (gy >= 0 && gy < Hdim && gx >= 0 && gx < Wdim) ? base[gy*Wdim + gx] : 0.f;
    }
    __syncthreads();
    int y = threadIdx.y, x = threadIdx.x;
    float a3 = 0.f, a5 = 0.f, a7 = 0.f;
    #pragma unroll
    for (int dy = 0; dy < 7; dy++)
        #pragma unroll
        for (int dx = 0; dx < 7; dx++) {
            float v = s[y + dy][x + dx];
            a7 += wts[34 + dy*7 + dx] * v;
            if (dy >= 1 && dy <= 5 && dx >= 1 && dx <= 5) a5 += wts[9 + (dy-1)*5 + (dx-1)] * v;
            if (dy >= 2 && dy <= 4 && dx >= 2 && dx <= 4) a3 += wts[(dy-2)*3 + (dx-2)] * v;
        }
    int gp = (ty0 + y)*Wdim + tx0 + x;
    size_t bo = (size_t)b * 960 * HW;
    g_cat[bo + (size_t)ch*HW + gp]        = a3;
    g_cat[bo + (size_t)(320 + ch)*HW + gp] = a5;
    g_cat[bo + (size_t)(640 + ch)*HW + gp] = a7;
}

// ---------------- big argsort of V (packed u64, branchless min/max) ----------------
__global__ void bigsort_kernel() {
    int seg = blockIdx.x;
    u64* K = g_sort + (size_t)seg * SEG;
    const float* src = g_qkv + ((size_t)(seg >> 6) * 320 + 256 + (seg & 63)) * HW;
    extern __shared__ u64 sk[];
    int t = threadIdx.x;

    for (int i = t; i < SEG; i += 1024)
        K[i] = (i < HW) ? pack_kv(src[i], (uint32_t)i)
                        : ((0xFFFFFFFFull << 32) | (uint32_t)i);
    __syncthreads();

    for (int cb = 0; cb < SEG; cb += CHUNK) {
        for (int i = t; i < CHUNK; i += 1024) sk[i] = K[cb + i];
        __syncthreads();
        for (int k = 2; k <= CHUNK; k <<= 1) {
            for (int s = k >> 1; s > 0; s >>= 1) {
                for (int p = t; p < CHUNK/2; p += 1024) {
                    int i = ((p & ~(s - 1)) << 1) | (p & (s - 1));
                    int j = i + s;
                    bool up = (((cb + i) & k) == 0);
                    u64 a = sk[i], b = sk[j];
                    u64 mn = a < b ? a : b;
                    u64 mx = a < b ? b : a;
                    sk[i] = up ? mn : mx;
                    sk[j] = up ? mx : mn;
                }
                __syncthreads();
            }
        }
        for (int i = t; i < CHUNK; i += 1024) K[cb + i] = sk[i];
        __syncthreads();
    }

    for (int k = CHUNK*2; k <= SEG; k <<= 1) {
        for (int s = k >> 1; s >= CHUNK; s >>= 1) {
            for (int p = t; p < SEG/2; p += 1024) {
                int i = ((p & ~(s - 1)) << 1) | (p & (s - 1));
                int j = i + s;
                bool up = ((i & k) == 0);
                u64 a = K[i], b = K[j];
                u64 mn = a < b ? a : b;
                u64 mx = a < b ? b : a;
                K[i] = up ? mn : mx;
                K[j] = up ? mx : mn;
            }
            __syncthreads();
        }
        for (int cb = 0; cb < SEG; cb += CHUNK) {
            for (int i = t; i < CHUNK; i += 1024) sk[i] = K[cb + i];
            __syncthreads();
            for (int s = CHUNK >> 1; s > 0; s >>= 1) {
                for (int p = t; p < CHUNK/2; p += 1024) {
                    int i = ((p & ~(s - 1)) << 1) | (p & (s - 1));
                    int j = i + s;
                    bool up = (((cb + i) & k) == 0);
                    u64 a = sk[i], b = sk[j];
                    u64 mn = a < b ? a : b;
                    u64 mx = a < b ? b : a;
                    sk[i] = up ? mn : mx;
                    sk[j] = up ? mx : mn;
                }
                __syncthreads();
            }
            for (int i = t; i < CHUNK; i += 1024) K[cb + i] = sk[i];
            __syncthreads();
        }
    }
}

// ---------------- gather q1/k1 + transposed q2/k2/v (nbt fused in) ----------------
__global__ void gather_kernel() {
    int gid = blockIdx.x * 256 + threadIdx.x;
    if (gid >= Bv*Cch*HW) return;
    int r = gid % HW; int c = (gid / HW) % Cch; int b = gid / (HW * Cch);
    u64 kv = g_sort[(size_t)(b*64 + c)*SEG + r];
    int src = (int)(uint32_t)kv;
    float v = unpack_key(kv);
    size_t qb = (size_t)b * 320 * HW;
    g_gq1[gid] = g_qkv[qb + (size_t)c*HW + src];
    g_gk1[gid] = g_qkv[qb + (size_t)(64 + c)*HW + src];
    float q2v = g_qkv[qb + (size_t)(128 + c)*HW + src];
    float k2v = g_qkv[qb + (size_t)(192 + c)*HW + src];
    g_vsc[gid] = v;
    int h = c >> 4, chi = c & 15;
    size_t ti = ((size_t)(b*4 + h)*64 + chi*4 + (r & 3))*9216 + (r >> 2);
    g_tq2[ti] = q2v;
    g_tk2[ti] = k2v;
    g_tv[ti]  = v;
}

__global__ void norm_kernel(const float* __restrict__ t, float* __restrict__ out) {
    int row = blockIdx.x;
    const float* p = t + (size_t)row * 9216;
    float ss = 0.f;
    for (int i = threadIdx.x; i < 9216; i += 256) { float v = p[i]; ss += v * v; }
    __shared__ float red[256];
    red[threadIdx.x] = ss;
    __syncthreads();
    for (int o = 128; o > 0; o >>= 1) {
        if (threadIdx.x < o) red[threadIdx.x] += red[threadIdx.x + o];
        __syncthreads();
    }
    if (threadIdx.x == 0) out[row] = fmaxf(sqrtf(red[0]), 1e-12f);
}

__global__ void qk_partial_kernel(const float* __restrict__ q, const float* __restrict__ k,
                                  float* __restrict__ part) {
    int kc = blockIdx.x, bh = blockIdx.y;
    const float* qb = q + (size_t)bh * 64 * 9216;
    const float* kb = k + (size_t)bh * 64 * 9216;
    __shared__ float qs[64][65];
    __shared__ float ks[64][65];
    int tid = threadIdx.x;
    int rm = (tid >> 4) * 4, rn = (tid & 15) * 4;
    float acc[4][4];
    #pragma unroll
    for (int i = 0; i < 4; i++)
        #pragma unroll
        for (int j = 0; j < 4; j++) acc[i][j] = 0.f;
    int nbase0 = kc * 576;
    for (int nt = 0; nt < 576; nt += 64) {
        #pragma unroll
        for (int l = 0; l < 16; l++) {
            int lin = l * 256 + tid;
            int d = lin >> 6, nn = lin & 63;
            qs[d][nn] = qb[(size_t)d*9216 + nbase0 + nt + nn];
            ks[d][nn] = kb[(size_t)d*9216 + nbase0 + nt + nn];
        }
        __syncthreads();
        #pragma unroll 8
        for (int nn = 0; nn < 64; nn++) {
            float a[4], bv[4];
            #pragma unroll
            for (int i = 0; i < 4; i++) a[i] = qs[rm + i][nn];
            #pragma unroll
            for (int j = 0; j < 4; j++) bv[j] = ks[rn + j][nn];
            #pragma unroll
            for (int i = 0; i < 4; i++)
                #pragma unroll
                for (int j = 0; j < 4; j++) acc[i][j] += a[i] * bv[j];
        }
        __syncthreads();
    }
    float* pp = part + ((size_t)bh * 16 + kc) * 4096;
    #pragma unroll
    for (int i = 0; i < 4; i++)
        #pragma unroll
        for (int j = 0; j < 4; j++) pp[(rm + i)*64 + rn + j] = acc[i][j];
}

__global__ void softmax_kernel(const float* __restrict__ temp) {
    int bh = blockIdx.x, var = blockIdx.y;
    int d = threadIdx.x;
    int h = bh & 3;
    const float* pp = g_part + ((size_t)(var*8 + bh) * 16) * 4096;
    float qn = g_nq[var*512 + bh*64 + d];
    float tmp = temp[h];
    float ev[64];
    float rs = 0.f;
    #pragma unroll
    for (int e = 0; e < 64; e++) {
        float s = 0.f;
        #pragma unroll
        for (int c2 = 0; c2 < 16; c2++) s += pp[(size_t)c2*4096 + d*64 + e];
        float a = s * tmp / (qn * g_nk[var*512 + bh*64 + e]);
        float x = expf(a);
        ev[e] = x;
        rs += x;
    }
    float inv = 1.f / (rs + 1.f);
    float* ap = g_attn + (size_t)(var*8 + bh) * 4096;
    #pragma unroll
    for (int e = 0; e < 64; e++) ap[d*64 + e] = ev[e] * inv;
}

__global__ void o_gemm_kernel(const float* __restrict__ attn, const float* __restrict__ v,
                              float* __restrict__ o) {
    int nt = blockIdx.x * 64, bh = blockIdx.y;
    const float* ap = attn + (size_t)bh * 4096;
    const float* vp = v + (size_t)bh * 64 * 9216;
    float* op = o + (size_t)bh * 64 * 9216;
    __shared__ float as_[64][65];
    __shared__ float vs_[64][65];
    int tid = threadIdx.x;
    #pragma unroll
    for (int l = 0; l < 16; l++) {
        int lin = l * 256 + tid;
        int r = lin >> 6, cc = lin & 63;
        as_[r][cc] = ap[lin];
        vs_[r][cc] = vp[(size_t)r*9216 + nt + cc];
    }
    __syncthreads();
    int rm = (tid >> 4) * 4, rn = (tid & 15) * 4;
    float acc[4][4];
    #pragma unroll
    for (int i = 0; i < 4; i++)
        #pragma unroll
        for (int j = 0; j < 4; j++) acc[i][j] = 0.f;
    #pragma unroll 8
    for (int e = 0; e < 64; e++) {
        float a[4], bv[4];
        #pragma unroll
        for (int i = 0; i < 4; i++) a[i] = as_[rm + i][e];
        #pragma unroll
        for (int j = 0; j < 4; j++) bv[j] = vs_[e][rn + j];
        #pragma unroll
        for (int i = 0; i < 4; i++)
            #pragma unroll
            for (int j = 0; j < 4; j++) acc[i][j] += a[i] * bv[j];
    }
    #pragma unroll
    for (int i = 0; i < 4; i++) {
        float4 ov = make_float4(acc[i][0], acc[i][1], acc[i][2], acc[i][3]);
        *reinterpret_cast<float4*>(&op[(size_t)(rm + i)*9216 + nt + rn]) = ov;
    }
}

// ---------------- combine out1*out2 (nbt_inv fused) + scatter back ----------------
__global__ void combine_scatter_kernel() {
    int gid = blockIdx.x * 256 + threadIdx.x;
    if (gid >= Bv*Cch*HW) return;
    int p = gid % HW; int c = (gid / HW) % 64; int b = gid / (HW * 64);
    u64 kv = g_sort[(size_t)(b*64 + c)*SEG + p];
    int dst = (int)(uint32_t)kv;
    int h = c >> 4, chi = c & 15;
    float o2v = g_ont[((size_t)(b*4 + h)*64 + chi*4 + (p & 3))*9216 + (p >> 2)];
    g_pre[(size_t)(b*64 + c)*HW + dst] = g_o1[gid] * o2v;
}

__global__ void final_kernel(float* __restrict__ out) {
    int gid = blockIdx.x * 256 + threadIdx.x;
    if (gid >= Bv*Cch*HW) return;
    int w = gid % Wdim; int h = (gid / Wdim) % Hdim;
    int c = (gid / HW) % 64; int b = gid / (HW * 64);
    if (c < 32) {
        int hh = g_invh[((b*32 + c)*Hdim + h)*Wdim + w];
        int ww = g_invw[((b*32 + c)*Hdim + hh)*Wdim + w];
        out[gid] = g_outp[(size_t)(b*64 + c)*HW + hh*Wdim + ww];
    } else {
        out[gid] = g_outp[gid];
    }
}

// ---------------- launcher ----------------
extern "C" void kernel_launch(void* const* d_in, const int* in_sizes, int n_in,
                              void* d_out, int out_size) {
    (void)in_sizes; (void)n_in; (void)out_size;
    const float* x      = (const float*)d_in[0];
    const float* temp   = (const float*)d_in[1];
    const float* w_qkv  = (const float*)d_in[2];
    const float* w_dw3  = (const float*)d_in[3];
    const float* w_dw5  = (const float*)d_in[4];
    const float* w_dw7  = (const float*)d_in[5];
    const float* w_fuse = (const float*)d_in[6];
    const float* b_fuse = (const float*)d_in[7];
    const float* w_proj = (const float*)d_in[8];
    float* out = (float*)d_out;

    const int GEMM_SMEM = 3 * 42496;  // 127488 B
    cudaFuncSetAttribute(bigsort_kernel, cudaFuncAttributeMaxDynamicSharedMemorySize, 65536);
    cudaFuncSetAttribute(mma_gemm<30,true>, cudaFuncAttributeMaxDynamicSharedMemorySize, GEMM_SMEM);

    void *p_xwork, *p_q, *p_cat, *p_qkv, *p_pre, *p_outp;
    void *p_gq1, *p_gk1, *p_vsc, *p_tq2, *p_tk2, *p_tv;
    void *p_o1, *p_ont, *p_part, *p_attn, *p_nq, *p_nk;
    cudaGetSymbolAddress(&p_xwork, g_xwork);
    cudaGetSymbolAddress(&p_q, g_q);
    cudaGetSymbolAddress(&p_cat, g_cat);
    cudaGetSymbolAddress(&p_qkv, g_qkv);
    cudaGetSymbolAddress(&p_pre, g_pre);
    cudaGetSymbolAddress(&p_outp, g_outp);
    cudaGetSymbolAddress(&p_gq1, g_gq1);
    cudaGetSymbolAddress(&p_gk1, g_gk1);
    cudaGetSymbolAddress(&p_vsc, g_vsc);
    cudaGetSymbolAddress(&p_tq2, g_tq2);
    cudaGetSymbolAddress(&p_tk2, g_tk2);
    cudaGetSymbolAddress(&p_tv, g_tv);
    cudaGetSymbolAddress(&p_o1, g_o1);
    cudaGetSymbolAddress(&p_ont, g_ont);
    cudaGetSymbolAddress(&p_part, g_part);
    cudaGetSymbolAddress(&p_attn, g_attn);
    cudaGetSymbolAddress(&p_nq, g_nq);
    cudaGetSymbolAddress(&p_nk, g_nk);

    const int NELT = Bv*Cch*HW;
    const int EB = (NELT + 255) / 256;

    // 1) channel sorts + copy of untouched channels
    copy_rest_kernel<<<(Bv*32*HW + 255)/256, 256>>>(x);
    sort_h_kernel<<<Bv*32*Wdim, 256>>>(x);
    sort_w_kernel<<<Bv*32*Hdim, 256>>>();

    // 2) q = w_qkv @ x   (M=320, K=64) — exact fp32 (feeds the v chain)
    gemm_kernel<<<dim3(HW/64, 3, Bv), 256>>>(
        w_qkv, (const float*)p_xwork, nullptr, (float*)p_q, 320, 64, HW);

    // 3) depthwise 3/5/7 -> cat (fp32)
    dwconv_kernel<<<dim3(144, 320, Bv), dim3(16, 16)>>>(w_dw3, w_dw5, w_dw7);

    // 4a) qkv rows 0..255 (attention operands, sort-insensitive) — 3xBF16 mma
    mma_gemm<30,true><<<dim3(4, HW/256, Bv), 256, GEMM_SMEM>>>(
        w_fuse, (const float*)p_cat, b_fuse, (float*)p_qkv, 320);

    // 4b) qkv rows 256..319 (v — feeds argsort, exact fp32)
    gemm64<<<dim3(HW/128, 1, Bv), 256>>>(
        w_fuse + (size_t)256*960, (const float*)p_cat, b_fuse + 256,
        (float*)p_qkv + (size_t)256*HW, 960,
        (long long)960*HW, (long long)320*HW);

    // 5) per-(b,c) argsort of v (packed u64)
    bigsort_kernel<<<128, 1024, 65536>>>();

    // 6) gather (writes q1/k1 flat + q2/k2/v transposed; nbt fused)
    gather_kernel<<<EB, 256>>>();

    // 7) L2 norms
    norm_kernel<<<512, 256>>>((const float*)p_gq1, (float*)p_nq);
    norm_kernel<<<512, 256>>>((const float*)p_gk1, (float*)p_nk);
    norm_kernel<<<512, 256>>>((const float*)p_tq2, (float*)p_nq + 512);
    norm_kernel<<<512, 256>>>((const float*)p_tk2, (float*)p_nk + 512);

    // 8) Q.K^T partials + softmax
    qk_partial_kernel<<<dim3(16, 8), 256>>>((const float*)p_gq1, (const float*)p_gk1,
                                            (float*)p_part);
    qk_partial_kernel<<<dim3(16, 8), 256>>>((const float*)p_tq2, (const float*)p_tk2,
                                            (float*)p_part + 8*16*4096);
    softmax_kernel<<<dim3(8, 2), 64>>>(temp);

    // 9) o = attn @ vv (both variants)
    o_gemm_kernel<<<dim3(144, 8), 256>>>((const float*)p_attn, (const float*)p_vsc,
                                         (float*)p_o1);
    o_gemm_kernel<<<dim3(144, 8), 256>>>((const float*)p_attn + 8*4096, (const float*)p_tv,
                                         (float*)p_ont);

    // 10) combine (nbt_inv fused) + scatter, proj (fp32), final unsort
    combine_scatter_kernel<<<EB, 256>>>();
    gemm64<<<dim3(HW/128, 1, Bv), 256>>>(
        w_proj, (const float*)p_pre, nullptr, (float*)p_outp, 64,
        (long long)64*HW, (long long)64*HW);
    final_kernel<<<EB, 256>>>(out);
}

// round 13
// speedup vs baseline: 1.2651x; 1.1021x over previous
#include <cuda_runtime.h>
#include <math.h>
#include <cstdint>

#define Bv 2
#define Cch 64
#define Hdim 192
#define Wdim 192
#define HW 36864
#define SEG 65536
#define CHUNK 8192

typedef unsigned long long u64;

// ---------------- scratch (static device globals; no runtime allocation) ----------------
__device__ float g_xwork[Bv*Cch*HW];
__device__ int   g_invh[Bv*32*HW];
__device__ int   g_invw[Bv*32*HW];
__device__ float g_q[Bv*320*HW];
__device__ float g_cat[Bv*960*HW];
__device__ float g_qkv[Bv*320*HW];
__device__ u64   g_sort[(size_t)Bv*64*SEG];   // packed (sortable-key<<32 | idx)
__device__ float g_gq1[Bv*Cch*HW];
__device__ float g_gk1[Bv*Cch*HW];
__device__ float g_vsc[Bv*Cch*HW];
__device__ float g_tq2[Bv*Cch*HW];
__device__ float g_tk2[Bv*Cch*HW];
__device__ float g_tv [Bv*Cch*HW];
__device__ float g_o1 [Bv*Cch*HW];
__device__ float g_ont[Bv*Cch*HW];
__device__ float g_pre[Bv*Cch*HW];
__device__ float g_outp[Bv*Cch*HW];
__device__ float g_part[2*8*16*4096];
__device__ float g_attn[2*8*4096];
__device__ float g_nq[2*512];
__device__ float g_nk[2*512];

// ---------------- sortable-key helpers ----------------
__device__ __forceinline__ u64 pack_kv(float f, uint32_t idx) {
    uint32_t u = __float_as_uint(f);
    u = (u & 0x80000000u) ? ~u : (u | 0x80000000u);
    return ((u64)u << 32) | idx;
}
__device__ __forceinline__ float unpack_key(u64 kv) {
    uint32_t u = (uint32_t)(kv >> 32);
    return __uint_as_float((u & 0x80000000u) ? (u ^ 0x80000000u) : ~u);
}
__device__ __forceinline__ void ce_reg(u64& a, u64& b, bool up) {
    u64 mn = a < b ? a : b;
    u64 mx = a < b ? b : a;
    a = up ? mn : mx;
    b = up ? mx : mn;
}

// ================= exact fp32 SIMT GEMM, BM=128 (q GEMM) =================
__global__ void gemm_kernel(const float* __restrict__ A, const float* __restrict__ Bm,
                            const float* __restrict__ bias, float* __restrict__ Cm,
                            int M, int K, int N) {
    const int BM = 128, BN = 64, BK = 16;
    int bn = blockIdx.x * BN, bm = blockIdx.y * BM, bb = blockIdx.z;
    const float* Bp = Bm + (size_t)bb * K * N;
    float* Cp = Cm + (size_t)bb * M * N;
    __shared__ float As[BK][BM];
    __shared__ float Bs[BK][BN];
    int tid = threadIdx.x;
    int tx = tid & 15, ty = tid >> 4;
    int rm = ty * 8, rn = tx * 4;
    float acc[8][4];
    #pragma unroll
    for (int i = 0; i < 8; i++)
        #pragma unroll
        for (int j = 0; j < 4; j++) acc[i][j] = 0.f;

    for (int k0 = 0; k0 < K; k0 += BK) {
        {
            int lm = tid >> 1;
            int lk = (tid & 1) * 8;
            int gm = bm + lm;
            if (gm < M) {
                float4 v0 = *reinterpret_cast<const float4*>(&A[(size_t)gm*K + k0 + lk]);
                float4 v1 = *reinterpret_cast<const float4*>(&A[(size_t)gm*K + k0 + lk + 4]);
                As[lk+0][lm] = v0.x; As[lk+1][lm] = v0.y; As[lk+2][lm] = v0.z; As[lk+3][lm] = v0.w;
                As[lk+4][lm] = v1.x; As[lk+5][lm] = v1.y; As[lk+6][lm] = v1.z; As[lk+7][lm] = v1.w;
            } else {
                #pragma unroll
                for (int i = 0; i < 8; i++) As[lk+i][lm] = 0.f;
            }
        }
        {
            int lk = tid >> 4; int ln = (tid & 15) * 4;
            float4 v = *reinterpret_cast<const float4*>(&Bp[(size_t)(k0 + lk)*N + bn + ln]);
            *reinterpret_cast<float4*>(&Bs[lk][ln]) = v;
        }
        __syncthreads();
        #pragma unroll
        for (int k = 0; k < BK; k++) {
            float4 a0 = *reinterpret_cast<const float4*>(&As[k][rm]);
            float4 a1 = *reinterpret_cast<const float4*>(&As[k][rm + 4]);
            float4 bv4 = *reinterpret_cast<const float4*>(&Bs[k][rn]);
            float av[8] = {a0.x, a0.y, a0.z, a0.w, a1.x, a1.y, a1.z, a1.w};
            float bv[4] = {bv4.x, bv4.y, bv4.z, bv4.w};
            #pragma unroll
            for (int i = 0; i < 8; i++)
                #pragma unroll
                for (int j = 0; j < 4; j++) acc[i][j] += av[i] * bv[j];
        }
        __syncthreads();
    }
    #pragma unroll
    for (int i = 0; i < 8; i++) {
        int gm = bm + rm + i;
        if (gm < M) {
            float bvv = bias ? bias[gm] : 0.f;
            float4 o = make_float4(acc[i][0] + bvv, acc[i][1] + bvv, acc[i][2] + bvv, acc[i][3] + bvv);
            *reinterpret_cast<float4*>(&Cp[(size_t)gm*N + bn + rn]) = o;
        }
    }
}

// ================= exact fp32 SIMT GEMM, BM=64 (v rows + proj) =================
__global__ void __launch_bounds__(256) gemm64(const float* __restrict__ A,
                                              const float* __restrict__ Bg,
                                              const float* __restrict__ bias,
                                              float* __restrict__ Cg, int K,
                                              long long bstr, long long cstr) {
    __shared__ float As[16][68];
    __shared__ float Bs[16][132];
    int tid = threadIdx.x;
    int bn = blockIdx.x * 128;
    const float* Bz = Bg + (size_t)blockIdx.z * bstr;
    float* Cz = Cg + (size_t)blockIdx.z * cstr;
    int arow = tid >> 2, akq = (tid & 3) * 4;
    int rm = (tid >> 4) * 4, rn = (tid & 15) * 8;
    float acc[4][8];
    #pragma unroll
    for (int i = 0; i < 4; i++)
        #pragma unroll
        for (int j = 0; j < 8; j++) acc[i][j] = 0.f;

    for (int k0 = 0; k0 < K; k0 += 16) {
        float4 av = *reinterpret_cast<const float4*>(&A[(size_t)arow * K + k0 + akq]);
        As[akq+0][arow] = av.x; As[akq+1][arow] = av.y;
        As[akq+2][arow] = av.z; As[akq+3][arow] = av.w;
        #pragma unroll
        for (int j = 0; j < 2; j++) {
            int v = tid + j * 256;
            int kk = v >> 5, nq = (v & 31) * 4;
            *reinterpret_cast<float4*>(&Bs[kk][nq]) =
                *reinterpret_cast<const float4*>(&Bz[(size_t)(k0 + kk)*HW + bn + nq]);
        }
        __syncthreads();
        #pragma unroll
        for (int kk = 0; kk < 16; kk++) {
            float a0 = As[kk][rm], a1 = As[kk][rm+1], a2 = As[kk][rm+2], a3 = As[kk][rm+3];
            float b[8];
            *reinterpret_cast<float4*>(&b[0]) = *reinterpret_cast<const float4*>(&Bs[kk][rn]);
            *reinterpret_cast<float4*>(&b[4]) = *reinterpret_cast<const float4*>(&Bs[kk][rn+4]);
            #pragma unroll
            for (int j = 0; j < 8; j++) {
                acc[0][j] += a0 * b[j];
                acc[1][j] += a1 * b[j];
                acc[2][j] += a2 * b[j];
                acc[3][j] += a3 * b[j];
            }
        }
        __syncthreads();
    }
    #pragma unroll
    for (int i = 0; i < 4; i++) {
        float bv = bias ? bias[rm + i] : 0.f;
        float4 o0 = make_float4(acc[i][0]+bv, acc[i][1]+bv, acc[i][2]+bv, acc[i][3]+bv);
        float4 o1 = make_float4(acc[i][4]+bv, acc[i][5]+bv, acc[i][6]+bv, acc[i][7]+bv);
        *reinterpret_cast<float4*>(&Cz[(size_t)(rm+i)*HW + bn + rn])     = o0;
        *reinterpret_cast<float4*>(&Cz[(size_t)(rm+i)*HW + bn + rn + 4]) = o1;
    }
}

// ================= mma.sync 3xBF16 GEMM (attention-operand rows only) =================
#define CP16CG(dst, src) asm volatile("cp.async.cg.shared.global [%0], [%1], 16;" :: "r"(dst), "l"(src) : "memory")
#define CP16CA(dst, src) asm volatile("cp.async.ca.shared.global [%0], [%1], 16;" :: "r"(dst), "l"(src) : "memory")
#define CP_COMMIT() asm volatile("cp.async.commit_group;" ::: "memory")
#define CP_WAIT(n)  asm volatile("cp.async.wait_group %0;" :: "n"(n) : "memory")
#define MMA_BF16(d, a0, a1, a2, a3, b0, b1) \
    asm volatile("mma.sync.aligned.m16n8k16.row.col.f32.bf16.bf16.f32 " \
        "{%0,%1,%2,%3}, {%4,%5,%6,%7}, {%8,%9}, {%0,%1,%2,%3};" \
        : "+f"((d)[0]), "+f"((d)[1]), "+f"((d)[2]), "+f"((d)[3]) \
        : "r"(a0), "r"(a1), "r"(a2), "r"(a3), "r"(b0), "r"(b1))

__device__ __forceinline__ uint32_t smem_u32(const void* p) {
    uint32_t a;
    asm("{ .reg .u64 t; cvta.to.shared.u64 t, %1; cvt.u32.u64 %0, t; }" : "=r"(a) : "l"(p));
    return a;
}
__device__ __forceinline__ void bf16_split2(float f0, float f1, uint32_t& hi, uint32_t& lo) {
    uint32_t h;
    asm("cvt.rn.bf16x2.f32 %0, %1, %2;" : "=r"(h) : "f"(f1), "f"(f0));
    float h0 = __uint_as_float(h << 16);
    float h1 = __uint_as_float(h & 0xFFFF0000u);
    float l0 = f0 - h0;
    float l1 = f1 - h1;
    asm("cvt.rn.bf16x2.f32 %0, %1, %2;" : "=r"(lo) : "f"(l1), "f"(l0));
    hi = h;
}

// BM=64, BN=256, BK=32, 3-stage cp.async, 8 warps (2Mx4N), warp tile 32x64 via m16n8k16.
template<int NC, bool HASBIAS>
__global__ void __launch_bounds__(256, 1) mma_gemm(const float* __restrict__ A,
                                                   const float* __restrict__ Bg,
                                                   const float* __restrict__ bias,
                                                   float* __restrict__ Cg, int M) {
    constexpr int K = NC * 32;
    constexpr int N = HW;
    constexpr int STAGES = 3;
    constexpr int APITCH = 36;
    constexpr int BPITCH = 260;
    constexpr int AWORDS = 64 * APITCH;
    constexpr int STAGE_WORDS = AWORDS + 32 * BPITCH;

    extern __shared__ float sm[];
    int tid = threadIdx.x;
    int bm = blockIdx.x * 64;
    int bn = blockIdx.y * 256;
    const float* Az = A + (size_t)bm * K;
    const float* Bz = Bg + (size_t)blockIdx.z * K * N;
    float* Cz = Cg + (size_t)blockIdx.z * M * N;
    uint32_t sbase = smem_u32(sm);

    auto load_stage = [&](int chunk, int buf) {
        int k0 = chunk * 32;
        uint32_t abase = sbase + (uint32_t)buf * STAGE_WORDS * 4;
        #pragma unroll
        for (int j = 0; j < 2; j++) {
            int v = tid + j * 256;
            int m = v >> 3, kq = v & 7;
            uint32_t dst = abase + (uint32_t)(m * APITCH + kq * 4) * 4;
            const float* src = Az + (size_t)m * K + k0 + kq * 4;
            CP16CA(dst, src);
        }
        uint32_t bbase = abase + AWORDS * 4;
        #pragma unroll
        for (int j = 0; j < 8; j++) {
            int v = tid + j * 256;
            int k = v >> 6, nq = v & 63;
            uint32_t dst = bbase + (uint32_t)(k * BPITCH + nq * 4) * 4;
            const float* src = Bz + (size_t)(k0 + k) * N + bn + nq * 4;
            CP16CG(dst, src);
        }
    };

    int lane = tid & 31, g = lane >> 2, tg = lane & 3;
    int wid = tid >> 5;
    int wm = (wid & 1) * 32;
    int wn = (wid >> 1) * 64;

    float acc[2][8][4];
    #pragma unroll
    for (int mf = 0; mf < 2; mf++)
        #pragma unroll
        for (int nf = 0; nf < 8; nf++)
            #pragma unroll
            for (int q = 0; q < 4; q++) acc[mf][nf][q] = 0.f;

    #pragma unroll
    for (int s = 0; s < STAGES - 1; s++) {
        if (s < NC) load_stage(s, s);
        CP_COMMIT();
    }

    for (int c = 0; c < NC; c++) {
        CP_WAIT(STAGES - 2);
        __syncthreads();
        {
            int nxt = c + STAGES - 1;
            if (nxt < NC) load_stage(nxt, nxt % STAGES);
            CP_COMMIT();
        }
        const float* As = sm + (size_t)(c % STAGES) * STAGE_WORDS;
        const float* Bs = As + AWORDS;
        #pragma unroll
        for (int ks = 0; ks < 2; ks++) {
            int ka = ks * 16 + 2 * tg;
            uint32_t ah[2][4], al[2][4];
            #pragma unroll
            for (int mf = 0; mf < 2; mf++) {
                int m = wm + mf * 16 + g;
                float2 v0 = *reinterpret_cast<const float2*>(&As[m * APITCH + ka]);
                float2 v1 = *reinterpret_cast<const float2*>(&As[(m + 8) * APITCH + ka]);
                float2 v2 = *reinterpret_cast<const float2*>(&As[m * APITCH + ka + 8]);
                float2 v3 = *reinterpret_cast<const float2*>(&As[(m + 8) * APITCH + ka + 8]);
                bf16_split2(v0.x, v0.y, ah[mf][0], al[mf][0]);
                bf16_split2(v1.x, v1.y, ah[mf][1], al[mf][1]);
                bf16_split2(v2.x, v2.y, ah[mf][2], al[mf][2]);
                bf16_split2(v3.x, v3.y, ah[mf][3], al[mf][3]);
            }
            #pragma unroll
            for (int nf = 0; nf < 8; nf++) {
                int n = wn + nf * 8 + g;
                uint32_t b0h, b0l, b1h, b1l;
                bf16_split2(Bs[(ka)     * BPITCH + n], Bs[(ka + 1) * BPITCH + n], b0h, b0l);
                bf16_split2(Bs[(ka + 8) * BPITCH + n], Bs[(ka + 9) * BPITCH + n], b1h, b1l);
                #pragma unroll
                for (int mf = 0; mf < 2; mf++) {
                    MMA_BF16(acc[mf][nf], ah[mf][0], ah[mf][1], ah[mf][2], ah[mf][3], b0h, b1h);
                    MMA_BF16(acc[mf][nf], ah[mf][0], ah[mf][1], ah[mf][2], ah[mf][3], b0l, b1l);
                    MMA_BF16(acc[mf][nf], al[mf][0], al[mf][1], al[mf][2], al[mf][3], b0h, b1h);
                }
            }
        }
        __syncthreads();
    }

    #pragma unroll
    for (int mf = 0; mf < 2; mf++) {
        int row = bm + wm + mf * 16 + g;
        float bv0 = 0.f, bv1 = 0.f;
        if (HASBIAS) { bv0 = bias[row]; bv1 = bias[row + 8]; }
        #pragma unroll
        for (int nf = 0; nf < 8; nf++) {
            int col = bn + wn + nf * 8 + 2 * tg;
            float2 v0 = make_float2(acc[mf][nf][0] + bv0, acc[mf][nf][1] + bv0);
            float2 v1 = make_float2(acc[mf][nf][2] + bv1, acc[mf][nf][3] + bv1);
            *reinterpret_cast<float2*>(&Cz[(size_t)row * N + col]) = v0;
            *reinterpret_cast<float2*>(&Cz[(size_t)(row + 8) * N + col]) = v1;
        }
    }
}

// ---------------- small 192-element sorts (stable, packed u64, padded to 256) ----------------
__global__ void sort_h_kernel(const float* __restrict__ x) {
    int blk = blockIdx.x;
    int w = blk % Wdim; int c = (blk / Wdim) % 32; int b = blk / (Wdim * 32);
    __shared__ u64 key[256];
    int t = threadIdx.x;
    key[t] = (t < Hdim) ? pack_kv(x[((b*Cch + c)*Hdim + t)*Wdim + w], (uint32_t)t)
                        : ((0xFFFFFFFFull << 32) | (uint32_t)t);
    __syncthreads();
    for (int k = 2; k <= 256; k <<= 1) {
        for (int s = k >> 1; s > 0; s >>= 1) {
            int j = t ^ s;
            if (j > t) {
                u64 a = key[t], bb = key[j];
                if ((a > bb) == ((t & k) == 0)) { key[t] = bb; key[j] = a; }
            }
            __syncthreads();
        }
    }
    if (t < Hdim) {
        u64 v = key[t];
        g_xwork[((b*Cch + c)*Hdim + t)*Wdim + w] = unpack_key(v);
        g_invh[((b*32 + c)*Hdim + (int)(uint32_t)v)*Wdim + w] = t;
    }
}

__global__ void sort_w_kernel() {
    int blk = blockIdx.x;
    int h = blk % Hdim; int c = (blk / Hdim) % 32; int b = blk / (Hdim * 32);
    int base = ((b*Cch + c)*Hdim + h)*Wdim;
    __shared__ u64 key[256];
    int t = threadIdx.x;
    key[t] = (t < Wdim) ? pack_kv(g_xwork[base + t], (uint32_t)t)
                        : ((0xFFFFFFFFull << 32) | (uint32_t)t);
    __syncthreads();
    for (int k = 2; k <= 256; k <<= 1) {
        for (int s = k >> 1; s > 0; s >>= 1) {
            int j = t ^ s;
            if (j > t) {
                u64 a = key[t], bb = key[j];
                if ((a > bb) == ((t & k) == 0)) { key[t] = bb; key[j] = a; }
            }
            __syncthreads();
        }
    }
    if (t < Wdim) {
        u64 v = key[t];
        g_xwork[base + t] = unpack_key(v);
        g_invw[((b*32 + c)*Hdim + h)*Wdim + (int)(uint32_t)v] = t;
    }
}

__global__ void copy_rest_kernel(const float* __restrict__ x) {
    int gid = blockIdx.x * 256 + threadIdx.x;
    if (gid >= Bv*32*HW) return;
    int p = gid % HW; int c = (gid / HW) % 32; int b = gid / (32 * HW);
    int o = (b*Cch + 32 + c)*HW + p;
    g_xwork[o] = x[o];
}

// ---------------- fused depthwise 3x3 / 5x5 / 7x7 ----------------
__global__ void dwconv_kernel(const float* __restrict__ w3, const float* __restrict__ w5,
                              const float* __restrict__ w7) {
    int tile = blockIdx.x; int ch = blockIdx.y; int b = blockIdx.z;
    int ty0 = (tile / 12) * 16, tx0 = (tile % 12) * 16;
    __shared__ float s[22][24];
    __shared__ float wts[83];
    int tid = threadIdx.y * 16 + threadIdx.x;
    if (tid < 9)       wts[tid] = w3[ch*9 + tid];
    else if (tid < 34) wts[tid] = w5[ch*25 + tid - 9];
    else if (tid < 83) wts[tid] = w7[ch*49 + tid - 34];
    const float* base = g_q + (size_t)(b*320 + ch) * HW;
    for (int i = tid; i < 22*22; i += 256) {
        int sy = i / 22, sx = i % 22;
        int gy = ty0 + sy - 3, gx = tx0 + sx - 3;
        s[sy][sx] = (gy >= 0 && gy < Hdim && gx >= 0 && gx < Wdim) ? base[gy*Wdim + gx] : 0.f;
    }
    __syncthreads();
    int y = threadIdx.y, x = threadIdx.x;
    float a3 = 0.f, a5 = 0.f, a7 = 0.f;
    #pragma unroll
    for (int dy = 0; dy < 7; dy++)
        #pragma unroll
        for (int dx = 0; dx < 7; dx++) {
            float v = s[y + dy][x + dx];
            a7 += wts[34 + dy*7 + dx] * v;
            if (dy >= 1 && dy <= 5 && dx >= 1 && dx <= 5) a5 += wts[9 + (dy-1)*5 + (dx-1)] * v;
            if (dy >= 2 && dy <= 4 && dx >= 2 && dx <= 4) a3 += wts[(dy-2)*3 + (dx-2)] * v;
        }
    int gp = (ty0 + y)*Wdim + tx0 + x;
    size_t bo = (size_t)b * 960 * HW;
    g_cat[bo + (size_t)ch*HW + gp]        = a3;
    g_cat[bo + (size_t)(320 + ch)*HW + gp] = a5;
    g_cat[bo + (size_t)(640 + ch)*HW + gp] = a7;
}

// ---------------- big argsort of V (packed u64, register-batched bitonic) ----------------
__global__ void __launch_bounds__(512) bigsort_kernel() {
    int seg = blockIdx.x;
    u64* K = g_sort + (size_t)seg * SEG;
    const float* src = g_qkv + ((size_t)(seg >> 6) * 320 + 256 + (seg & 63)) * HW;
    extern __shared__ u64 sk[];
    int t = threadIdx.x;

    for (int i = t; i < SEG; i += 512)
        K[i] = (i < HW) ? pack_kv(src[i], (uint32_t)i)
                        : ((0xFFFFFFFFull << 32) | (uint32_t)i);
    __syncthreads();

    // phase 1: fully sort each 8192-chunk in smem (stages 2..CHUNK)
    for (int cb = 0; cb < SEG; cb += CHUNK) {
        for (int i = t; i < CHUNK; i += 512) sk[i] = K[cb + i];
        __syncthreads();
        // stages k=2,4,8 fully in registers (8 contiguous elems per group)
        for (int gr = t; gr < CHUNK/8; gr += 512) {
            int base = gr * 8;
            u64 r[8];
            #pragma unroll
            for (int j = 0; j < 8; j++) r[j] = sk[base + j];
            // k=2 (s=1)
            ce_reg(r[0], r[1], ((base + 0) & 2) == 0);
            ce_reg(r[2], r[3], ((base + 2) & 2) == 0);
            ce_reg(r[4], r[5], ((base + 4) & 2) == 0);
            ce_reg(r[6], r[7], ((base + 6) & 2) == 0);
            // k=4 (s=2,1)
            {
                bool u0 = ((base + 0) & 4) == 0, u1 = ((base + 4) & 4) == 0;
                ce_reg(r[0], r[2], u0); ce_reg(r[1], r[3], u0);
                ce_reg(r[4], r[6], u1); ce_reg(r[5], r[7], u1);
                ce_reg(r[0], r[1], u0); ce_reg(r[2], r[3], u0);
                ce_reg(r[4], r[5], u1); ce_reg(r[6], r[7], u1);
            }
            // k=8 (s=4,2,1), direction constant per group
            {
                bool u = (base & 8) == 0;
                ce_reg(r[0], r[4], u); ce_reg(r[1], r[5], u); ce_reg(r[2], r[6], u); ce_reg(r[3], r[7], u);
                ce_reg(r[0], r[2], u); ce_reg(r[1], r[3], u); ce_reg(r[4], r[6], u); ce_reg(r[5], r[7], u);
                ce_reg(r[0], r[1], u); ce_reg(r[2], r[3], u); ce_reg(r[4], r[5], u); ce_reg(r[6], r[7], u);
            }
            #pragma unroll
            for (int j = 0; j < 8; j++) sk[base + j] = r[j];
        }
        __syncthreads();
        for (int k = 16; k <= CHUNK; k <<= 1) {
            for (int s = k >> 1; s >= 8; s >>= 1) {
                for (int p = t; p < CHUNK/2; p += 512) {
                    int i = ((p & ~(s - 1)) << 1) | (p & (s - 1));
                    int j = i + s;
                    bool up = (((cb + i) & k) == 0);
                    u64 a = sk[i], b = sk[j];
                    u64 mn = a < b ? a : b;
                    u64 mx = a < b ? b : a;
                    sk[i] = up ? mn : mx;
                    sk[j] = up ? mx : mn;
                }
                __syncthreads();
            }
            // s=4,2,1 in registers (direction constant per 8-group since k>=16)
            for (int gr = t; gr < CHUNK/8; gr += 512) {
                int base = gr * 8;
                bool u = (((cb + base) & k) == 0);
                u64 r[8];
                #pragma unroll
                for (int j = 0; j < 8; j++) r[j] = sk[base + j];
                ce_reg(r[0], r[4], u); ce_reg(r[1], r[5], u); ce_reg(r[2], r[6], u); ce_reg(r[3], r[7], u);
                ce_reg(r[0], r[2], u); ce_reg(r[1], r[3], u); ce_reg(r[4], r[6], u); ce_reg(r[5], r[7], u);
                ce_reg(r[0], r[1], u); ce_reg(r[2], r[3], u); ce_reg(r[4], r[5], u); ce_reg(r[6], r[7], u);
                #pragma unroll
                for (int j = 0; j < 8; j++) sk[base + j] = r[j];
            }
            __syncthreads();
        }
        for (int i = t; i < CHUNK; i += 512) K[cb + i] = sk[i];
        __syncthreads();
    }

    // phase 2: global stages k = 16384, 32768, 65536
    for (int k = CHUNK*2; k <= SEG; k <<= 1) {
        for (int s = k >> 1; s >= CHUNK; s >>= 1) {
            for (int p = t; p < SEG/2; p += 512) {
                int i = ((p & ~(s - 1)) << 1) | (p & (s - 1));
                int j = i + s;
                bool up = ((i & k) == 0);
                u64 a = K[i], b = K[j];
                u64 mn = a < b ? a : b;
                u64 mx = a < b ? b : a;
                K[i] = up ? mn : mx;
                K[j] = up ? mx : mn;
            }
            __syncthreads();
        }
        for (int cb = 0; cb < SEG; cb += CHUNK) {
            for (int i = t; i < CHUNK; i += 512) sk[i] = K[cb + i];
            __syncthreads();
            for (int s = CHUNK >> 1; s >= 8; s >>= 1) {
                for (int p = t; p < CHUNK/2; p += 512) {
                    int i = ((p & ~(s - 1)) << 1) | (p & (s - 1));
                    int j = i + s;
                    bool up = (((cb + i) & k) == 0);
                    u64 a = sk[i], b = sk[j];
                    u64 mn = a < b ? a : b;
                    u64 mx = a < b ? b : a;
                    sk[i] = up ? mn : mx;
                    sk[j] = up ? mx : mn;
                }
                __syncthreads();
            }
            for (int gr = t; gr < CHUNK/8; gr += 512) {
                int base = gr * 8;
                bool u = (((cb + base) & k) == 0);
                u64 r[8];
                #pragma unroll
                for (int j = 0; j < 8; j++) r[j] = sk[base + j];
                ce_reg(r[0], r[4], u); ce_reg(r[1], r[5], u); ce_reg(r[2], r[6], u); ce_reg(r[3], r[7], u);
                ce_reg(r[0], r[2], u); ce_reg(r[1], r[3], u); ce_reg(r[4], r[6], u); ce_reg(r[5], r[7], u);
                ce_reg(r[0], r[1], u); ce_reg(r[2], r[3], u); ce_reg(r[4], r[5], u); ce_reg(r[6], r[7], u);
                #pragma unroll
                for (int j = 0; j < 8; j++) sk[base + j] = r[j];
            }
            __syncthreads();
            for (int i = t; i < CHUNK; i += 512) K[cb + i] = sk[i];
            __syncthreads();
        }
    }
}

// ---------------- gather q1/k1 + transposed q2/k2/v (nbt fused in) ----------------
__global__ void gather_kernel() {
    int gid = blockIdx.x * 256 + threadIdx.x;
    if (gid >= Bv*Cch*HW) return;
    int r = gid % HW; int c = (gid / HW) % Cch; int b = gid / (HW * Cch);
    u64 kv = g_sort[(size_t)(b*64 + c)*SEG + r];
    int src = (int)(uint32_t)kv;
    float v = unpack_key(kv);
    size_t qb = (size_t)b * 320 * HW;
    g_gq1[gid] = g_qkv[qb + (size_t)c*HW + src];
    g_gk1[gid] = g_qkv[qb + (size_t)(64 + c)*HW + src];
    float q2v = g_qkv[qb + (size_t)(128 + c)*HW + src];
    float k2v = g_qkv[qb + (size_t)(192 + c)*HW + src];
    g_vsc[gid] = v;
    int h = c >> 4, chi = c & 15;
    size_t ti = ((size_t)(b*4 + h)*64 + chi*4 + (r & 3))*9216 + (r >> 2);
    g_tq2[ti] = q2v;
    g_tk2[ti] = k2v;
    g_tv[ti]  = v;
}

__global__ void norm_kernel(const float* __restrict__ t, float* __restrict__ out) {
    int row = blockIdx.x;
    const float* p = t + (size_t)row * 9216;
    float ss = 0.f;
    for (int i = threadIdx.x; i < 9216; i += 256) { float v = p[i]; ss += v * v; }
    __shared__ float red[256];
    red[threadIdx.x] = ss;
    __syncthreads();
    for (int o = 128; o > 0; o >>= 1) {
        if (threadIdx.x < o) red[threadIdx.x] += red[threadIdx.x + o];
        __syncthreads();
    }
    if (threadIdx.x == 0) out[row] = fmaxf(sqrtf(red[0]), 1e-12f);
}

__global__ void qk_partial_kernel(const float* __restrict__ q, const float* __restrict__ k,
                                  float* __restrict__ part) {
    int kc = blockIdx.x, bh = blockIdx.y;
    const float* qb = q + (size_t)bh * 64 * 9216;
    const float* kb = k + (size_t)bh * 64 * 9216;
    __shared__ float qs[64][65];
    __shared__ float ks[64][65];
    int tid = threadIdx.x;
    int rm = (tid >> 4) * 4, rn = (tid & 15) * 4;
    float acc[4][4];
    #pragma unroll
    for (int i = 0; i < 4; i++)
        #pragma unroll
        for (int j = 0; j < 4; j++) acc[i][j] = 0.f;
    int nbase0 = kc * 576;
    for (int nt = 0; nt < 576; nt += 64) {
        #pragma unroll
        for (int l = 0; l < 16; l++) {
            int lin = l * 256 + tid;
            int d = lin >> 6, nn = lin & 63;
            qs[d][nn] = qb[(size_t)d*9216 + nbase0 + nt + nn];
            ks[d][nn] = kb[(size_t)d*9216 + nbase0 + nt + nn];
        }
        __syncthreads();
        #pragma unroll 8
        for (int nn = 0; nn < 64; nn++) {
            float a[4], bv[4];
            #pragma unroll
            for (int i = 0; i < 4; i++) a[i] = qs[rm + i][nn];
            #pragma unroll
            for (int j = 0; j < 4; j++) bv[j] = ks[rn + j][nn];
            #pragma unroll
            for (int i = 0; i < 4; i++)
                #pragma unroll
                for (int j = 0; j < 4; j++) acc[i][j] += a[i] * bv[j];
        }
        __syncthreads();
    }
    float* pp = part + ((size_t)bh * 16 + kc) * 4096;
    #pragma unroll
    for (int i = 0; i < 4; i++)
        #pragma unroll
        for (int j = 0; j < 4; j++) pp[(rm + i)*64 + rn + j] = acc[i][j];
}

__global__ void softmax_kernel(const float* __restrict__ temp) {
    int bh = blockIdx.x, var = blockIdx.y;
    int d = threadIdx.x;
    int h = bh & 3;
    const float* pp = g_part + ((size_t)(var*8 + bh) * 16) * 4096;
    float qn = g_nq[var*512 + bh*64 + d];
    float tmp = temp[h];
    float ev[64];
    float rs = 0.f;
    #pragma unroll
    for (int e = 0; e < 64; e++) {
        float s = 0.f;
        #pragma unroll
        for (int c2 = 0; c2 < 16; c2++) s += pp[(size_t)c2*4096 + d*64 + e];
        float a = s * tmp / (qn * g_nk[var*512 + bh*64 + e]);
        float x = expf(a);
        ev[e] = x;
        rs += x;
    }
    float inv = 1.f / (rs + 1.f);
    float* ap = g_attn + (size_t)(var*8 + bh) * 4096;
    #pragma unroll
    for (int e = 0; e < 64; e++) ap[d*64 + e] = ev[e] * inv;
}

__global__ void o_gemm_kernel(const float* __restrict__ attn, const float* __restrict__ v,
                              float* __restrict__ o) {
    int nt = blockIdx.x * 64, bh = blockIdx.y;
    const float* ap = attn + (size_t)bh * 4096;
    const float* vp = v + (size_t)bh * 64 * 9216;
    float* op = o + (size_t)bh * 64 * 9216;
    __shared__ float as_[64][65];
    __shared__ float vs_[64][65];
    int tid = threadIdx.x;
    #pragma unroll
    for (int l = 0; l < 16; l++) {
        int lin = l * 256 + tid;
        int r = lin >> 6, cc = lin & 63;
        as_[r][cc] = ap[lin];
        vs_[r][cc] = vp[(size_t)r*9216 + nt + cc];
    }
    __syncthreads();
    int rm = (tid >> 4) * 4, rn = (tid & 15) * 4;
    float acc[4][4];
    #pragma unroll
    for (int i = 0; i < 4; i++)
        #pragma unroll
        for (int j = 0; j < 4; j++) acc[i][j] = 0.f;
    #pragma unroll 8
    for (int e = 0; e < 64; e++) {
        float a[4], bv[4];
        #pragma unroll
        for (int i = 0; i < 4; i++) a[i] = as_[rm + i][e];
        #pragma unroll
        for (int j = 0; j < 4; j++) bv[j] = vs_[e][rn + j];
        #pragma unroll
        for (int i = 0; i < 4; i++)
            #pragma unroll
            for (int j = 0; j < 4; j++) acc[i][j] += a[i] * bv[j];
    }
    #pragma unroll
    for (int i = 0; i < 4; i++) {
        float4 ov = make_float4(acc[i][0], acc[i][1], acc[i][2], acc[i][3]);
        *reinterpret_cast<float4*>(&op[(size_t)(rm + i)*9216 + nt + rn]) = ov;
    }
}

// ---------------- combine out1*out2 (nbt_inv fused) + scatter back ----------------
__global__ void combine_scatter_kernel() {
    int gid = blockIdx.x * 256 + threadIdx.x;
    if (gid >= Bv*Cch*HW) return;
    int p = gid % HW; int c = (gid / HW) % 64; int b = gid / (HW * 64);
    u64 kv = g_sort[(size_t)(b*64 + c)*SEG + p];
    int dst = (int)(uint32_t)kv;
    int h = c >> 4, chi = c & 15;
    float o2v = g_ont[((size_t)(b*4 + h)*64 + chi*4 + (p & 3))*9216 + (p >> 2)];
    g_pre[(size_t)(b*64 + c)*HW + dst] = g_o1[gid] * o2v;
}

__global__ void final_kernel(float* __restrict__ out) {
    int gid = blockIdx.x * 256 + threadIdx.x;
    if (gid >= Bv*Cch*HW) return;
    int w = gid % Wdim; int h = (gid / Wdim) % Hdim;
    int c = (gid / HW) % 64; int b = gid / (HW * 64);
    if (c < 32) {
        int hh = g_invh[((b*32 + c)*Hdim + h)*Wdim + w];
        int ww = g_invw[((b*32 + c)*Hdim + hh)*Wdim + w];
        out[gid] = g_outp[(size_t)(b*64 + c)*HW + hh*Wdim + ww];
    } else {
        out[gid] = g_outp[gid];
    }
}

// ---------------- launcher ----------------
extern "C" void kernel_launch(void* const* d_in, const int* in_sizes, int n_in,
                              void* d_out, int out_size) {
    (void)in_sizes; (void)n_in; (void)out_size;
    const float* x      = (const float*)d_in[0];
    const float* temp   = (const float*)d_in[1];
    const float* w_qkv  = (const float*)d_in[2];
    const float* w_dw3  = (const float*)d_in[3];
    const float* w_dw5  = (const float*)d_in[4];
    const float* w_dw7  = (const float*)d_in[5];
    const float* w_fuse = (const float*)d_in[6];
    const float* b_fuse = (const float*)d_in[7];
    const float* w_proj = (const float*)d_in[8];
    float* out = (float*)d_out;

    // one-time side stream + events (created on first, uncaptured, call)
    static cudaStream_t s2 = nullptr;
    static cudaEvent_t evV = nullptr, evS = nullptr;
    if (!s2) {
        cudaStreamCreateWithFlags(&s2, cudaStreamNonBlocking);
        cudaEventCreateWithFlags(&evV, cudaEventDisableTiming);
        cudaEventCreateWithFlags(&evS, cudaEventDisableTiming);
    }

    const int GEMM_SMEM = 3 * 42496;  // 127488 B
    cudaFuncSetAttribute(bigsort_kernel, cudaFuncAttributeMaxDynamicSharedMemorySize, 65536);
    cudaFuncSetAttribute(mma_gemm<30,true>, cudaFuncAttributeMaxDynamicSharedMemorySize, GEMM_SMEM);

    void *p_xwork, *p_q, *p_cat, *p_qkv, *p_pre, *p_outp;
    void *p_gq1, *p_gk1, *p_vsc, *p_tq2, *p_tk2, *p_tv;
    void *p_o1, *p_ont, *p_part, *p_attn, *p_nq, *p_nk;
    cudaGetSymbolAddress(&p_xwork, g_xwork);
    cudaGetSymbolAddress(&p_q, g_q);
    cudaGetSymbolAddress(&p_cat, g_cat);
    cudaGetSymbolAddress(&p_qkv, g_qkv);
    cudaGetSymbolAddress(&p_pre, g_pre);
    cudaGetSymbolAddress(&p_outp, g_outp);
    cudaGetSymbolAddress(&p_gq1, g_gq1);
    cudaGetSymbolAddress(&p_gk1, g_gk1);
    cudaGetSymbolAddress(&p_vsc, g_vsc);
    cudaGetSymbolAddress(&p_tq2, g_tq2);
    cudaGetSymbolAddress(&p_tk2, g_tk2);
    cudaGetSymbolAddress(&p_tv, g_tv);
    cudaGetSymbolAddress(&p_o1, g_o1);
    cudaGetSymbolAddress(&p_ont, g_ont);
    cudaGetSymbolAddress(&p_part, g_part);
    cudaGetSymbolAddress(&p_attn, g_attn);
    cudaGetSymbolAddress(&p_nq, g_nq);
    cudaGetSymbolAddress(&p_nk, g_nk);

    const int NELT = Bv*Cch*HW;
    const int EB = (NELT + 255) / 256;

    // 1) channel sorts + copy of untouched channels
    copy_rest_kernel<<<(Bv*32*HW + 255)/256, 256>>>(x);
    sort_h_kernel<<<Bv*32*Wdim, 256>>>(x);
    sort_w_kernel<<<Bv*32*Hdim, 256>>>();

    // 2) q = w_qkv @ x   (M=320, K=64) — exact fp32 (feeds the v chain)
    gemm_kernel<<<dim3(HW/64, 3, Bv), 256>>>(
        w_qkv, (const float*)p_xwork, nullptr, (float*)p_q, 320, 64, HW);

    // 3) depthwise 3/5/7 -> cat (fp32)
    dwconv_kernel<<<dim3(144, 320, Bv), dim3(16, 16)>>>(w_dw3, w_dw5, w_dw7);

    // 4b FIRST) qkv rows 256..319 (v — feeds argsort, exact fp32)
    gemm64<<<dim3(HW/128, 1, Bv), 256>>>(
        w_fuse + (size_t)256*960, (const float*)p_cat, b_fuse + 256,
        (float*)p_qkv + (size_t)256*HW, 960,
        (long long)960*HW, (long long)320*HW);
    cudaEventRecord(evV, 0);

    // 5) bigsort on side stream — overlaps with the big mma below
    cudaStreamWaitEvent(s2, evV, 0);
    bigsort_kernel<<<128, 512, 65536, s2>>>();
    cudaEventRecord(evS, s2);

    // 4a) qkv rows 0..255 (attention operands, sort-insensitive) — 3xBF16 mma (main stream)
    mma_gemm<30,true><<<dim3(4, HW/256, Bv), 256, GEMM_SMEM>>>(
        w_fuse, (const float*)p_cat, b_fuse, (float*)p_qkv, 320);

    // join: gather needs both mma output (stream order) and bigsort (event)
    cudaStreamWaitEvent(0, evS, 0);

    // 6) gather (writes q1/k1 flat + q2/k2/v transposed; nbt fused)
    gather_kernel<<<EB, 256>>>();

    // 7) L2 norms
    norm_kernel<<<512, 256>>>((const float*)p_gq1, (float*)p_nq);
    norm_kernel<<<512, 256>>>((const float*)p_gk1, (float*)p_nk);
    norm_kernel<<<512, 256>>>((const float*)p_tq2, (float*)p_nq + 512);
    norm_kernel<<<512, 256>>>((const float*)p_tk2, (float*)p_nk + 512);

    // 8) Q.K^T partials + softmax
    qk_partial_kernel<<<dim3(16, 8), 256>>>((const float*)p_gq1, (const float*)p_gk1,
                                            (float*)p_part);
    qk_partial_kernel<<<dim3(16, 8), 256>>>((const float*)p_tq2, (const float*)p_tk2,
                                            (float*)p_part + 8*16*4096);
    softmax_kernel<<<dim3(8, 2), 64>>>(temp);

    // 9) o = attn @ vv (both variants)
    o_gemm_kernel<<<dim3(144, 8), 256>>>((const float*)p_attn, (const float*)p_vsc,
                                         (float*)p_o1);
    o_gemm_kernel<<<dim3(144, 8), 256>>>((const float*)p_attn + 8*4096, (const float*)p_tv,
                                         (float*)p_ont);

    // 10) combine (nbt_inv fused) + scatter, proj (fp32), final unsort
    combine_scatter_kernel<<<EB, 256>>>();
    gemm64<<<dim3(HW/128, 1, Bv), 256>>>(
        w_proj, (const float*)p_pre, nullptr, (float*)p_outp, 64,
        (long long)64*HW, (long long)64*HW);
    final_kernel<<<EB, 256>>>(out);
}

// round 16
// speedup vs baseline: 1.4379x; 1.1366x over previous
#include <cuda_runtime.h>
#include <math.h>
#include <cstdint>

#define Bv 2
#define Cch 64
#define Hdim 192
#define Wdim 192
#define HW 36864
#define SEG 65536
#define CHUNK 8192

typedef unsigned long long u64;

// ---------------- scratch (static device globals; no runtime allocation) ----------------
__device__ float g_xwork[Bv*Cch*HW];
__device__ int   g_invh[Bv*32*HW];
__device__ int   g_invw[Bv*32*HW];
__device__ float g_q[Bv*320*HW];
__device__ float g_cat[Bv*960*HW];
__device__ float g_qkv[Bv*320*HW];
__device__ u64   g_sort[(size_t)Bv*64*SEG];
__device__ float g_gq1[Bv*Cch*HW];
__device__ float g_gk1[Bv*Cch*HW];
__device__ float g_vsc[Bv*Cch*HW];
__device__ float g_tq2[Bv*Cch*HW];
__device__ float g_tk2[Bv*Cch*HW];
__device__ float g_tv [Bv*Cch*HW];
__device__ float g_o1 [Bv*Cch*HW];
__device__ float g_ont[Bv*Cch*HW];
__device__ float g_pre[Bv*Cch*HW];
__device__ float g_outp[Bv*Cch*HW];
__device__ float g_part[2*8*16*4096];
__device__ float g_attn[2*8*4096];
__device__ float g_nq[2*512];
__device__ float g_nk[2*512];

// ---------------- sortable-key helpers ----------------
__device__ __forceinline__ u64 pack_kv(float f, uint32_t idx) {
    uint32_t u = __float_as_uint(f);
    u = (u & 0x80000000u) ? ~u : (u | 0x80000000u);
    return ((u64)u << 32) | idx;
}
__device__ __forceinline__ float unpack_key(u64 kv) {
    uint32_t u = (uint32_t)(kv >> 32);
    return __uint_as_float((u & 0x80000000u) ? (u ^ 0x80000000u) : ~u);
}
__device__ __forceinline__ void ce_reg(u64& a, u64& b, bool up) {
    u64 mn = a < b ? a : b;
    u64 mx = a < b ? b : a;
    a = up ? mn : mx;
    b = up ? mx : mn;
}

// ================= exact fp32 SIMT GEMM, BM=128 (q GEMM) =================
__global__ void gemm_kernel(const float* __restrict__ A, const float* __restrict__ Bm,
                            const float* __restrict__ bias, float* __restrict__ Cm,
                            int M, int K, int N) {
    const int BM = 128, BN = 64, BK = 16;
    int bn = blockIdx.x * BN, bm = blockIdx.y * BM, bb = blockIdx.z;
    const float* Bp = Bm + (size_t)bb * K * N;
    float* Cp = Cm + (size_t)bb * M * N;
    __shared__ float As[BK][BM];
    __shared__ float Bs[BK][BN];
    int tid = threadIdx.x;
    int tx = tid & 15, ty = tid >> 4;
    int rm = ty * 8, rn = tx * 4;
    float acc[8][4];
    #pragma unroll
    for (int i = 0; i < 8; i++)
        #pragma unroll
        for (int j = 0; j < 4; j++) acc[i][j] = 0.f;

    for (int k0 = 0; k0 < K; k0 += BK) {
        {
            int lm = tid >> 1;
            int lk = (tid & 1) * 8;
            int gm = bm + lm;
            if (gm < M) {
                float4 v0 = *reinterpret_cast<const float4*>(&A[(size_t)gm*K + k0 + lk]);
                float4 v1 = *reinterpret_cast<const float4*>(&A[(size_t)gm*K + k0 + lk + 4]);
                As[lk+0][lm] = v0.x; As[lk+1][lm] = v0.y; As[lk+2][lm] = v0.z; As[lk+3][lm] = v0.w;
                As[lk+4][lm] = v1.x; As[lk+5][lm] = v1.y; As[lk+6][lm] = v1.z; As[lk+7][lm] = v1.w;
            } else {
                #pragma unroll
                for (int i = 0; i < 8; i++) As[lk+i][lm] = 0.f;
            }
        }
        {
            int lk = tid >> 4; int ln = (tid & 15) * 4;
            float4 v = *reinterpret_cast<const float4*>(&Bp[(size_t)(k0 + lk)*N + bn + ln]);
            *reinterpret_cast<float4*>(&Bs[lk][ln]) = v;
        }
        __syncthreads();
        #pragma unroll
        for (int k = 0; k < BK; k++) {
            float4 a0 = *reinterpret_cast<const float4*>(&As[k][rm]);
            float4 a1 = *reinterpret_cast<const float4*>(&As[k][rm + 4]);
            float4 bv4 = *reinterpret_cast<const float4*>(&Bs[k][rn]);
            float av[8] = {a0.x, a0.y, a0.z, a0.w, a1.x, a1.y, a1.z, a1.w};
            float bv[4] = {bv4.x, bv4.y, bv4.z, bv4.w};
            #pragma unroll
            for (int i = 0; i < 8; i++)
                #pragma unroll
                for (int j = 0; j < 4; j++) acc[i][j] += av[i] * bv[j];
        }
        __syncthreads();
    }
    #pragma unroll
    for (int i = 0; i < 8; i++) {
        int gm = bm + rm + i;
        if (gm < M) {
            float bvv = bias ? bias[gm] : 0.f;
            float4 o = make_float4(acc[i][0] + bvv, acc[i][1] + bvv, acc[i][2] + bvv, acc[i][3] + bvv);
            *reinterpret_cast<float4*>(&Cp[(size_t)gm*N + bn + rn]) = o;
        }
    }
}

// ================= exact fp32 SIMT GEMM, BM=64 (v rows + proj) =================
__global__ void __launch_bounds__(256) gemm64(const float* __restrict__ A,
                                              const float* __restrict__ Bg,
                                              const float* __restrict__ bias,
                                              float* __restrict__ Cg, int K,
                                              long long bstr, long long cstr) {
    __shared__ float As[16][68];
    __shared__ float Bs[16][132];
    int tid = threadIdx.x;
    int bn = blockIdx.x * 128;
    const float* Bz = Bg + (size_t)blockIdx.z * bstr;
    float* Cz = Cg + (size_t)blockIdx.z * cstr;
    int arow = tid >> 2, akq = (tid & 3) * 4;
    int rm = (tid >> 4) * 4, rn = (tid & 15) * 8;
    float acc[4][8];
    #pragma unroll
    for (int i = 0; i < 4; i++)
        #pragma unroll
        for (int j = 0; j < 8; j++) acc[i][j] = 0.f;

    for (int k0 = 0; k0 < K; k0 += 16) {
        float4 av = *reinterpret_cast<const float4*>(&A[(size_t)arow * K + k0 + akq]);
        As[akq+0][arow] = av.x; As[akq+1][arow] = av.y;
        As[akq+2][arow] = av.z; As[akq+3][arow] = av.w;
        #pragma unroll
        for (int j = 0; j < 2; j++) {
            int v = tid + j * 256;
            int kk = v >> 5, nq = (v & 31) * 4;
            *reinterpret_cast<float4*>(&Bs[kk][nq]) =
                *reinterpret_cast<const float4*>(&Bz[(size_t)(k0 + kk)*HW + bn + nq]);
        }
        __syncthreads();
        #pragma unroll
        for (int kk = 0; kk < 16; kk++) {
            float a0 = As[kk][rm], a1 = As[kk][rm+1], a2 = As[kk][rm+2], a3 = As[kk][rm+3];
            float b[8];
            *reinterpret_cast<float4*>(&b[0]) = *reinterpret_cast<const float4*>(&Bs[kk][rn]);
            *reinterpret_cast<float4*>(&b[4]) = *reinterpret_cast<const float4*>(&Bs[kk][rn+4]);
            #pragma unroll
            for (int j = 0; j < 8; j++) {
                acc[0][j] += a0 * b[j];
                acc[1][j] += a1 * b[j];
                acc[2][j] += a2 * b[j];
                acc[3][j] += a3 * b[j];
            }
        }
        __syncthreads();
    }
    #pragma unroll
    for (int i = 0; i < 4; i++) {
        float bv = bias ? bias[rm + i] : 0.f;
        float4 o0 = make_float4(acc[i][0]+bv, acc[i][1]+bv, acc[i][2]+bv, acc[i][3]+bv);
        float4 o1 = make_float4(acc[i][4]+bv, acc[i][5]+bv, acc[i][6]+bv, acc[i][7]+bv);
        *reinterpret_cast<float4*>(&Cz[(size_t)(rm+i)*HW + bn + rn])     = o0;
        *reinterpret_cast<float4*>(&Cz[(size_t)(rm+i)*HW + bn + rn + 4]) = o1;
    }
}

// ================= mma.sync 3xBF16 GEMM (attention-operand rows only) =================
#define CP16CG(dst, src) asm volatile("cp.async.cg.shared.global [%0], [%1], 16;" :: "r"(dst), "l"(src) : "memory")
#define CP16CA(dst, src) asm volatile("cp.async.ca.shared.global [%0], [%1], 16;" :: "r"(dst), "l"(src) : "memory")
#define CP_COMMIT() asm volatile("cp.async.commit_group;" ::: "memory")
#define CP_WAIT(n)  asm volatile("cp.async.wait_group %0;" :: "n"(n) : "memory")
#define MMA_BF16(d, a0, a1, a2, a3, b0, b1) \
    asm volatile("mma.sync.aligned.m16n8k16.row.col.f32.bf16.bf16.f32 " \
        "{%0,%1,%2,%3}, {%4,%5,%6,%7}, {%8,%9}, {%0,%1,%2,%3};" \
        : "+f"((d)[0]), "+f"((d)[1]), "+f"((d)[2]), "+f"((d)[3]) \
        : "r"(a0), "r"(a1), "r"(a2), "r"(a3), "r"(b0), "r"(b1))

__device__ __forceinline__ uint32_t smem_u32(const void* p) {
    uint32_t a;
    asm("{ .reg .u64 t; cvta.to.shared.u64 t, %1; cvt.u32.u64 %0, t; }" : "=r"(a) : "l"(p));
    return a;
}
__device__ __forceinline__ void bf16_split2(float f0, float f1, uint32_t& hi, uint32_t& lo) {
    uint32_t h;
    asm("cvt.rn.bf16x2.f32 %0, %1, %2;" : "=r"(h) : "f"(f1), "f"(f0));
    float h0 = __uint_as_float(h << 16);
    float h1 = __uint_as_float(h & 0xFFFF0000u);
    float l0 = f0 - h0;
    float l1 = f1 - h1;
    asm("cvt.rn.bf16x2.f32 %0, %1, %2;" : "=r"(lo) : "f"(l1), "f"(l0));
    hi = h;
}

// BM=64, BN=256, BK=32, 2-stage cp.async, 8 warps (2Mx4N), 2 CTAs/SM.
template<int NC, bool HASBIAS>
__global__ void __launch_bounds__(256, 2) mma_gemm(const float* __restrict__ A,
                                                   const float* __restrict__ Bg,
                                                   const float* __restrict__ bias,
                                                   float* __restrict__ Cg, int M) {
    constexpr int K = NC * 32;
    constexpr int N = HW;
    constexpr int APITCH = 36;
    constexpr int BPITCH = 260;
    constexpr int AWORDS = 64 * APITCH;
    constexpr int STAGE_WORDS = AWORDS + 32 * BPITCH;

    extern __shared__ float sm[];
    int tid = threadIdx.x;
    int bm = blockIdx.x * 64;
    int bn = blockIdx.y * 256;
    const float* Az = A + (size_t)bm * K;
    const float* Bz = Bg + (size_t)blockIdx.z * K * N;
    float* Cz = Cg + (size_t)blockIdx.z * M * N;
    uint32_t sbase = smem_u32(sm);

    auto load_stage = [&](int chunk, int buf) {
        int k0 = chunk * 32;
        uint32_t abase = sbase + (uint32_t)buf * STAGE_WORDS * 4;
        #pragma unroll
        for (int j = 0; j < 2; j++) {
            int v = tid + j * 256;
            int m = v >> 3, kq = v & 7;
            uint32_t dst = abase + (uint32_t)(m * APITCH + kq * 4) * 4;
            const float* src = Az + (size_t)m * K + k0 + kq * 4;
            CP16CA(dst, src);
        }
        uint32_t bbase = abase + AWORDS * 4;
        #pragma unroll
        for (int j = 0; j < 8; j++) {
            int v = tid + j * 256;
            int k = v >> 6, nq = v & 63;
            uint32_t dst = bbase + (uint32_t)(k * BPITCH + nq * 4) * 4;
            const float* src = Bz + (size_t)(k0 + k) * N + bn + nq * 4;
            CP16CG(dst, src);
        }
    };

    int lane = tid & 31, g = lane >> 2, tg = lane & 3;
    int wid = tid >> 5;
    int wm = (wid & 1) * 32;
    int wn = (wid >> 1) * 64;

    float acc[2][8][4];
    #pragma unroll
    for (int mf = 0; mf < 2; mf++)
        #pragma unroll
        for (int nf = 0; nf < 8; nf++)
            #pragma unroll
            for (int q = 0; q < 4; q++) acc[mf][nf][q] = 0.f;

    load_stage(0, 0);
    CP_COMMIT();

    for (int c = 0; c < NC; c++) {
        CP_WAIT(0);
        __syncthreads();
        {
            int nxt = c + 1;
            if (nxt < NC) load_stage(nxt, nxt & 1);
            CP_COMMIT();
        }
        const float* As = sm + (size_t)(c & 1) * STAGE_WORDS;
        const float* Bs = As + AWORDS;
        #pragma unroll
        for (int ks = 0; ks < 2; ks++) {
            int ka = ks * 16 + 2 * tg;
            uint32_t ah[2][4], al[2][4];
            #pragma unroll
            for (int mf = 0; mf < 2; mf++) {
                int m = wm + mf * 16 + g;
                float2 v0 = *reinterpret_cast<const float2*>(&As[m * APITCH + ka]);
                float2 v1 = *reinterpret_cast<const float2*>(&As[(m + 8) * APITCH + ka]);
                float2 v2 = *reinterpret_cast<const float2*>(&As[m * APITCH + ka + 8]);
                float2 v3 = *reinterpret_cast<const float2*>(&As[(m + 8) * APITCH + ka + 8]);
                bf16_split2(v0.x, v0.y, ah[mf][0], al[mf][0]);
                bf16_split2(v1.x, v1.y, ah[mf][1], al[mf][1]);
                bf16_split2(v2.x, v2.y, ah[mf][2], al[mf][2]);
                bf16_split2(v3.x, v3.y, ah[mf][3], al[mf][3]);
            }
            #pragma unroll
            for (int nf = 0; nf < 8; nf++) {
                int n = wn + nf * 8 + g;
                uint32_t b0h, b0l, b1h, b1l;
                bf16_split2(Bs[(ka)     * BPITCH + n], Bs[(ka + 1) * BPITCH + n], b0h, b0l);
                bf16_split2(Bs[(ka + 8) * BPITCH + n], Bs[(ka + 9) * BPITCH + n], b1h, b1l);
                #pragma unroll
                for (int mf = 0; mf < 2; mf++) {
                    MMA_BF16(acc[mf][nf], ah[mf][0], ah[mf][1], ah[mf][2], ah[mf][3], b0h, b1h);
                    MMA_BF16(acc[mf][nf], ah[mf][0], ah[mf][1], ah[mf][2], ah[mf][3], b0l, b1l);
                    MMA_BF16(acc[mf][nf], al[mf][0], al[mf][1], al[mf][2], al[mf][3], b0h, b1h);
                }
            }
        }
        __syncthreads();
    }

    #pragma unroll
    for (int mf = 0; mf < 2; mf++) {
        int row = bm + wm + mf * 16 + g;
        float bv0 = 0.f, bv1 = 0.f;
        if (HASBIAS) { bv0 = bias[row]; bv1 = bias[row + 8]; }
        #pragma unroll
        for (int nf = 0; nf < 8; nf++) {
            int col = bn + wn + nf * 8 + 2 * tg;
            float2 v0 = make_float2(acc[mf][nf][0] + bv0, acc[mf][nf][1] + bv0);
            float2 v1 = make_float2(acc[mf][nf][2] + bv1, acc[mf][nf][3] + bv1);
            *reinterpret_cast<float2*>(&Cz[(size_t)row * N + col]) = v0;
            *reinterpret_cast<float2*>(&Cz[(size_t)(row + 8) * N + col]) = v1;
        }
    }
}

// ---------------- small 192-element sorts (stable, packed u64, padded to 256) ----------------
__global__ void sort_h_kernel(const float* __restrict__ x) {
    int blk = blockIdx.x;
    int w = blk % Wdim; int c = (blk / Wdim) % 32; int b = blk / (Wdim * 32);
    __shared__ u64 key[256];
    int t = threadIdx.x;
    key[t] = (t < Hdim) ? pack_kv(x[((b*Cch + c)*Hdim + t)*Wdim + w], (uint32_t)t)
                        : ((0xFFFFFFFFull << 32) | (uint32_t)t);
    __syncthreads();
    for (int k = 2; k <= 256; k <<= 1) {
        for (int s = k >> 1; s > 0; s >>= 1) {
            int j = t ^ s;
            if (j > t) {
                u64 a = key[t], bb = key[j];
                if ((a > bb) == ((t & k) == 0)) { key[t] = bb; key[j] = a; }
            }
            __syncthreads();
        }
    }
    if (t < Hdim) {
        u64 v = key[t];
        g_xwork[((b*Cch + c)*Hdim + t)*Wdim + w] = unpack_key(v);
        g_invh[((b*32 + c)*Hdim + (int)(uint32_t)v)*Wdim + w] = t;
    }
}

__global__ void sort_w_kernel() {
    int blk = blockIdx.x;
    int h = blk % Hdim; int c = (blk / Hdim) % 32; int b = blk / (Hdim * 32);
    int base = ((b*Cch + c)*Hdim + h)*Wdim;
    __shared__ u64 key[256];
    int t = threadIdx.x;
    key[t] = (t < Wdim) ? pack_kv(g_xwork[base + t], (uint32_t)t)
                        : ((0xFFFFFFFFull << 32) | (uint32_t)t);
    __syncthreads();
    for (int k = 2; k <= 256; k <<= 1) {
        for (int s = k >> 1; s > 0; s >>= 1) {
            int j = t ^ s;
            if (j > t) {
                u64 a = key[t], bb = key[j];
                if ((a > bb) == ((t & k) == 0)) { key[t] = bb; key[j] = a; }
            }
            __syncthreads();
        }
    }
    if (t < Wdim) {
        u64 v = key[t];
        g_xwork[base + t] = unpack_key(v);
        g_invw[((b*32 + c)*Hdim + h)*Wdim + (int)(uint32_t)v] = t;
    }
}

__global__ void copy_rest_kernel(const float* __restrict__ x) {
    int gid = blockIdx.x * 256 + threadIdx.x;
    if (gid >= Bv*32*HW) return;
    int p = gid % HW; int c = (gid / HW) % 32; int b = gid / (32 * HW);
    int o = (b*Cch + 32 + c)*HW + p;
    g_xwork[o] = x[o];
}

// ---------------- fused depthwise 3x3 / 5x5 / 7x7 ----------------
__global__ void dwconv_kernel(const float* __restrict__ w3, const float* __restrict__ w5,
                              const float* __restrict__ w7) {
    int tile = blockIdx.x; int ch = blockIdx.y; int b = blockIdx.z;
    int ty0 = (tile / 12) * 16, tx0 = (tile % 12) * 16;
    __shared__ float s[22][24];
    __shared__ float wts[83];
    int tid = threadIdx.y * 16 + threadIdx.x;
    if (tid < 9)       wts[tid] = w3[ch*9 + tid];
    else if (tid < 34) wts[tid] = w5[ch*25 + tid - 9];
    else if (tid < 83) wts[tid] = w7[ch*49 + tid - 34];
    const float* base = g_q + (size_t)(b*320 + ch) * HW;
    for (int i = tid; i < 22*22; i += 256) {
        int sy = i / 22, sx = i % 22;
        int gy = ty0 + sy - 3, gx = tx0 + sx - 3;
        s[sy][sx] = (gy >= 0 && gy < Hdim && gx >= 0 && gx < Wdim) ? base[gy*Wdim + gx] : 0.f;
    }
    __syncthreads();
    int y = threadIdx.y, x = threadIdx.x;
    float a3 = 0.f, a5 = 0.f, a7 = 0.f;
    #pragma unroll
    for (int dy = 0; dy < 7; dy++)
        #pragma unroll
        for (int dx = 0; dx < 7; dx++) {
            float v = s[y + dy][x + dx];
            a7 += wts[34 + dy*7 + dx] * v;
            if (dy >= 1 && dy <= 5 && dx >= 1 && dx <= 5) a5 += wts[9 + (dy-1)*5 + (dx-1)] * v;
            if (dy >= 2 && dy <= 4 && dx >= 2 && dx <= 4) a3 += wts[(dy-2)*3 + (dx-2)] * v;
        }
    int gp = (ty0 + y)*Wdim + tx0 + x;
    size_t bo = (size_t)b * 960 * HW;
    g_cat[bo + (size_t)ch*HW + gp]        = a3;
    g_cat[bo + (size_t)(320 + ch)*HW + gp] = a5;
    g_cat[bo + (size_t)(640 + ch)*HW + gp] = a7;
}

// ================= parallel padding-aware bitonic sort =================
__global__ void init_pad_kernel() {
    int gid = blockIdx.x * 256 + threadIdx.x;
    const int per = 3 * CHUNK;
    if (gid >= 128 * per) return;
    int seg = gid / per;
    int i = 5 * CHUNK + gid % per;
    g_sort[(size_t)seg * SEG + i] = (0xFFFFFFFFull << 32) | (uint32_t)i;
}

__global__ void __launch_bounds__(512) sort_chunk_kernel() {
    int seg = blockIdx.x;
    int cb = blockIdx.y * CHUNK;
    u64* K = g_sort + (size_t)seg * SEG;
    const float* src = g_qkv + ((size_t)(seg >> 6) * 320 + 256 + (seg & 63)) * HW;
    extern __shared__ u64 sk[];
    int t = threadIdx.x;

    for (int i = t; i < CHUNK; i += 512) {
        int gi = cb + i;
        sk[i] = (gi < HW) ? pack_kv(src[gi], (uint32_t)gi)
                          : ((0xFFFFFFFFull << 32) | (uint32_t)gi);
    }
    __syncthreads();
    for (int gr = t; gr < CHUNK/8; gr += 512) {
        int base = gr * 8;
        u64 r[8];
        #pragma unroll
        for (int j = 0; j < 8; j++) r[j] = sk[base + j];
        ce_reg(r[0], r[1], ((base + 0) & 2) == 0);
        ce_reg(r[2], r[3], ((base + 2) & 2) == 0);
        ce_reg(r[4], r[5], ((base + 4) & 2) == 0);
        ce_reg(r[6], r[7], ((base + 6) & 2) == 0);
        {
            bool u0 = ((base + 0) & 4) == 0, u1 = ((base + 4) & 4) == 0;
            ce_reg(r[0], r[2], u0); ce_reg(r[1], r[3], u0);
            ce_reg(r[4], r[6], u1); ce_reg(r[5], r[7], u1);
            ce_reg(r[0], r[1], u0); ce_reg(r[2], r[3], u0);
            ce_reg(r[4], r[5], u1); ce_reg(r[6], r[7], u1);
        }
        {
            bool u = (base & 8) == 0;
            ce_reg(r[0], r[4], u); ce_reg(r[1], r[5], u); ce_reg(r[2], r[6], u); ce_reg(r[3], r[7], u);
            ce_reg(r[0], r[2], u); ce_reg(r[1], r[3], u); ce_reg(r[4], r[6], u); ce_reg(r[5], r[7], u);
            ce_reg(r[0], r[1], u); ce_reg(r[2], r[3], u); ce_reg(r[4], r[5], u); ce_reg(r[6], r[7], u);
        }
        #pragma unroll
        for (int j = 0; j < 8; j++) sk[base + j] = r[j];
    }
    __syncthreads();
    for (int k = 16; k <= CHUNK; k <<= 1) {
        for (int s = k >> 1; s >= 8; s >>= 1) {
            for (int p = t; p < CHUNK/2; p += 512) {
                int i = ((p & ~(s - 1)) << 1) | (p & (s - 1));
                int j = i + s;
                bool up = (((cb + i) & k) == 0);
                u64 a = sk[i], b = sk[j];
                u64 mn = a < b ? a : b;
                u64 mx = a < b ? b : a;
                sk[i] = up ? mn : mx;
                sk[j] = up ? mx : mn;
            }
            __syncthreads();
        }
        for (int gr = t; gr < CHUNK/8; gr += 512) {
            int base = gr * 8;
            bool u = (((cb + base) & k) == 0);
            u64 r[8];
            #pragma unroll
            for (int j = 0; j < 8; j++) r[j] = sk[base + j];
            ce_reg(r[0], r[4], u); ce_reg(r[1], r[5], u); ce_reg(r[2], r[6], u); ce_reg(r[3], r[7], u);
            ce_reg(r[0], r[2], u); ce_reg(r[1], r[3], u); ce_reg(r[4], r[6], u); ce_reg(r[5], r[7], u);
            ce_reg(r[0], r[1], u); ce_reg(r[2], r[3], u); ce_reg(r[4], r[5], u); ce_reg(r[6], r[7], u);
            #pragma unroll
            for (int j = 0; j < 8; j++) sk[base + j] = r[j];
        }
        __syncthreads();
    }
    for (int i = t; i < CHUNK; i += 512) K[cb + i] = sk[i];
}

__global__ void gpass_kernel(int k, int s) {
    int t = blockIdx.x * 256 + threadIdx.x;
    if (t >= 128 * (SEG/2)) return;
    int seg = t / (SEG/2);
    int p = t % (SEG/2);
    int i = ((p & ~(s - 1)) << 1) | (p & (s - 1));
    int j = i + s;
    u64* K = g_sort + (size_t)seg * SEG;
    bool up = ((i & k) == 0);
    u64 a = K[i], b = K[j];
    u64 mn = a < b ? a : b;
    u64 mx = a < b ? b : a;
    K[i] = up ? mn : mx;
    K[j] = up ? mx : mn;
}

__global__ void __launch_bounds__(512) merge_chunk_kernel(int k, int mask) {
    int seg = blockIdx.x;
    int y = blockIdx.y;
    int cidx = 0;
    {
        int cnt = -1;
        #pragma unroll
        for (int b = 0; b < 8; b++) {
            if (mask & (1 << b)) { cnt++; if (cnt == y) { cidx = b; break; } }
        }
    }
    int cb = cidx * CHUNK;
    u64* K = g_sort + (size_t)seg * SEG;
    extern __shared__ u64 sk[];
    int t = threadIdx.x;
    for (int i = t; i < CHUNK; i += 512) sk[i] = K[cb + i];
    __syncthreads();
    for (int s = CHUNK >> 1; s >= 8; s >>= 1) {
        for (int p = t; p < CHUNK/2; p += 512) {
            int i = ((p & ~(s - 1)) << 1) | (p & (s - 1));
            int j = i + s;
            bool up = (((cb + i) & k) == 0);
            u64 a = sk[i], b = sk[j];
            u64 mn = a < b ? a : b;
            u64 mx = a < b ? b : a;
            sk[i] = up ? mn : mx;
            sk[j] = up ? mx : mn;
        }
        __syncthreads();
    }
    for (int gr = t; gr < CHUNK/8; gr += 512) {
        int base = gr * 8;
        bool u = (((cb + base) & k) == 0);
        u64 r[8];
        #pragma unroll
        for (int j = 0; j < 8; j++) r[j] = sk[base + j];
        ce_reg(r[0], r[4], u); ce_reg(r[1], r[5], u); ce_reg(r[2], r[6], u); ce_reg(r[3], r[7], u);
        ce_reg(r[0], r[2], u); ce_reg(r[1], r[3], u); ce_reg(r[4], r[6], u); ce_reg(r[5], r[7], u);
        ce_reg(r[0], r[1], u); ce_reg(r[2], r[3], u); ce_reg(r[4], r[5], u); ce_reg(r[6], r[7], u);
        #pragma unroll
        for (int j = 0; j < 8; j++) sk[base + j] = r[j];
    }
    __syncthreads();
    for (int i = t; i < CHUNK; i += 512) K[cb + i] = sk[i];
}

// ---------------- gather q1/k1 + transposed q2/k2/v (nbt fused in) ----------------
__global__ void gather_kernel() {
    int gid = blockIdx.x * 256 + threadIdx.x;
    if (gid >= Bv*Cch*HW) return;
    int r = gid % HW; int c = (gid / HW) % Cch; int b = gid / (HW * Cch);
    u64 kv = g_sort[(size_t)(b*64 + c)*SEG + r];
    int src = (int)(uint32_t)kv;
    float v = unpack_key(kv);
    size_t qb = (size_t)b * 320 * HW;
    g_gq1[gid] = g_qkv[qb + (size_t)c*HW + src];
    g_gk1[gid] = g_qkv[qb + (size_t)(64 + c)*HW + src];
    float q2v = g_qkv[qb + (size_t)(128 + c)*HW + src];
    float k2v = g_qkv[qb + (size_t)(192 + c)*HW + src];
    g_vsc[gid] = v;
    int h = c >> 4, chi = c & 15;
    size_t ti = ((size_t)(b*4 + h)*64 + chi*4 + (r & 3))*9216 + (r >> 2);
    g_tq2[ti] = q2v;
    g_tk2[ti] = k2v;
    g_tv[ti]  = v;
}

__global__ void norm_kernel(const float* __restrict__ t, float* __restrict__ out) {
    int row = blockIdx.x;
    const float* p = t + (size_t)row * 9216;
    float ss = 0.f;
    for (int i = threadIdx.x; i < 9216; i += 256) { float v = p[i]; ss += v * v; }
    __shared__ float red[256];
    red[threadIdx.x] = ss;
    __syncthreads();
    for (int o = 128; o > 0; o >>= 1) {
        if (threadIdx.x < o) red[threadIdx.x] += red[threadIdx.x + o];
        __syncthreads();
    }
    if (threadIdx.x == 0) out[row] = fmaxf(sqrtf(red[0]), 1e-12f);
}

__global__ void qk_partial_kernel(const float* __restrict__ q, const float* __restrict__ k,
                                  float* __restrict__ part) {
    int kc = blockIdx.x, bh = blockIdx.y;
    const float* qb = q + (size_t)bh * 64 * 9216;
    const float* kb = k + (size_t)bh * 64 * 9216;
    __shared__ float qs[64][65];
    __shared__ float ks[64][65];
    int tid = threadIdx.x;
    int rm = (tid >> 4) * 4, rn = (tid & 15) * 4;
    float acc[4][4];
    #pragma unroll
    for (int i = 0; i < 4; i++)
        #pragma unroll
        for (int j = 0; j < 4; j++) acc[i][j] = 0.f;
    int nbase0 = kc * 576;
    for (int nt = 0; nt < 576; nt += 64) {
        #pragma unroll
        for (int l = 0; l < 16; l++) {
            int lin = l * 256 + tid;
            int d = lin >> 6, nn = lin & 63;
            qs[d][nn] = qb[(size_t)d*9216 + nbase0 + nt + nn];
            ks[d][nn] = kb[(size_t)d*9216 + nbase0 + nt + nn];
        }
        __syncthreads();
        #pragma unroll 8
        for (int nn = 0; nn < 64; nn++) {
            float a[4], bv[4];
            #pragma unroll
            for (int i = 0; i < 4; i++) a[i] = qs[rm + i][nn];
            #pragma unroll
            for (int j = 0; j < 4; j++) bv[j] = ks[rn + j][nn];
            #pragma unroll
            for (int i = 0; i < 4; i++)
                #pragma unroll
                for (int j = 0; j < 4; j++) acc[i][j] += a[i] * bv[j];
        }
        __syncthreads();
    }
    float* pp = part + ((size_t)bh * 16 + kc) * 4096;
    #pragma unroll
    for (int i = 0; i < 4; i++)
        #pragma unroll
        for (int j = 0; j < 4; j++) pp[(rm + i)*64 + rn + j] = acc[i][j];
}

__global__ void softmax_kernel(const float* __restrict__ temp) {
    int bh = blockIdx.x, var = blockIdx.y;
    int d = threadIdx.x;
    int h = bh & 3;
    const float* pp = g_part + ((size_t)(var*8 + bh) * 16) * 4096;
    float qn = g_nq[var*512 + bh*64 + d];
    float tmp = temp[h];
    float ev[64];
    float rs = 0.f;
    #pragma unroll
    for (int e = 0; e < 64; e++) {
        float s = 0.f;
        #pragma unroll
        for (int c2 = 0; c2 < 16; c2++) s += pp[(size_t)c2*4096 + d*64 + e];
        float a = s * tmp / (qn * g_nk[var*512 + bh*64 + e]);
        float x = expf(a);
        ev[e] = x;
        rs += x;
    }
    float inv = 1.f / (rs + 1.f);
    float* ap = g_attn + (size_t)(var*8 + bh) * 4096;
    #pragma unroll
    for (int e = 0; e < 64; e++) ap[d*64 + e] = ev[e] * inv;
}

__global__ void o_gemm_kernel(const float* __restrict__ attn, const float* __restrict__ v,
                              float* __restrict__ o) {
    int nt = blockIdx.x * 64, bh = blockIdx.y;
    const float* ap = attn + (size_t)bh * 4096;
    const float* vp = v + (size_t)bh * 64 * 9216;
    float* op = o + (size_t)bh * 64 * 9216;
    __shared__ float as_[64][65];
    __shared__ float vs_[64][65];
    int tid = threadIdx.x;
    #pragma unroll
    for (int l = 0; l < 16; l++) {
        int lin = l * 256 + tid;
        int r = lin >> 6, cc = lin & 63;
        as_[r][cc] = ap[lin];
        vs_[r][cc] = vp[(size_t)r*9216 + nt + cc];
    }
    __syncthreads();
    int rm = (tid >> 4) * 4, rn = (tid & 15) * 4;
    float acc[4][4];
    #pragma unroll
    for (int i = 0; i < 4; i++)
        #pragma unroll
        for (int j = 0; j < 4; j++) acc[i][j] = 0.f;
    #pragma unroll 8
    for (int e = 0; e < 64; e++) {
        float a[4], bv[4];
        #pragma unroll
        for (int i = 0; i < 4; i++) a[i] = as_[rm + i][e];
        #pragma unroll
        for (int j = 0; j < 4; j++) bv[j] = vs_[e][rn + j];
        #pragma unroll
        for (int i = 0; i < 4; i++)
            #pragma unroll
            for (int j = 0; j < 4; j++) acc[i][j] += a[i] * bv[j];
    }
    #pragma unroll
    for (int i = 0; i < 4; i++) {
        float4 ov = make_float4(acc[i][0], acc[i][1], acc[i][2], acc[i][3]);
        *reinterpret_cast<float4*>(&op[(size_t)(rm + i)*9216 + nt + rn]) = ov;
    }
}

// ---------------- combine out1*out2 (nbt_inv fused) + scatter back ----------------
__global__ void combine_scatter_kernel() {
    int gid = blockIdx.x * 256 + threadIdx.x;
    if (gid >= Bv*Cch*HW) return;
    int p = gid % HW; int c = (gid / HW) % 64; int b = gid / (HW * 64);
    u64 kv = g_sort[(size_t)(b*64 + c)*SEG + p];
    int dst = (int)(uint32_t)kv;
    int h = c >> 4, chi = c & 15;
    float o2v = g_ont[((size_t)(b*4 + h)*64 + chi*4 + (p & 3))*9216 + (p >> 2)];
    g_pre[(size_t)(b*64 + c)*HW + dst] = g_o1[gid] * o2v;
}

__global__ void final_kernel(float* __restrict__ out) {
    int gid = blockIdx.x * 256 + threadIdx.x;
    if (gid >= Bv*Cch*HW) return;
    int w = gid % Wdim; int h = (gid / Wdim) % Hdim;
    int c = (gid / HW) % 64; int b = gid / (HW * 64);
    if (c < 32) {
        int hh = g_invh[((b*32 + c)*Hdim + h)*Wdim + w];
        int ww = g_invw[((b*32 + c)*Hdim + hh)*Wdim + w];
        out[gid] = g_outp[(size_t)(b*64 + c)*HW + hh*Wdim + ww];
    } else {
        out[gid] = g_outp[gid];
    }
}

// ---------------- launcher ----------------
extern "C" void kernel_launch(void* const* d_in, const int* in_sizes, int n_in,
                              void* d_out, int out_size) {
    (void)in_sizes; (void)n_in; (void)out_size;
    const float* x      = (const float*)d_in[0];
    const float* temp   = (const float*)d_in[1];
    const float* w_qkv  = (const float*)d_in[2];
    const float* w_dw3  = (const float*)d_in[3];
    const float* w_dw5  = (const float*)d_in[4];
    const float* w_dw7  = (const float*)d_in[5];
    const float* w_fuse = (const float*)d_in[6];
    const float* b_fuse = (const float*)d_in[7];
    const float* w_proj = (const float*)d_in[8];
    float* out = (float*)d_out;

    static cudaStream_t s2 = nullptr;
    static cudaEvent_t evF = nullptr, evV = nullptr, evS = nullptr, evC = nullptr;
    if (!s2) {
        cudaStreamCreateWithFlags(&s2, cudaStreamNonBlocking);
        cudaEventCreateWithFlags(&evF, cudaEventDisableTiming);
        cudaEventCreateWithFlags(&evV, cudaEventDisableTiming);
        cudaEventCreateWithFlags(&evS, cudaEventDisableTiming);
        cudaEventCreateWithFlags(&evC, cudaEventDisableTiming);
    }

    const int GEMM_SMEM = 2 * 42496;  // 84992 B (2-stage, 2 CTAs/SM)
    const int SORT_SMEM = CHUNK * 8;  // 65536 B
    cudaFuncSetAttribute(sort_chunk_kernel, cudaFuncAttributeMaxDynamicSharedMemorySize, SORT_SMEM);
    cudaFuncSetAttribute(merge_chunk_kernel, cudaFuncAttributeMaxDynamicSharedMemorySize, SORT_SMEM);
    cudaFuncSetAttribute(mma_gemm<30,true>, cudaFuncAttributeMaxDynamicSharedMemorySize, GEMM_SMEM);

    void *p_xwork, *p_q, *p_cat, *p_qkv, *p_pre, *p_outp;
    void *p_gq1, *p_gk1, *p_vsc, *p_tq2, *p_tk2, *p_tv;
    void *p_o1, *p_ont, *p_part, *p_attn, *p_nq, *p_nk;
    cudaGetSymbolAddress(&p_xwork, g_xwork);
    cudaGetSymbolAddress(&p_q, g_q);
    cudaGetSymbolAddress(&p_cat, g_cat);
    cudaGetSymbolAddress(&p_qkv, g_qkv);
    cudaGetSymbolAddress(&p_pre, g_pre);
    cudaGetSymbolAddress(&p_outp, g_outp);
    cudaGetSymbolAddress(&p_gq1, g_gq1);
    cudaGetSymbolAddress(&p_gk1, g_gk1);
    cudaGetSymbolAddress(&p_vsc, g_vsc);
    cudaGetSymbolAddress(&p_tq2, g_tq2);
    cudaGetSymbolAddress(&p_tk2, g_tk2);
    cudaGetSymbolAddress(&p_tv, g_tv);
    cudaGetSymbolAddress(&p_o1, g_o1);
    cudaGetSymbolAddress(&p_ont, g_ont);
    cudaGetSymbolAddress(&p_part, g_part);
    cudaGetSymbolAddress(&p_attn, g_attn);
    cudaGetSymbolAddress(&p_nq, g_nq);
    cudaGetSymbolAddress(&p_nk, g_nk);

    const int NELT = Bv*Cch*HW;
    const int EB = (NELT + 255) / 256;

    // 0) capture-legal fork of side stream from the origin stream
    cudaEventRecord(evF, 0);
    cudaStreamWaitEvent(s2, evF, 0);

    // 1) channel sorts on main; copy of untouched channels + pad init on side
    copy_rest_kernel<<<(Bv*32*HW + 255)/256, 256, 0, s2>>>(x);
    init_pad_kernel<<<(128*3*CHUNK + 255)/256, 256, 0, s2>>>();
    cudaEventRecord(evC, s2);
    sort_h_kernel<<<Bv*32*Wdim, 256>>>(x);
    sort_w_kernel<<<Bv*32*Hdim, 256>>>();
    cudaStreamWaitEvent(0, evC, 0);   // q gemm needs copy_rest

    // 2) q = w_qkv @ x   (M=320, K=64) — exact fp32 (feeds the v chain)
    gemm_kernel<<<dim3(HW/64, 3, Bv), 256>>>(
        w_qkv, (const float*)p_xwork, nullptr, (float*)p_q, 320, 64, HW);

    // 3) depthwise 3/5/7 -> cat (fp32)
    dwconv_kernel<<<dim3(144, 320, Bv), dim3(16, 16)>>>(w_dw3, w_dw5, w_dw7);

    // 4b FIRST) qkv rows 256..319 (v — feeds argsort, exact fp32)
    gemm64<<<dim3(HW/128, 1, Bv), 256>>>(
        w_fuse + (size_t)256*960, (const float*)p_cat, b_fuse + 256,
        (float*)p_qkv + (size_t)256*HW, 960,
        (long long)960*HW, (long long)320*HW);
    cudaEventRecord(evV, 0);

    // 5) parallel bitonic sort on side stream (bit-exact, padding-skipping)
    cudaStreamWaitEvent(s2, evV, 0);
    {
        const int GP_GRID = (128 * (SEG/2) + 255) / 256;
        sort_chunk_kernel<<<dim3(128, 5), 512, SORT_SMEM, s2>>>();
        // k = 16384
        gpass_kernel<<<GP_GRID, 256, 0, s2>>>(16384, 8192);
        merge_chunk_kernel<<<dim3(128, 5), 512, SORT_SMEM, s2>>>(16384, 31);    // {0,1,2,3,4}
        // k = 32768
        gpass_kernel<<<GP_GRID, 256, 0, s2>>>(32768, 16384);
        gpass_kernel<<<GP_GRID, 256, 0, s2>>>(32768, 8192);
        merge_chunk_kernel<<<dim3(128, 5), 512, SORT_SMEM, s2>>>(32768, 143);   // {0,1,2,3,7}
        // k = 65536
        gpass_kernel<<<GP_GRID, 256, 0, s2>>>(65536, 32768);
        gpass_kernel<<<GP_GRID, 256, 0, s2>>>(65536, 16384);
        gpass_kernel<<<GP_GRID, 256, 0, s2>>>(65536, 8192);
        merge_chunk_kernel<<<dim3(128, 5), 512, SORT_SMEM, s2>>>(65536, 31);    // {0,1,2,3,4}
    }
    cudaEventRecord(evS, s2);

    // 4a) qkv rows 0..255 (attention operands, sort-insensitive) — 3xBF16 mma (main stream)
    mma_gemm<30,true><<<dim3(4, HW/256, Bv), 256, GEMM_SMEM>>>(
        w_fuse, (const float*)p_cat, b_fuse, (float*)p_qkv, 320);

    // join: gather needs both mma output (stream order) and sort (event)
    cudaStreamWaitEvent(0, evS, 0);

    // 6) gather (writes q1/k1 flat + q2/k2/v transposed; nbt fused)
    gather_kernel<<<EB, 256>>>();

    // 7) L2 norms
    norm_kernel<<<512, 256>>>((const float*)p_gq1, (float*)p_nq);
    norm_kernel<<<512, 256>>>((const float*)p_gk1, (float*)p_nk);
    norm_kernel<<<512, 256>>>((const float*)p_tq2, (float*)p_nq + 512);
    norm_kernel<<<512, 256>>>((const float*)p_tk2, (float*)p_nk + 512);

    // 8) Q.K^T partials + softmax
    qk_partial_kernel<<<dim3(16, 8), 256>>>((const float*)p_gq1, (const float*)p_gk1,
                                            (float*)p_part);
    qk_partial_kernel<<<dim3(16, 8), 256>>>((const float*)p_tq2, (const float*)p_tk2,
                                            (float*)p_part + 8*16*4096);
    softmax_kernel<<<dim3(8, 2), 64>>>(temp);

    // 9) o = attn @ vv (both variants)
    o_gemm_kernel<<<dim3(144, 8), 256>>>((const float*)p_attn, (const float*)p_vsc,
                                         (float*)p_o1);
    o_gemm_kernel<<<dim3(144, 8), 256>>>((const float*)p_attn + 8*4096, (const float*)p_tv,
                                         (float*)p_ont);

    // 10) combine (nbt_inv fused) + scatter, proj (fp32), final unsort
    combine_scatter_kernel<<<EB, 256>>>();
    gemm64<<<dim3(HW/128, 1, Bv), 256>>>(
        w_proj, (const float*)p_pre, nullptr, (float*)p_outp, 64,
        (long long)64*HW, (long long)64*HW);
    final_kernel<<<EB, 256>>>(out);
}

// round 17
// speedup vs baseline: 1.5093x; 1.0497x over previous
#include <cuda_runtime.h>
#include <math.h>
#include <cstdint>

#define Bv 2
#define Cch 64
#define Hdim 192
#define Wdim 192
#define HW 36864
#define SEG 65536
#define CHUNK 8192

typedef unsigned long long u64;

// ---------------- scratch (static device globals; no runtime allocation) ----------------
__device__ float g_xwork[Bv*Cch*HW];
__device__ int   g_invh[Bv*32*HW];
__device__ int   g_invw[Bv*32*HW];
__device__ float g_q[Bv*320*HW];
__device__ float g_cat[Bv*960*HW];
__device__ float g_qkv[Bv*320*HW];
__device__ u64   g_sort[(size_t)Bv*64*SEG];
__device__ float g_gq1[Bv*Cch*HW];
__device__ float g_gk1[Bv*Cch*HW];
__device__ float g_vsc[Bv*Cch*HW];
__device__ float g_tq2[Bv*Cch*HW];
__device__ float g_tk2[Bv*Cch*HW];
__device__ float g_tv [Bv*Cch*HW];
__device__ float g_o1 [Bv*Cch*HW];
__device__ float g_ont[Bv*Cch*HW];
__device__ float g_pre[Bv*Cch*HW];
__device__ float g_outp[Bv*Cch*HW];
__device__ float g_part[2*8*16*4096];
__device__ float g_attn[2*8*4096];
__device__ float g_nq[2*512];
__device__ float g_nk[2*512];

// ---------------- sortable-key helpers ----------------
__device__ __forceinline__ u64 pack_kv(float f, uint32_t idx) {
    uint32_t u = __float_as_uint(f);
    u = (u & 0x80000000u) ? ~u : (u | 0x80000000u);
    return ((u64)u << 32) | idx;
}
__device__ __forceinline__ float unpack_key(u64 kv) {
    uint32_t u = (uint32_t)(kv >> 32);
    return __uint_as_float((u & 0x80000000u) ? (u ^ 0x80000000u) : ~u);
}
__device__ __forceinline__ void ce_reg(u64& a, u64& b, bool up) {
    u64 mn = a < b ? a : b;
    u64 mx = a < b ? b : a;
    a = up ? mn : mx;
    b = up ? mx : mn;
}

// ================= exact fp32 SIMT GEMM, BM=128 (q GEMM) =================
__global__ void gemm_kernel(const float* __restrict__ A, const float* __restrict__ Bm,
                            const float* __restrict__ bias, float* __restrict__ Cm,
                            int M, int K, int N) {
    const int BM = 128, BN = 64, BK = 16;
    int bn = blockIdx.x * BN, bm = blockIdx.y * BM, bb = blockIdx.z;
    const float* Bp = Bm + (size_t)bb * K * N;
    float* Cp = Cm + (size_t)bb * M * N;
    __shared__ float As[BK][BM];
    __shared__ float Bs[BK][BN];
    int tid = threadIdx.x;
    int tx = tid & 15, ty = tid >> 4;
    int rm = ty * 8, rn = tx * 4;
    float acc[8][4];
    #pragma unroll
    for (int i = 0; i < 8; i++)
        #pragma unroll
        for (int j = 0; j < 4; j++) acc[i][j] = 0.f;

    for (int k0 = 0; k0 < K; k0 += BK) {
        {
            int lm = tid >> 1;
            int lk = (tid & 1) * 8;
            int gm = bm + lm;
            if (gm < M) {
                float4 v0 = *reinterpret_cast<const float4*>(&A[(size_t)gm*K + k0 + lk]);
                float4 v1 = *reinterpret_cast<const float4*>(&A[(size_t)gm*K + k0 + lk + 4]);
                As[lk+0][lm] = v0.x; As[lk+1][lm] = v0.y; As[lk+2][lm] = v0.z; As[lk+3][lm] = v0.w;
                As[lk+4][lm] = v1.x; As[lk+5][lm] = v1.y; As[lk+6][lm] = v1.z; As[lk+7][lm] = v1.w;
            } else {
                #pragma unroll
                for (int i = 0; i < 8; i++) As[lk+i][lm] = 0.f;
            }
        }
        {
            int lk = tid >> 4; int ln = (tid & 15) * 4;
            float4 v = *reinterpret_cast<const float4*>(&Bp[(size_t)(k0 + lk)*N + bn + ln]);
            *reinterpret_cast<float4*>(&Bs[lk][ln]) = v;
        }
        __syncthreads();
        #pragma unroll
        for (int k = 0; k < BK; k++) {
            float4 a0 = *reinterpret_cast<const float4*>(&As[k][rm]);
            float4 a1 = *reinterpret_cast<const float4*>(&As[k][rm + 4]);
            float4 bv4 = *reinterpret_cast<const float4*>(&Bs[k][rn]);
            float av[8] = {a0.x, a0.y, a0.z, a0.w, a1.x, a1.y, a1.z, a1.w};
            float bv[4] = {bv4.x, bv4.y, bv4.z, bv4.w};
            #pragma unroll
            for (int i = 0; i < 8; i++)
                #pragma unroll
                for (int j = 0; j < 4; j++) acc[i][j] += av[i] * bv[j];
        }
        __syncthreads();
    }
    #pragma unroll
    for (int i = 0; i < 8; i++) {
        int gm = bm + rm + i;
        if (gm < M) {
            float bvv = bias ? bias[gm] : 0.f;
            float4 o = make_float4(acc[i][0] + bvv, acc[i][1] + bvv, acc[i][2] + bvv, acc[i][3] + bvv);
            *reinterpret_cast<float4*>(&Cp[(size_t)gm*N + bn + rn]) = o;
        }
    }
}

// ================= exact fp32 SIMT GEMM, BM=64 (v rows + proj) =================
__global__ void __launch_bounds__(256) gemm64(const float* __restrict__ A,
                                              const float* __restrict__ Bg,
                                              const float* __restrict__ bias,
                                              float* __restrict__ Cg, int K,
                                              long long bstr, long long cstr) {
    __shared__ float As[16][68];
    __shared__ float Bs[16][132];
    int tid = threadIdx.x;
    int bn = blockIdx.x * 128;
    const float* Bz = Bg + (size_t)blockIdx.z * bstr;
    float* Cz = Cg + (size_t)blockIdx.z * cstr;
    int arow = tid >> 2, akq = (tid & 3) * 4;
    int rm = (tid >> 4) * 4, rn = (tid & 15) * 8;
    float acc[4][8];
    #pragma unroll
    for (int i = 0; i < 4; i++)
        #pragma unroll
        for (int j = 0; j < 8; j++) acc[i][j] = 0.f;

    for (int k0 = 0; k0 < K; k0 += 16) {
        float4 av = *reinterpret_cast<const float4*>(&A[(size_t)arow * K + k0 + akq]);
        As[akq+0][arow] = av.x; As[akq+1][arow] = av.y;
        As[akq+2][arow] = av.z; As[akq+3][arow] = av.w;
        #pragma unroll
        for (int j = 0; j < 2; j++) {
            int v = tid + j * 256;
            int kk = v >> 5, nq = (v & 31) * 4;
            *reinterpret_cast<float4*>(&Bs[kk][nq]) =
                *reinterpret_cast<const float4*>(&Bz[(size_t)(k0 + kk)*HW + bn + nq]);
        }
        __syncthreads();
        #pragma unroll
        for (int kk = 0; kk < 16; kk++) {
            float a0 = As[kk][rm], a1 = As[kk][rm+1], a2 = As[kk][rm+2], a3 = As[kk][rm+3];
            float b[8];
            *reinterpret_cast<float4*>(&b[0]) = *reinterpret_cast<const float4*>(&Bs[kk][rn]);
            *reinterpret_cast<float4*>(&b[4]) = *reinterpret_cast<const float4*>(&Bs[kk][rn+4]);
            #pragma unroll
            for (int j = 0; j < 8; j++) {
                acc[0][j] += a0 * b[j];
                acc[1][j] += a1 * b[j];
                acc[2][j] += a2 * b[j];
                acc[3][j] += a3 * b[j];
            }
        }
        __syncthreads();
    }
    #pragma unroll
    for (int i = 0; i < 4; i++) {
        float bv = bias ? bias[rm + i] : 0.f;
        float4 o0 = make_float4(acc[i][0]+bv, acc[i][1]+bv, acc[i][2]+bv, acc[i][3]+bv);
        float4 o1 = make_float4(acc[i][4]+bv, acc[i][5]+bv, acc[i][6]+bv, acc[i][7]+bv);
        *reinterpret_cast<float4*>(&Cz[(size_t)(rm+i)*HW + bn + rn])     = o0;
        *reinterpret_cast<float4*>(&Cz[(size_t)(rm+i)*HW + bn + rn + 4]) = o1;
    }
}

// ================= mma.sync 3xBF16 GEMM (attention-operand rows only) =================
#define CP16CG(dst, src) asm volatile("cp.async.cg.shared.global [%0], [%1], 16;" :: "r"(dst), "l"(src) : "memory")
#define CP16CA(dst, src) asm volatile("cp.async.ca.shared.global [%0], [%1], 16;" :: "r"(dst), "l"(src) : "memory")
#define CP_COMMIT() asm volatile("cp.async.commit_group;" ::: "memory")
#define CP_WAIT(n)  asm volatile("cp.async.wait_group %0;" :: "n"(n) : "memory")
#define MMA_BF16(d, a0, a1, a2, a3, b0, b1) \
    asm volatile("mma.sync.aligned.m16n8k16.row.col.f32.bf16.bf16.f32 " \
        "{%0,%1,%2,%3}, {%4,%5,%6,%7}, {%8,%9}, {%0,%1,%2,%3};" \
        : "+f"((d)[0]), "+f"((d)[1]), "+f"((d)[2]), "+f"((d)[3]) \
        : "r"(a0), "r"(a1), "r"(a2), "r"(a3), "r"(b0), "r"(b1))

__device__ __forceinline__ uint32_t smem_u32(const void* p) {
    uint32_t a;
    asm("{ .reg .u64 t; cvta.to.shared.u64 t, %1; cvt.u32.u64 %0, t; }" : "=r"(a) : "l"(p));
    return a;
}
__device__ __forceinline__ void bf16_split2(float f0, float f1, uint32_t& hi, uint32_t& lo) {
    uint32_t h;
    asm("cvt.rn.bf16x2.f32 %0, %1, %2;" : "=r"(h) : "f"(f1), "f"(f0));
    float h0 = __uint_as_float(h << 16);
    float h1 = __uint_as_float(h & 0xFFFF0000u);
    float l0 = f0 - h0;
    float l1 = f1 - h1;
    asm("cvt.rn.bf16x2.f32 %0, %1, %2;" : "=r"(lo) : "f"(l1), "f"(l0));
    hi = h;
}

// BM=64, BN=256, BK=32, 2-stage cp.async, 8 warps (2Mx4N), 2 CTAs/SM.
template<int NC, bool HASBIAS>
__global__ void __launch_bounds__(256, 2) mma_gemm(const float* __restrict__ A,
                                                   const float* __restrict__ Bg,
                                                   const float* __restrict__ bias,
                                                   float* __restrict__ Cg, int M) {
    constexpr int K = NC * 32;
    constexpr int N = HW;
    constexpr int APITCH = 36;
    constexpr int BPITCH = 260;
    constexpr int AWORDS = 64 * APITCH;
    constexpr int STAGE_WORDS = AWORDS + 32 * BPITCH;

    extern __shared__ float sm[];
    int tid = threadIdx.x;
    int bm = blockIdx.x * 64;
    int bn = blockIdx.y * 256;
    const float* Az = A + (size_t)bm * K;
    const float* Bz = Bg + (size_t)blockIdx.z * K * N;
    float* Cz = Cg + (size_t)blockIdx.z * M * N;
    uint32_t sbase = smem_u32(sm);

    auto load_stage = [&](int chunk, int buf) {
        int k0 = chunk * 32;
        uint32_t abase = sbase + (uint32_t)buf * STAGE_WORDS * 4;
        #pragma unroll
        for (int j = 0; j < 2; j++) {
            int v = tid + j * 256;
            int m = v >> 3, kq = v & 7;
            uint32_t dst = abase + (uint32_t)(m * APITCH + kq * 4) * 4;
            const float* src = Az + (size_t)m * K + k0 + kq * 4;
            CP16CA(dst, src);
        }
        uint32_t bbase = abase + AWORDS * 4;
        #pragma unroll
        for (int j = 0; j < 8; j++) {
            int v = tid + j * 256;
            int k = v >> 6, nq = v & 63;
            uint32_t dst = bbase + (uint32_t)(k * BPITCH + nq * 4) * 4;
            const float* src = Bz + (size_t)(k0 + k) * N + bn + nq * 4;
            CP16CG(dst, src);
        }
    };

    int lane = tid & 31, g = lane >> 2, tg = lane & 3;
    int wid = tid >> 5;
    int wm = (wid & 1) * 32;
    int wn = (wid >> 1) * 64;

    float acc[2][8][4];
    #pragma unroll
    for (int mf = 0; mf < 2; mf++)
        #pragma unroll
        for (int nf = 0; nf < 8; nf++)
            #pragma unroll
            for (int q = 0; q < 4; q++) acc[mf][nf][q] = 0.f;

    load_stage(0, 0);
    CP_COMMIT();

    for (int c = 0; c < NC; c++) {
        CP_WAIT(0);
        __syncthreads();
        {
            int nxt = c + 1;
            if (nxt < NC) load_stage(nxt, nxt & 1);
            CP_COMMIT();
        }
        const float* As = sm + (size_t)(c & 1) * STAGE_WORDS;
        const float* Bs = As + AWORDS;
        #pragma unroll
        for (int ks = 0; ks < 2; ks++) {
            int ka = ks * 16 + 2 * tg;
            uint32_t ah[2][4], al[2][4];
            #pragma unroll
            for (int mf = 0; mf < 2; mf++) {
                int m = wm + mf * 16 + g;
                float2 v0 = *reinterpret_cast<const float2*>(&As[m * APITCH + ka]);
                float2 v1 = *reinterpret_cast<const float2*>(&As[(m + 8) * APITCH + ka]);
                float2 v2 = *reinterpret_cast<const float2*>(&As[m * APITCH + ka + 8]);
                float2 v3 = *reinterpret_cast<const float2*>(&As[(m + 8) * APITCH + ka + 8]);
                bf16_split2(v0.x, v0.y, ah[mf][0], al[mf][0]);
                bf16_split2(v1.x, v1.y, ah[mf][1], al[mf][1]);
                bf16_split2(v2.x, v2.y, ah[mf][2], al[mf][2]);
                bf16_split2(v3.x, v3.y, ah[mf][3], al[mf][3]);
            }
            #pragma unroll
            for (int nf = 0; nf < 8; nf++) {
                int n = wn + nf * 8 + g;
                uint32_t b0h, b0l, b1h, b1l;
                bf16_split2(Bs[(ka)     * BPITCH + n], Bs[(ka + 1) * BPITCH + n], b0h, b0l);
                bf16_split2(Bs[(ka + 8) * BPITCH + n], Bs[(ka + 9) * BPITCH + n], b1h, b1l);
                #pragma unroll
                for (int mf = 0; mf < 2; mf++) {
                    MMA_BF16(acc[mf][nf], ah[mf][0], ah[mf][1], ah[mf][2], ah[mf][3], b0h, b1h);
                    MMA_BF16(acc[mf][nf], ah[mf][0], ah[mf][1], ah[mf][2], ah[mf][3], b0l, b1l);
                    MMA_BF16(acc[mf][nf], al[mf][0], al[mf][1], al[mf][2], al[mf][3], b0h, b1h);
                }
            }
        }
        __syncthreads();
    }

    #pragma unroll
    for (int mf = 0; mf < 2; mf++) {
        int row = bm + wm + mf * 16 + g;
        float bv0 = 0.f, bv1 = 0.f;
        if (HASBIAS) { bv0 = bias[row]; bv1 = bias[row + 8]; }
        #pragma unroll
        for (int nf = 0; nf < 8; nf++) {
            int col = bn + wn + nf * 8 + 2 * tg;
            float2 v0 = make_float2(acc[mf][nf][0] + bv0, acc[mf][nf][1] + bv0);
            float2 v1 = make_float2(acc[mf][nf][2] + bv1, acc[mf][nf][3] + bv1);
            *reinterpret_cast<float2*>(&Cz[(size_t)row * N + col]) = v0;
            *reinterpret_cast<float2*>(&Cz[(size_t)(row + 8) * N + col]) = v1;
        }
    }
}

// ---------------- small 256-elt bitonic: registers + warp shuffles ----------------
// one element per thread; s<=16 passes via shfl.xor (no barrier), s>=32 via smem.
__device__ __forceinline__ void small_sort_256(u64& v, u64* sm, int t) {
    auto ce_shfl = [&](int s, int k) {
        u64 p = __shfl_xor_sync(0xFFFFFFFFu, v, s);
        bool up = ((t & k) == 0);
        bool lower = ((t & s) == 0);
        u64 mn = v < p ? v : p;
        u64 mx = v < p ? p : v;
        v = (lower == up) ? mn : mx;
    };
    #pragma unroll
    for (int k = 2; k <= 32; k <<= 1)
        for (int s = k >> 1; s > 0; s >>= 1) ce_shfl(s, k);
    #pragma unroll
    for (int k = 64; k <= 256; k <<= 1) {
        for (int s = k >> 1; s >= 32; s >>= 1) {
            sm[t] = v;
            __syncthreads();
            u64 p = sm[t ^ s];
            bool up = ((t & k) == 0);
            bool lower = ((t & s) == 0);
            u64 mn = v < p ? v : p;
            u64 mx = v < p ? p : v;
            v = (lower == up) ? mn : mx;
            __syncthreads();
        }
        #pragma unroll
        for (int s = 16; s > 0; s >>= 1) ce_shfl(s, k);
    }
}

__global__ void sort_h_kernel(const float* __restrict__ x) {
    int blk = blockIdx.x;
    int w = blk % Wdim; int c = (blk / Wdim) % 32; int b = blk / (Wdim * 32);
    __shared__ u64 sm[256];
    int t = threadIdx.x;
    u64 v = (t < Hdim) ? pack_kv(x[((b*Cch + c)*Hdim + t)*Wdim + w], (uint32_t)t)
                       : ((0xFFFFFFFFull << 32) | (uint32_t)t);
    small_sort_256(v, sm, t);
    if (t < Hdim) {
        g_xwork[((b*Cch + c)*Hdim + t)*Wdim + w] = unpack_key(v);
        g_invh[((b*32 + c)*Hdim + (int)(uint32_t)v)*Wdim + w] = t;
    }
}

__global__ void sort_w_kernel() {
    int blk = blockIdx.x;
    int h = blk % Hdim; int c = (blk / Hdim) % 32; int b = blk / (Hdim * 32);
    int base = ((b*Cch + c)*Hdim + h)*Wdim;
    __shared__ u64 sm[256];
    int t = threadIdx.x;
    u64 v = (t < Wdim) ? pack_kv(g_xwork[base + t], (uint32_t)t)
                       : ((0xFFFFFFFFull << 32) | (uint32_t)t);
    small_sort_256(v, sm, t);
    if (t < Wdim) {
        g_xwork[base + t] = unpack_key(v);
        g_invw[((b*32 + c)*Hdim + h)*Wdim + (int)(uint32_t)v] = t;
    }
}

__global__ void copy_rest_kernel(const float* __restrict__ x) {
    int gid = blockIdx.x * 256 + threadIdx.x;
    if (gid >= Bv*32*HW) return;
    int p = gid % HW; int c = (gid / HW) % 32; int b = gid / (32 * HW);
    int o = (b*Cch + 32 + c)*HW + p;
    g_xwork[o] = x[o];
}

// ---------------- fused depthwise 3x3 / 5x5 / 7x7 ----------------
__global__ void dwconv_kernel(const float* __restrict__ w3, const float* __restrict__ w5,
                              const float* __restrict__ w7) {
    int tile = blockIdx.x; int ch = blockIdx.y; int b = blockIdx.z;
    int ty0 = (tile / 12) * 16, tx0 = (tile % 12) * 16;
    __shared__ float s[22][24];
    __shared__ float wts[83];
    int tid = threadIdx.y * 16 + threadIdx.x;
    if (tid < 9)       wts[tid] = w3[ch*9 + tid];
    else if (tid < 34) wts[tid] = w5[ch*25 + tid - 9];
    else if (tid < 83) wts[tid] = w7[ch*49 + tid - 34];
    const float* base = g_q + (size_t)(b*320 + ch) * HW;
    for (int i = tid; i < 22*22; i += 256) {
        int sy = i / 22, sx = i % 22;
        int gy = ty0 + sy - 3, gx = tx0 + sx - 3;
        s[sy][sx] = (gy >= 0 && gy < Hdim && gx >= 0 && gx < Wdim) ? base[gy*Wdim + gx] : 0.f;
    }
    __syncthreads();
    int y = threadIdx.y, x = threadIdx.x;
    float a3 = 0.f, a5 = 0.f, a7 = 0.f;
    #pragma unroll
    for (int dy = 0; dy < 7; dy++)
        #pragma unroll
        for (int dx = 0; dx < 7; dx++) {
            float v = s[y + dy][x + dx];
            a7 += wts[34 + dy*7 + dx] * v;
            if (dy >= 1 && dy <= 5 && dx >= 1 && dx <= 5) a5 += wts[9 + (dy-1)*5 + (dx-1)] * v;
            if (dy >= 2 && dy <= 4 && dx >= 2 && dx <= 4) a3 += wts[(dy-2)*3 + (dx-2)] * v;
        }
    int gp = (ty0 + y)*Wdim + tx0 + x;
    size_t bo = (size_t)b * 960 * HW;
    g_cat[bo + (size_t)ch*HW + gp]        = a3;
    g_cat[bo + (size_t)(320 + ch)*HW + gp] = a5;
    g_cat[bo + (size_t)(640 + ch)*HW + gp] = a7;
}

// ================= parallel padding-aware bitonic sort =================
__global__ void init_pad_kernel() {
    int gid = blockIdx.x * 256 + threadIdx.x;
    const int per = 3 * CHUNK;
    if (gid >= 128 * per) return;
    int seg = gid / per;
    int i = 5 * CHUNK + gid % per;
    g_sort[(size_t)seg * SEG + i] = (0xFFFFFFFFull << 32) | (uint32_t)i;
}

__global__ void __launch_bounds__(512) sort_chunk_kernel() {
    int seg = blockIdx.x;
    int cb = blockIdx.y * CHUNK;
    u64* K = g_sort + (size_t)seg * SEG;
    const float* src = g_qkv + ((size_t)(seg >> 6) * 320 + 256 + (seg & 63)) * HW;
    extern __shared__ u64 sk[];
    int t = threadIdx.x;

    for (int i = t; i < CHUNK; i += 512) {
        int gi = cb + i;
        sk[i] = (gi < HW) ? pack_kv(src[gi], (uint32_t)gi)
                          : ((0xFFFFFFFFull << 32) | (uint32_t)gi);
    }
    __syncthreads();
    for (int gr = t; gr < CHUNK/8; gr += 512) {
        int base = gr * 8;
        u64 r[8];
        #pragma unroll
        for (int j = 0; j < 8; j++) r[j] = sk[base + j];
        ce_reg(r[0], r[1], ((base + 0) & 2) == 0);
        ce_reg(r[2], r[3], ((base + 2) & 2) == 0);
        ce_reg(r[4], r[5], ((base + 4) & 2) == 0);
        ce_reg(r[6], r[7], ((base + 6) & 2) == 0);
        {
            bool u0 = ((base + 0) & 4) == 0, u1 = ((base + 4) & 4) == 0;
            ce_reg(r[0], r[2], u0); ce_reg(r[1], r[3], u0);
            ce_reg(r[4], r[6], u1); ce_reg(r[5], r[7], u1);
            ce_reg(r[0], r[1], u0); ce_reg(r[2], r[3], u0);
            ce_reg(r[4], r[5], u1); ce_reg(r[6], r[7], u1);
        }
        {
            bool u = (base & 8) == 0;
            ce_reg(r[0], r[4], u); ce_reg(r[1], r[5], u); ce_reg(r[2], r[6], u); ce_reg(r[3], r[7], u);
            ce_reg(r[0], r[2], u); ce_reg(r[1], r[3], u); ce_reg(r[4], r[6], u); ce_reg(r[5], r[7], u);
            ce_reg(r[0], r[1], u); ce_reg(r[2], r[3], u); ce_reg(r[4], r[5], u); ce_reg(r[6], r[7], u);
        }
        #pragma unroll
        for (int j = 0; j < 8; j++) sk[base + j] = r[j];
    }
    __syncthreads();
    for (int k = 16; k <= CHUNK; k <<= 1) {
        for (int s = k >> 1; s >= 8; s >>= 1) {
            for (int p = t; p < CHUNK/2; p += 512) {
                int i = ((p & ~(s - 1)) << 1) | (p & (s - 1));
                int j = i + s;
                bool up = (((cb + i) & k) == 0);
                u64 a = sk[i], b = sk[j];
                u64 mn = a < b ? a : b;
                u64 mx = a < b ? b : a;
                sk[i] = up ? mn : mx;
                sk[j] = up ? mx : mn;
            }
            __syncthreads();
        }
        for (int gr = t; gr < CHUNK/8; gr += 512) {
            int base = gr * 8;
            bool u = (((cb + base) & k) == 0);
            u64 r[8];
            #pragma unroll
            for (int j = 0; j < 8; j++) r[j] = sk[base + j];
            ce_reg(r[0], r[4], u); ce_reg(r[1], r[5], u); ce_reg(r[2], r[6], u); ce_reg(r[3], r[7], u);
            ce_reg(r[0], r[2], u); ce_reg(r[1], r[3], u); ce_reg(r[4], r[6], u); ce_reg(r[5], r[7], u);
            ce_reg(r[0], r[1], u); ce_reg(r[2], r[3], u); ce_reg(r[4], r[5], u); ce_reg(r[6], r[7], u);
            #pragma unroll
            for (int j = 0; j < 8; j++) sk[base + j] = r[j];
        }
        __syncthreads();
    }
    for (int i = t; i < CHUNK; i += 512) K[cb + i] = sk[i];
}

__global__ void gpass_kernel(int k, int s) {
    int t = blockIdx.x * 256 + threadIdx.x;
    if (t >= 128 * (SEG/2)) return;
    int seg = t / (SEG/2);
    int p = t % (SEG/2);
    int i = ((p & ~(s - 1)) << 1) | (p & (s - 1));
    int j = i + s;
    u64* K = g_sort + (size_t)seg * SEG;
    bool up = ((i & k) == 0);
    u64 a = K[i], b = K[j];
    u64 mn = a < b ? a : b;
    u64 mx = a < b ? b : a;
    K[i] = up ? mn : mx;
    K[j] = up ? mx : mn;
}

__global__ void __launch_bounds__(512) merge_chunk_kernel(int k, int mask) {
    int seg = blockIdx.x;
    int y = blockIdx.y;
    int cidx = 0;
    {
        int cnt = -1;
        #pragma unroll
        for (int b = 0; b < 8; b++) {
            if (mask & (1 << b)) { cnt++; if (cnt == y) { cidx = b; break; } }
        }
    }
    int cb = cidx * CHUNK;
    u64* K = g_sort + (size_t)seg * SEG;
    extern __shared__ u64 sk[];
    int t = threadIdx.x;
    for (int i = t; i < CHUNK; i += 512) sk[i] = K[cb + i];
    __syncthreads();
    for (int s = CHUNK >> 1; s >= 8; s >>= 1) {
        for (int p = t; p < CHUNK/2; p += 512) {
            int i = ((p & ~(s - 1)) << 1) | (p & (s - 1));
            int j = i + s;
            bool up = (((cb + i) & k) == 0);
            u64 a = sk[i], b = sk[j];
            u64 mn = a < b ? a : b;
            u64 mx = a < b ? b : a;
            sk[i] = up ? mn : mx;
            sk[j] = up ? mx : mn;
        }
        __syncthreads();
    }
    for (int gr = t; gr < CHUNK/8; gr += 512) {
        int base = gr * 8;
        bool u = (((cb + base) & k) == 0);
        u64 r[8];
        #pragma unroll
        for (int j = 0; j < 8; j++) r[j] = sk[base + j];
        ce_reg(r[0], r[4], u); ce_reg(r[1], r[5], u); ce_reg(r[2], r[6], u); ce_reg(r[3], r[7], u);
        ce_reg(r[0], r[2], u); ce_reg(r[1], r[3], u); ce_reg(r[4], r[6], u); ce_reg(r[5], r[7], u);
        ce_reg(r[0], r[1], u); ce_reg(r[2], r[3], u); ce_reg(r[4], r[5], u); ce_reg(r[6], r[7], u);
        #pragma unroll
        for (int j = 0; j < 8; j++) sk[base + j] = r[j];
    }
    __syncthreads();
    for (int i = t; i < CHUNK; i += 512) K[cb + i] = sk[i];
}

// ---------------- gather q1/k1 + transposed q2/k2/v (nbt fused in) ----------------
__global__ void gather_kernel() {
    int gid = blockIdx.x * 256 + threadIdx.x;
    if (gid >= Bv*Cch*HW) return;
    int r = gid % HW; int c = (gid / HW) % Cch; int b = gid / (HW * Cch);
    u64 kv = g_sort[(size_t)(b*64 + c)*SEG + r];
    int src = (int)(uint32_t)kv;
    float v = unpack_key(kv);
    size_t qb = (size_t)b * 320 * HW;
    g_gq1[gid] = g_qkv[qb + (size_t)c*HW + src];
    g_gk1[gid] = g_qkv[qb + (size_t)(64 + c)*HW + src];
    float q2v = g_qkv[qb + (size_t)(128 + c)*HW + src];
    float k2v = g_qkv[qb + (size_t)(192 + c)*HW + src];
    g_vsc[gid] = v;
    int h = c >> 4, chi = c & 15;
    size_t ti = ((size_t)(b*4 + h)*64 + chi*4 + (r & 3))*9216 + (r >> 2);
    g_tq2[ti] = q2v;
    g_tk2[ti] = k2v;
    g_tv[ti]  = v;
}

__global__ void norm_kernel(const float* __restrict__ t, float* __restrict__ out) {
    int row = blockIdx.x;
    const float* p = t + (size_t)row * 9216;
    float ss = 0.f;
    for (int i = threadIdx.x; i < 9216; i += 256) { float v = p[i]; ss += v * v; }
    __shared__ float red[256];
    red[threadIdx.x] = ss;
    __syncthreads();
    for (int o = 128; o > 0; o >>= 1) {
        if (threadIdx.x < o) red[threadIdx.x] += red[threadIdx.x + o];
        __syncthreads();
    }
    if (threadIdx.x == 0) out[row] = fmaxf(sqrtf(red[0]), 1e-12f);
}

__global__ void qk_partial_kernel(const float* __restrict__ q, const float* __restrict__ k,
                                  float* __restrict__ part) {
    int kc = blockIdx.x, bh = blockIdx.y;
    const float* qb = q + (size_t)bh * 64 * 9216;
    const float* kb = k + (size_t)bh * 64 * 9216;
    __shared__ float qs[64][65];
    __shared__ float ks[64][65];
    int tid = threadIdx.x;
    int rm = (tid >> 4) * 4, rn = (tid & 15) * 4;
    float acc[4][4];
    #pragma unroll
    for (int i = 0; i < 4; i++)
        #pragma unroll
        for (int j = 0; j < 4; j++) acc[i][j] = 0.f;
    int nbase0 = kc * 576;
    for (int nt = 0; nt < 576; nt += 64) {
        #pragma unroll
        for (int l = 0; l < 16; l++) {
            int lin = l * 256 + tid;
            int d = lin >> 6, nn = lin & 63;
            qs[d][nn] = qb[(size_t)d*9216 + nbase0 + nt + nn];
            ks[d][nn] = kb[(size_t)d*9216 + nbase0 + nt + nn];
        }
        __syncthreads();
        #pragma unroll 8
        for (int nn = 0; nn < 64; nn++) {
            float a[4], bv[4];
            #pragma unroll
            for (int i = 0; i < 4; i++) a[i] = qs[rm + i][nn];
            #pragma unroll
            for (int j = 0; j < 4; j++) bv[j] = ks[rn + j][nn];
            #pragma unroll
            for (int i = 0; i < 4; i++)
                #pragma unroll
                for (int j = 0; j < 4; j++) acc[i][j] += a[i] * bv[j];
        }
        __syncthreads();
    }
    float* pp = part + ((size_t)bh * 16 + kc) * 4096;
    #pragma unroll
    for (int i = 0; i < 4; i++)
        #pragma unroll
        for (int j = 0; j < 4; j++) pp[(rm + i)*64 + rn + j] = acc[i][j];
}

// per-variant softmax (var = 0 box, 1 nonbox)
__global__ void softmax_kernel(const float* __restrict__ temp, int var) {
    int bh = blockIdx.x;
    int d = threadIdx.x;
    int h = bh & 3;
    const float* pp = g_part + ((size_t)(var*8 + bh) * 16) * 4096;
    float qn = g_nq[var*512 + bh*64 + d];
    float tmp = temp[h];
    float ev[64];
    float rs = 0.f;
    #pragma unroll
    for (int e = 0; e < 64; e++) {
        float s = 0.f;
        #pragma unroll
        for (int c2 = 0; c2 < 16; c2++) s += pp[(size_t)c2*4096 + d*64 + e];
        float a = s * tmp / (qn * g_nk[var*512 + bh*64 + e]);
        float x = expf(a);
        ev[e] = x;
        rs += x;
    }
    float inv = 1.f / (rs + 1.f);
    float* ap = g_attn + (size_t)(var*8 + bh) * 4096;
    #pragma unroll
    for (int e = 0; e < 64; e++) ap[d*64 + e] = ev[e] * inv;
}

__global__ void o_gemm_kernel(const float* __restrict__ attn, const float* __restrict__ v,
                              float* __restrict__ o) {
    int nt = blockIdx.x * 64, bh = blockIdx.y;
    const float* ap = attn + (size_t)bh * 4096;
    const float* vp = v + (size_t)bh * 64 * 9216;
    float* op = o + (size_t)bh * 64 * 9216;
    __shared__ float as_[64][65];
    __shared__ float vs_[64][65];
    int tid = threadIdx.x;
    #pragma unroll
    for (int l = 0; l < 16; l++) {
        int lin = l * 256 + tid;
        int r = lin >> 6, cc = lin & 63;
        as_[r][cc] = ap[lin];
        vs_[r][cc] = vp[(size_t)r*9216 + nt + cc];
    }
    __syncthreads();
    int rm = (tid >> 4) * 4, rn = (tid & 15) * 4;
    float acc[4][4];
    #pragma unroll
    for (int i = 0; i < 4; i++)
        #pragma unroll
        for (int j = 0; j < 4; j++) acc[i][j] = 0.f;
    #pragma unroll 8
    for (int e = 0; e < 64; e++) {
        float a[4], bv[4];
        #pragma unroll
        for (int i = 0; i < 4; i++) a[i] = as_[rm + i][e];
        #pragma unroll
        for (int j = 0; j < 4; j++) bv[j] = vs_[e][rn + j];
        #pragma unroll
        for (int i = 0; i < 4; i++)
            #pragma unroll
            for (int j = 0; j < 4; j++) acc[i][j] += a[i] * bv[j];
    }
    #pragma unroll
    for (int i = 0; i < 4; i++) {
        float4 ov = make_float4(acc[i][0], acc[i][1], acc[i][2], acc[i][3]);
        *reinterpret_cast<float4*>(&op[(size_t)(rm + i)*9216 + nt + rn]) = ov;
    }
}

// ---------------- combine out1*out2 (nbt_inv fused) + scatter back ----------------
__global__ void combine_scatter_kernel() {
    int gid = blockIdx.x * 256 + threadIdx.x;
    if (gid >= Bv*Cch*HW) return;
    int p = gid % HW; int c = (gid / HW) % 64; int b = gid / (HW * 64);
    u64 kv = g_sort[(size_t)(b*64 + c)*SEG + p];
    int dst = (int)(uint32_t)kv;
    int h = c >> 4, chi = c & 15;
    float o2v = g_ont[((size_t)(b*4 + h)*64 + chi*4 + (p & 3))*9216 + (p >> 2)];
    g_pre[(size_t)(b*64 + c)*HW + dst] = g_o1[gid] * o2v;
}

__global__ void final_kernel(float* __restrict__ out) {
    int gid = blockIdx.x * 256 + threadIdx.x;
    if (gid >= Bv*Cch*HW) return;
    int w = gid % Wdim; int h = (gid / Wdim) % Hdim;
    int c = (gid / HW) % 64; int b = gid / (HW * 64);
    if (c < 32) {
        int hh = g_invh[((b*32 + c)*Hdim + h)*Wdim + w];
        int ww = g_invw[((b*32 + c)*Hdim + hh)*Wdim + w];
        out[gid] = g_outp[(size_t)(b*64 + c)*HW + hh*Wdim + ww];
    } else {
        out[gid] = g_outp[gid];
    }
}

// ---------------- launcher ----------------
extern "C" void kernel_launch(void* const* d_in, const int* in_sizes, int n_in,
                              void* d_out, int out_size) {
    (void)in_sizes; (void)n_in; (void)out_size;
    const float* x      = (const float*)d_in[0];
    const float* temp   = (const float*)d_in[1];
    const float* w_qkv  = (const float*)d_in[2];
    const float* w_dw3  = (const float*)d_in[3];
    const float* w_dw5  = (const float*)d_in[4];
    const float* w_dw7  = (const float*)d_in[5];
    const float* w_fuse = (const float*)d_in[6];
    const float* b_fuse = (const float*)d_in[7];
    const float* w_proj = (const float*)d_in[8];
    float* out = (float*)d_out;

    static cudaStream_t s2 = nullptr;
    static cudaEvent_t evF = nullptr, evV = nullptr, evS = nullptr, evC = nullptr;
    static cudaEvent_t evG = nullptr, evO = nullptr;
    if (!s2) {
        cudaStreamCreateWithFlags(&s2, cudaStreamNonBlocking);
        cudaEventCreateWithFlags(&evF, cudaEventDisableTiming);
        cudaEventCreateWithFlags(&evV, cudaEventDisableTiming);
        cudaEventCreateWithFlags(&evS, cudaEventDisableTiming);
        cudaEventCreateWithFlags(&evC, cudaEventDisableTiming);
        cudaEventCreateWithFlags(&evG, cudaEventDisableTiming);
        cudaEventCreateWithFlags(&evO, cudaEventDisableTiming);
    }

    const int GEMM_SMEM = 2 * 42496;  // 84992 B (2-stage, 2 CTAs/SM)
    const int SORT_SMEM = CHUNK * 8;  // 65536 B
    cudaFuncSetAttribute(sort_chunk_kernel, cudaFuncAttributeMaxDynamicSharedMemorySize, SORT_SMEM);
    cudaFuncSetAttribute(merge_chunk_kernel, cudaFuncAttributeMaxDynamicSharedMemorySize, SORT_SMEM);
    cudaFuncSetAttribute(mma_gemm<30,true>, cudaFuncAttributeMaxDynamicSharedMemorySize, GEMM_SMEM);

    void *p_xwork, *p_q, *p_cat, *p_qkv, *p_pre, *p_outp;
    void *p_gq1, *p_gk1, *p_vsc, *p_tq2, *p_tk2, *p_tv;
    void *p_o1, *p_ont, *p_part, *p_attn, *p_nq, *p_nk;
    cudaGetSymbolAddress(&p_xwork, g_xwork);
    cudaGetSymbolAddress(&p_q, g_q);
    cudaGetSymbolAddress(&p_cat, g_cat);
    cudaGetSymbolAddress(&p_qkv, g_qkv);
    cudaGetSymbolAddress(&p_pre, g_pre);
    cudaGetSymbolAddress(&p_outp, g_outp);
    cudaGetSymbolAddress(&p_gq1, g_gq1);
    cudaGetSymbolAddress(&p_gk1, g_gk1);
    cudaGetSymbolAddress(&p_vsc, g_vsc);
    cudaGetSymbolAddress(&p_tq2, g_tq2);
    cudaGetSymbolAddress(&p_tk2, g_tk2);
    cudaGetSymbolAddress(&p_tv, g_tv);
    cudaGetSymbolAddress(&p_o1, g_o1);
    cudaGetSymbolAddress(&p_ont, g_ont);
    cudaGetSymbolAddress(&p_part, g_part);
    cudaGetSymbolAddress(&p_attn, g_attn);
    cudaGetSymbolAddress(&p_nq, g_nq);
    cudaGetSymbolAddress(&p_nk, g_nk);

    const int NELT = Bv*Cch*HW;
    const int EB = (NELT + 255) / 256;

    // 0) capture-legal fork of side stream from the origin stream
    cudaEventRecord(evF, 0);
    cudaStreamWaitEvent(s2, evF, 0);

    // 1) channel sorts on main; copy of untouched channels + pad init on side
    copy_rest_kernel<<<(Bv*32*HW + 255)/256, 256, 0, s2>>>(x);
    init_pad_kernel<<<(128*3*CHUNK + 255)/256, 256, 0, s2>>>();
    cudaEventRecord(evC, s2);
    sort_h_kernel<<<Bv*32*Wdim, 256>>>(x);
    sort_w_kernel<<<Bv*32*Hdim, 256>>>();
    cudaStreamWaitEvent(0, evC, 0);   // q gemm needs copy_rest

    // 2) q = w_qkv @ x   (M=320, K=64) — exact fp32 (feeds the v chain)
    gemm_kernel<<<dim3(HW/64, 3, Bv), 256>>>(
        w_qkv, (const float*)p_xwork, nullptr, (float*)p_q, 320, 64, HW);

    // 3) depthwise 3/5/7 -> cat (fp32)
    dwconv_kernel<<<dim3(144, 320, Bv), dim3(16, 16)>>>(w_dw3, w_dw5, w_dw7);

    // 4b FIRST) qkv rows 256..319 (v — feeds argsort, exact fp32)
    gemm64<<<dim3(HW/128, 1, Bv), 256>>>(
        w_fuse + (size_t)256*960, (const float*)p_cat, b_fuse + 256,
        (float*)p_qkv + (size_t)256*HW, 960,
        (long long)960*HW, (long long)320*HW);
    cudaEventRecord(evV, 0);

    // 5) parallel bitonic sort on side stream (bit-exact, padding-skipping)
    cudaStreamWaitEvent(s2, evV, 0);
    {
        const int GP_GRID = (128 * (SEG/2) + 255) / 256;
        sort_chunk_kernel<<<dim3(128, 5), 512, SORT_SMEM, s2>>>();
        gpass_kernel<<<GP_GRID, 256, 0, s2>>>(16384, 8192);
        merge_chunk_kernel<<<dim3(128, 5), 512, SORT_SMEM, s2>>>(16384, 31);
        gpass_kernel<<<GP_GRID, 256, 0, s2>>>(32768, 16384);
        gpass_kernel<<<GP_GRID, 256, 0, s2>>>(32768, 8192);
        merge_chunk_kernel<<<dim3(128, 5), 512, SORT_SMEM, s2>>>(32768, 143);
        gpass_kernel<<<GP_GRID, 256, 0, s2>>>(65536, 32768);
        gpass_kernel<<<GP_GRID, 256, 0, s2>>>(65536, 16384);
        gpass_kernel<<<GP_GRID, 256, 0, s2>>>(65536, 8192);
        merge_chunk_kernel<<<dim3(128, 5), 512, SORT_SMEM, s2>>>(65536, 31);
    }
    cudaEventRecord(evS, s2);

    // 4a) qkv rows 0..255 (attention operands) — 3xBF16 mma (main stream)
    mma_gemm<30,true><<<dim3(4, HW/256, Bv), 256, GEMM_SMEM>>>(
        w_fuse, (const float*)p_cat, b_fuse, (float*)p_qkv, 320);

    // join: gather needs both mma output (stream order) and sort (event)
    cudaStreamWaitEvent(0, evS, 0);

    // 6) gather (writes q1/k1 flat + q2/k2/v transposed; nbt fused)
    gather_kernel<<<EB, 256>>>();
    cudaEventRecord(evG, 0);

    // 7-9 variant 2 (nonbox) on side stream
    cudaStreamWaitEvent(s2, evG, 0);
    norm_kernel<<<512, 256, 0, s2>>>((const float*)p_tq2, (float*)p_nq + 512);
    norm_kernel<<<512, 256, 0, s2>>>((const float*)p_tk2, (float*)p_nk + 512);
    qk_partial_kernel<<<dim3(16, 8), 256, 0, s2>>>((const float*)p_tq2, (const float*)p_tk2,
                                                   (float*)p_part + 8*16*4096);
    softmax_kernel<<<8, 64, 0, s2>>>(temp, 1);
    o_gemm_kernel<<<dim3(144, 8), 256, 0, s2>>>((const float*)p_attn + 8*4096,
                                                (const float*)p_tv, (float*)p_ont);
    cudaEventRecord(evO, s2);

    // 7-9 variant 1 (box) on main stream
    norm_kernel<<<512, 256>>>((const float*)p_gq1, (float*)p_nq);
    norm_kernel<<<512, 256>>>((const float*)p_gk1, (float*)p_nk);
    qk_partial_kernel<<<dim3(16, 8), 256>>>((const float*)p_gq1, (const float*)p_gk1,
                                            (float*)p_part);
    softmax_kernel<<<8, 64>>>(temp, 0);
    o_gemm_kernel<<<dim3(144, 8), 256>>>((const float*)p_attn, (const float*)p_vsc,
                                         (float*)p_o1);

    // join variant 2 before combine
    cudaStreamWaitEvent(0, evO, 0);

    // 10) combine (nbt_inv fused) + scatter, proj (fp32), final unsort
    combine_scatter_kernel<<<EB, 256>>>();
    gemm64<<<dim3(HW/128, 1, Bv), 256>>>(
        w_proj, (const float*)p_pre, nullptr, (float*)p_outp, 64,
        (long long)64*HW, (long long)64*HW);
    final_kernel<<<EB, 256>>>(out);
}